// round 1
// baseline (speedup 1.0000x reference)
#include <cuda_runtime.h>
#include <math.h>

#define N 2048
#define D 16384
#define NB 128
#define NBLK 16            // N / NB
#define PI_F 3.14159265358979323846f

// ---------------- device scratch (no allocations allowed) ----------------
__device__ float g_S[(size_t)N * N];      // gram / sigma / L (lower, in place)
__device__ float g_W[(size_t)N * N];      // L^{-1} (lower)
__device__ float g_invD[NBLK * NB * NB];  // per-panel inv(L11)
__device__ float g_T[NB * N];             // GEMM scratch
__device__ float g_diag[N];               // diag snapshot for kernel step
__device__ float g_scal[4];               // [0]=trace acc, [1]=proj acc

// ==========================================================================
// NT tile kernel: C(bi,bj) (lower tile pairs) = f(A_rows(bi) * A_rows(bj)^T)
// mode 0: C = clip(scale*acc, -1, 1)      (gram)
// mode 1: C -= acc                        (syrk trailing update)
// 128x128 tiles, BK=8, 256 threads, 8x8 micro-tiles, reg prefetch.
// ==========================================================================
__global__ __launch_bounds__(256, 1)
void nt_tile_kernel(const float* __restrict__ Abase, int lda,
                    float* __restrict__ Cbase, int ldc,
                    int K, float scale, int mode)
{
    __shared__ float As[8][128];
    __shared__ float Bs[8][128];

    int t = blockIdx.x;
    int bi = (int)((sqrtf(8.f * (float)t + 1.f) - 1.f) * 0.5f);
    while ((bi + 1) * (bi + 2) / 2 <= t) bi++;
    while (bi * (bi + 1) / 2 > t) bi--;
    int bj = t - bi * (bi + 1) / 2;

    int tid = threadIdx.x;
    int tx = tid & 15, ty = tid >> 4;

    int lrow = tid >> 1;
    int lkk  = (tid & 1) * 4;
    const float* Ap = Abase + (size_t)(bi * 128 + lrow) * lda + lkk;
    const float* Bp = Abase + (size_t)(bj * 128 + lrow) * lda + lkk;

    float4 pa = *(const float4*)(Ap);
    float4 pb = *(const float4*)(Bp);

    float acc[8][8];
#pragma unroll
    for (int i = 0; i < 8; i++)
#pragma unroll
        for (int j = 0; j < 8; j++) acc[i][j] = 0.f;

    for (int k0 = 0; k0 < K; k0 += 8) {
        if (k0) __syncthreads();
        As[lkk + 0][lrow] = pa.x; As[lkk + 1][lrow] = pa.y;
        As[lkk + 2][lrow] = pa.z; As[lkk + 3][lrow] = pa.w;
        Bs[lkk + 0][lrow] = pb.x; Bs[lkk + 1][lrow] = pb.y;
        Bs[lkk + 2][lrow] = pb.z; Bs[lkk + 3][lrow] = pb.w;
        __syncthreads();
        if (k0 + 8 < K) {
            pa = *(const float4*)(Ap + k0 + 8);
            pb = *(const float4*)(Bp + k0 + 8);
        }
#pragma unroll
        for (int kk = 0; kk < 8; kk++) {
            float4 a0 = *(const float4*)&As[kk][ty * 4];
            float4 a1 = *(const float4*)&As[kk][64 + ty * 4];
            float4 b0 = *(const float4*)&Bs[kk][tx * 4];
            float4 b1 = *(const float4*)&Bs[kk][64 + tx * 4];
            float a[8] = {a0.x, a0.y, a0.z, a0.w, a1.x, a1.y, a1.z, a1.w};
            float b[8] = {b0.x, b0.y, b0.z, b0.w, b1.x, b1.y, b1.z, b1.w};
#pragma unroll
            for (int i = 0; i < 8; i++)
#pragma unroll
                for (int j = 0; j < 8; j++)
                    acc[i][j] += a[i] * b[j];
        }
    }

#pragma unroll
    for (int i = 0; i < 8; i++) {
        int r = bi * 128 + ((i < 4) ? ty * 4 + i : 64 + ty * 4 + (i - 4));
#pragma unroll
        for (int j = 0; j < 8; j++) {
            int cc = bj * 128 + ((j < 4) ? tx * 4 + j : 64 + tx * 4 + (j - 4));
            float* cp = Cbase + (size_t)r * ldc + cc;
            if (mode == 0) {
                float v = acc[i][j] * scale;
                *cp = fminf(fmaxf(v, -1.f), 1.f);
            } else {
                *cp -= acc[i][j];
            }
        }
    }
}

// ==========================================================================
// diag snapshot (avoids in-place race in step kernel)
// ==========================================================================
__global__ void diag_kernel()
{
    int i = blockIdx.x * blockDim.x + threadIdx.x;
    if (i < N) g_diag[i] = g_S[(size_t)i * N + i];
}

// ==========================================================================
// arc-cosine kernel step (lower triangle, in place)
// ==========================================================================
__global__ void step_kernel(const float* __restrict__ alpha_p)
{
    int j = blockIdx.x * 32 + threadIdx.x;
    int i = blockIdx.y * 8 + threadIdx.y;
    if (i >= N || j > i) return;
    float a  = *alpha_p;
    float a2 = a * a;
    float dii = g_diag[i];
    float djj = g_diag[j];
    float cross = sqrtf(dii * djj);
    float s = g_S[(size_t)i * N + j];
    float m = fminf(fmaxf(s / cross, -1.f), 1.f);
    float q = 1.f - m * m;
    float sq, ac;
    if (q > 0.f) { sq = sqrtf(q); ac = acosf(m); }
    else         { sq = 0.f;      ac = (m > 0.f) ? 0.f : PI_F; }
    float f  = (sq + m * (PI_F - ac)) / PI_F;
    float ts = cross * f;
    float ov = (s + a2 * ts) / (1.f + a2);
    g_S[(size_t)i * N + j] = fminf(fmaxf(ov, -1.f), 1.f);
}

// ==========================================================================
// panel factorization: factor 128x128 diag block in smem, also produce
// inv(L11) (used as TRSM-by-GEMM and for blocked triangular inversion)
// ==========================================================================
__global__ void potrf_invert(int kb)
{
    extern __shared__ float sh[];
    float* A = sh;             // NB*NB
    float* W = sh + NB * NB;   // NB*NB
    int tid = threadIdx.x;     // 256
    int base = kb * NB;

    for (int idx = tid; idx < NB * NB; idx += 256) {
        int i = idx >> 7, j = idx & 127;
        A[idx] = (j <= i) ? g_S[(size_t)(base + i) * N + base + j] : 0.f;
        W[idx] = 0.f;
    }
    __syncthreads();

    for (int j = 0; j < NB; j++) {
        if (tid == 0) A[j * NB + j] = sqrtf(A[j * NB + j]);
        __syncthreads();
        float dinv = 1.0f / A[j * NB + j];
        for (int i = j + 1 + tid; i < NB; i += 256) A[i * NB + j] *= dinv;
        __syncthreads();
        int tcol = j + 1 + tid;            // thread-per-column rank-1 update
        if (tcol < NB) {
            float ltj = A[tcol * NB + j];
            for (int i = tcol; i < NB; i++)
                A[i * NB + tcol] -= A[i * NB + j] * ltj;
        }
        __syncthreads();
    }

    // W = inv(A), forward substitution, one thread per column
    if (tid < NB) {
        int c = tid;
        for (int i = c; i < NB; i++) {
            float s = (i == c) ? 1.f : 0.f;
            for (int t = c; t < i; t++)
                s -= A[i * NB + t] * W[t * NB + c];
            W[i * NB + c] = s / A[i * NB + i];
        }
    }
    __syncthreads();

    for (int idx = tid; idx < NB * NB; idx += 256) {
        int i = idx >> 7, j = idx & 127;
        if (j <= i) g_S[(size_t)(base + i) * N + base + j] = A[idx];
        g_invD[kb * NB * NB + idx] = W[idx];
    }
}

// ==========================================================================
// TRSM panel: L21 = A21 * inv(L11)^T   (one block per row, in place)
// ==========================================================================
__global__ void trsm_kernel(int kb)
{
    __shared__ float arow[NB];
    int r = (kb + 1) * NB + blockIdx.x;
    int tid = threadIdx.x;  // 128
    float* rowp = g_S + (size_t)r * N + kb * NB;
    arow[tid] = rowp[tid];
    __syncthreads();
    const float* wrow = g_invD + kb * NB * NB + tid * NB;  // row tid of inv(L11)
    float s = 0.f;
    for (int t = 0; t <= tid; t++) s += arow[t] * wrow[t];
    rowp[tid] = s;
}

// ==========================================================================
// generic small GEMM: C[M x Ncol] = alpha * A[M x K] * B[K x Ncol]  (beta=0)
// 64x64 tiles, BK=16, 256 threads, 4x4 micro-tiles. grid=(Ncol/64, M/64).
// ==========================================================================
__global__ __launch_bounds__(256, 2)
void gemm_nn(const float* __restrict__ A, int lda,
             const float* __restrict__ B, int ldb,
             float* __restrict__ C, int ldc,
             int K, float alpha)
{
    __shared__ float As[16][64];
    __shared__ float Bs[16][64];
    int bi = blockIdx.y, bj = blockIdx.x;
    int tid = threadIdx.x;
    int tx = tid & 15, ty = tid >> 4;

    const float* Ab = A + (size_t)(bi * 64) * lda;
    const float* Bb = B + bj * 64;

    int arow = tid >> 2, akk = (tid & 3) << 2;
    int brow = tid >> 4, bcol = (tid & 15) << 2;

    float acc[4][4];
#pragma unroll
    for (int i = 0; i < 4; i++)
#pragma unroll
        for (int j = 0; j < 4; j++) acc[i][j] = 0.f;

    for (int k0 = 0; k0 < K; k0 += 16) {
        float4 va = *(const float4*)(Ab + (size_t)arow * lda + k0 + akk);
        float4 vb = *(const float4*)(Bb + (size_t)(k0 + brow) * ldb + bcol);
        As[akk + 0][arow] = va.x; As[akk + 1][arow] = va.y;
        As[akk + 2][arow] = va.z; As[akk + 3][arow] = va.w;
        *(float4*)&Bs[brow][bcol] = vb;
        __syncthreads();
#pragma unroll
        for (int kk = 0; kk < 16; kk++) {
            float4 a = *(const float4*)&As[kk][ty * 4];
            float4 b = *(const float4*)&Bs[kk][tx * 4];
            float av[4] = {a.x, a.y, a.z, a.w};
            float bv[4] = {b.x, b.y, b.z, b.w};
#pragma unroll
            for (int i = 0; i < 4; i++)
#pragma unroll
                for (int j = 0; j < 4; j++)
                    acc[i][j] += av[i] * bv[j];
        }
        __syncthreads();
    }

#pragma unroll
    for (int i = 0; i < 4; i++)
#pragma unroll
        for (int j = 0; j < 4; j++)
            C[(size_t)(bi * 64 + ty * 4 + i) * ldc + bj * 64 + tx * 4 + j] =
                alpha * acc[i][j];
}

// ==========================================================================
// misc small kernels
// ==========================================================================
__global__ void zero_kernel(float* p, int n)
{
    for (int i = blockIdx.x * blockDim.x + threadIdx.x; i < n;
         i += gridDim.x * blockDim.x)
        p[i] = 0.f;
}

__global__ void copy_diag_kernel()
{
    int kb = blockIdx.y;
    int idx = blockIdx.x * 256 + threadIdx.x;  // 64*256 = NB*NB
    int i = idx >> 7, j = idx & 127;
    g_W[(size_t)(kb * NB + i) * N + kb * NB + j] = g_invD[kb * NB * NB + idx];
}

__global__ void fnorm_kernel()
{
    __shared__ float red[256];
    float s = 0.f;
    size_t total = (size_t)N * N;
    for (size_t i = blockIdx.x * blockDim.x + threadIdx.x; i < total;
         i += (size_t)gridDim.x * blockDim.x) {
        float v = g_W[i];
        s += v * v;
    }
    red[threadIdx.x] = s; __syncthreads();
    for (int o = 128; o > 0; o >>= 1) {
        if (threadIdx.x < o) red[threadIdx.x] += red[threadIdx.x + o];
        __syncthreads();
    }
    if (threadIdx.x == 0) atomicAdd(&g_scal[0], red[0]);
}

__global__ void proj_kernel(const float* __restrict__ c)
{
    __shared__ float red[256];
    int r = blockIdx.x;
    const float* row = g_W + (size_t)r * N;
    float s = 0.f;
    for (int j = threadIdx.x; j < N; j += 256) s += row[j] * c[j];
    red[threadIdx.x] = s; __syncthreads();
    for (int o = 128; o > 0; o >>= 1) {
        if (threadIdx.x < o) red[threadIdx.x] += red[threadIdx.x + o];
        __syncthreads();
    }
    if (threadIdx.x == 0) {
        float y = red[0];
        atomicAdd(&g_scal[1], y * y);
    }
}

__global__ void final_kernel(float* out)
{
    __shared__ float red[256];
    float s = 0.f;
    for (int i = threadIdx.x; i < N; i += 256)
        s += logf(g_S[(size_t)i * N + i]);
    red[threadIdx.x] = s; __syncthreads();
    for (int o = 128; o > 0; o >>= 1) {
        if (threadIdx.x < o) red[threadIdx.x] += red[threadIdx.x + o];
        __syncthreads();
    }
    if (threadIdx.x == 0) {
        float nrd = expf(red[0] * (2.0f / (float)N));
        float tr = g_scal[0];
        float pj = g_scal[1];
        out[0] = (float)N / 5.0f +
                 nrd * ((0.5f - 1.0f / PI_F) * tr + pj / PI_F);
    }
}

// ==========================================================================
// host orchestration
// ==========================================================================
extern "C" void kernel_launch(void* const* d_in, const int* in_sizes, int n_in,
                              void* d_out, int out_size)
{
    (void)in_sizes; (void)n_in; (void)out_size;
    const float* x     = (const float*)d_in[0];
    const float* c     = (const float*)d_in[1];
    const float* alpha = (const float*)d_in[2];
    float* out = (float*)d_out;

    float *Sp, *Wp, *iDp, *Tp, *scalp;
    cudaGetSymbolAddress((void**)&Sp,    g_S);
    cudaGetSymbolAddress((void**)&Wp,    g_W);
    cudaGetSymbolAddress((void**)&iDp,   g_invD);
    cudaGetSymbolAddress((void**)&Tp,    g_T);
    cudaGetSymbolAddress((void**)&scalp, g_scal);

    cudaFuncSetAttribute(potrf_invert,
                         cudaFuncAttributeMaxDynamicSharedMemorySize,
                         2 * NB * NB * (int)sizeof(float));

    // 1. gram: sigma = clip(X X^T / D), lower tiles only
    nt_tile_kernel<<<NBLK * (NBLK + 1) / 2, 256>>>(x, D, Sp, N, D,
                                                   1.0f / (float)D, 0);

    // 2. arc-cosine kernel step (DEPTH=2 -> one step)
    diag_kernel<<<N / 256, 256>>>();
    step_kernel<<<dim3(N / 32, N / 8), dim3(32, 8)>>>(alpha);

    // 3. blocked Cholesky (in place, lower)
    for (int k = 0; k < NBLK; k++) {
        potrf_invert<<<1, 256, 2 * NB * NB * sizeof(float)>>>(k);
        if (k < NBLK - 1) {
            int rows = (NBLK - 1 - k) * NB;
            trsm_kernel<<<rows, NB>>>(k);
            int T2 = NBLK - 1 - k;
            nt_tile_kernel<<<T2 * (T2 + 1) / 2, 256>>>(
                Sp + (size_t)(k + 1) * NB * N + (size_t)k * NB, N,
                Sp + (size_t)(k + 1) * NB * N + (size_t)(k + 1) * NB, N,
                NB, 1.0f, 1);
        }
    }

    // 4. blocked triangular inversion: W = L^{-1} (lower)
    zero_kernel<<<4096, 256>>>(Wp, N * N);
    copy_diag_kernel<<<dim3(64, NBLK), 256>>>();
    for (int i = 1; i < NBLK; i++) {
        // T = L_{i,0:i} * W_{0:i,0:i}
        gemm_nn<<<dim3(2 * i, 2), 256>>>(Sp + (size_t)i * NB * N, N,
                                         Wp, N, Tp, N, i * NB, 1.0f);
        // W_{i,0:i} = -inv(L_ii) * T
        gemm_nn<<<dim3(2 * i, 2), 256>>>(iDp + (size_t)i * NB * NB, NB,
                                         Tp, N, Wp + (size_t)i * NB * N, N,
                                         NB, -1.0f);
    }

    // 5. reductions + final scalar
    zero_kernel<<<1, 32>>>(scalp, 4);
    fnorm_kernel<<<1024, 256>>>();          // trace(inv) = ||L^{-1}||_F^2
    proj_kernel<<<N, 256>>>(c);             // c^T inv c = ||L^{-1} c||^2
    final_kernel<<<1, 256>>>(out);
}

// round 2
// speedup vs baseline: 1.1384x; 1.1384x over previous
#include <cuda_runtime.h>
#include <math.h>

#define N 2048
#define D 16384
#define NB 128
#define LDA 129            // padded smem stride (bank-conflict-free columns)
#define NBLK 16            // N / NB
#define PI_F 3.14159265358979323846f

// ---------------- device scratch (no allocations allowed) ----------------
__device__ float g_S[(size_t)N * N];      // gram / sigma / L (lower, in place)
__device__ float g_W[(size_t)N * N];      // L^{-1} (lower)
__device__ float g_invD[NBLK * NB * NB];  // per-panel inv(L11)
__device__ float g_T[NB * N];             // GEMM scratch
__device__ float g_P[(size_t)N * NB];     // TRSM panel scratch
__device__ float g_diag[N];               // diag snapshot for kernel step
__device__ float g_scal[4];               // [0]=trace acc, [1]=proj acc

// ==========================================================================
// NT tile kernel: C(bi,bj) (lower tile pairs) = f(A_rows(bi) * A_rows(bj)^T)
// mode 0: C = clip(scale*acc, -1, 1)      (gram)
// mode 1: C -= acc                        (syrk trailing update)
// 128x128 tiles, BK=8, 256 threads, 8x8 micro-tiles, reg prefetch.
// ==========================================================================
__global__ __launch_bounds__(256, 1)
void nt_tile_kernel(const float* __restrict__ Abase, int lda,
                    float* __restrict__ Cbase, int ldc,
                    int K, float scale, int mode)
{
    __shared__ float As[8][128];
    __shared__ float Bs[8][128];

    int t = blockIdx.x;
    int bi = (int)((sqrtf(8.f * (float)t + 1.f) - 1.f) * 0.5f);
    while ((bi + 1) * (bi + 2) / 2 <= t) bi++;
    while (bi * (bi + 1) / 2 > t) bi--;
    int bj = t - bi * (bi + 1) / 2;

    int tid = threadIdx.x;
    int tx = tid & 15, ty = tid >> 4;

    int lrow = tid >> 1;
    int lkk  = (tid & 1) * 4;
    const float* Ap = Abase + (size_t)(bi * 128 + lrow) * lda + lkk;
    const float* Bp = Abase + (size_t)(bj * 128 + lrow) * lda + lkk;

    float4 pa = *(const float4*)(Ap);
    float4 pb = *(const float4*)(Bp);

    float acc[8][8];
#pragma unroll
    for (int i = 0; i < 8; i++)
#pragma unroll
        for (int j = 0; j < 8; j++) acc[i][j] = 0.f;

    for (int k0 = 0; k0 < K; k0 += 8) {
        if (k0) __syncthreads();
        As[lkk + 0][lrow] = pa.x; As[lkk + 1][lrow] = pa.y;
        As[lkk + 2][lrow] = pa.z; As[lkk + 3][lrow] = pa.w;
        Bs[lkk + 0][lrow] = pb.x; Bs[lkk + 1][lrow] = pb.y;
        Bs[lkk + 2][lrow] = pb.z; Bs[lkk + 3][lrow] = pb.w;
        __syncthreads();
        if (k0 + 8 < K) {
            pa = *(const float4*)(Ap + k0 + 8);
            pb = *(const float4*)(Bp + k0 + 8);
        }
#pragma unroll
        for (int kk = 0; kk < 8; kk++) {
            float4 a0 = *(const float4*)&As[kk][ty * 4];
            float4 a1 = *(const float4*)&As[kk][64 + ty * 4];
            float4 b0 = *(const float4*)&Bs[kk][tx * 4];
            float4 b1 = *(const float4*)&Bs[kk][64 + tx * 4];
            float a[8] = {a0.x, a0.y, a0.z, a0.w, a1.x, a1.y, a1.z, a1.w};
            float b[8] = {b0.x, b0.y, b0.z, b0.w, b1.x, b1.y, b1.z, b1.w};
#pragma unroll
            for (int i = 0; i < 8; i++)
#pragma unroll
                for (int j = 0; j < 8; j++)
                    acc[i][j] += a[i] * b[j];
        }
    }

#pragma unroll
    for (int i = 0; i < 8; i++) {
        int r = bi * 128 + ((i < 4) ? ty * 4 + i : 64 + ty * 4 + (i - 4));
#pragma unroll
        for (int j = 0; j < 8; j++) {
            int cc = bj * 128 + ((j < 4) ? tx * 4 + j : 64 + tx * 4 + (j - 4));
            float* cp = Cbase + (size_t)r * ldc + cc;
            if (mode == 0) {
                float v = acc[i][j] * scale;
                *cp = fminf(fmaxf(v, -1.f), 1.f);
            } else {
                *cp -= acc[i][j];
            }
        }
    }
}

// ==========================================================================
// diag snapshot (avoids in-place race in step kernel)
// ==========================================================================
__global__ void diag_kernel()
{
    int i = blockIdx.x * blockDim.x + threadIdx.x;
    if (i < N) g_diag[i] = g_S[(size_t)i * N + i];
}

// ==========================================================================
// arc-cosine kernel step (lower triangle, in place)
// ==========================================================================
__global__ void step_kernel(const float* __restrict__ alpha_p)
{
    int j = blockIdx.x * 32 + threadIdx.x;
    int i = blockIdx.y * 8 + threadIdx.y;
    if (i >= N || j > i) return;
    float a  = *alpha_p;
    float a2 = a * a;
    float dii = g_diag[i];
    float djj = g_diag[j];
    float cross = sqrtf(dii * djj);
    float s = g_S[(size_t)i * N + j];
    float m = fminf(fmaxf(s / cross, -1.f), 1.f);
    float q = 1.f - m * m;
    float sq, ac;
    if (q > 0.f) { sq = sqrtf(q); ac = acosf(m); }
    else         { sq = 0.f;      ac = (m > 0.f) ? 0.f : PI_F; }
    float f  = (sq + m * (PI_F - ac)) / PI_F;
    float ts = cross * f;
    float ov = (s + a2 * ts) / (1.f + a2);
    g_S[(size_t)i * N + j] = fminf(fmaxf(ov, -1.f), 1.f);
}

// ==========================================================================
// panel factorization + inversion of the 128x128 diag block.
// LDL-trick right-looking factorization: columns stay unscaled so each
// column step needs ONE sync; scale to L at the end. Inverse is
// thread-per-column (independent, zero syncs) with 4-way unrolled sums.
// Smem padded to stride 129 -> conflict-free column access.
// ==========================================================================
__global__ void potrf_invert(int kb)
{
    extern __shared__ float sh[];
    float* A = sh;                 // NB x NB, stride LDA
    float* W = sh + NB * LDA;      // NB x NB, stride LDA
    __shared__ float sq[NB], rs[NB];
    int tid = threadIdx.x;         // 256
    int base = kb * NB;

    for (int idx = tid; idx < NB * NB; idx += 256) {
        int i = idx >> 7, j = idx & 127;
        A[i * LDA + j] = (j <= i) ? g_S[(size_t)(base + i) * N + base + j] : 0.f;
        W[i * LDA + j] = 0.f;
    }
    __syncthreads();

    // right-looking, unscaled columns (LDL-style): 1 sync per column
    for (int j = 0; j < NB - 1; j++) {
        float pinv = 1.0f / A[j * LDA + j];
        int t = j + 1 + (tid & 127);
        if (t < NB) {
            float ctj = A[t * LDA + j] * pinv;
            for (int i = t + (tid >> 7); i < NB; i += 2)
                A[i * LDA + t] -= A[i * LDA + j] * ctj;
        }
        __syncthreads();
    }

    // diag sqrt + reciprocal
    if (tid < NB) {
        float d = A[tid * LDA + tid];
        float s = sqrtf(d);
        sq[tid] = s;
        rs[tid] = 1.0f / s;
    }
    __syncthreads();
    // scale to true L
    for (int idx = tid; idx < NB * NB; idx += 256) {
        int i = idx >> 7, j = idx & 127;
        if (j < i)       A[i * LDA + j] *= rs[j];
        else if (j == i) A[i * LDA + j] = sq[i];
    }
    __syncthreads();

    // W = inv(L): thread-per-column forward substitution, no syncs needed
    if (tid < NB) {
        int c = tid;
        W[c * LDA + c] = rs[c];
        for (int i = c + 1; i < NB; i++) {
            float s0 = 0.f, s1 = 0.f, s2 = 0.f, s3 = 0.f;
            int t = c;
            for (; t + 3 < i; t += 4) {
                s0 -= A[i * LDA + t]     * W[t * LDA + c];
                s1 -= A[i * LDA + t + 1] * W[(t + 1) * LDA + c];
                s2 -= A[i * LDA + t + 2] * W[(t + 2) * LDA + c];
                s3 -= A[i * LDA + t + 3] * W[(t + 3) * LDA + c];
            }
            float s = (s0 + s1) + (s2 + s3);
            for (; t < i; t++) s -= A[i * LDA + t] * W[t * LDA + c];
            W[i * LDA + c] = s * rs[i];
        }
    }
    __syncthreads();

    for (int idx = tid; idx < NB * NB; idx += 256) {
        int i = idx >> 7, j = idx & 127;
        if (j <= i) g_S[(size_t)(base + i) * N + base + j] = A[i * LDA + j];
        g_invD[(size_t)kb * NB * NB + idx] = W[i * LDA + j];
    }
}

// ==========================================================================
// NT GEMM: C[M x Ncol] = A[M x K] * B[Ncol x K]^T  (both row-major)
// used for TRSM: L21 = A21 * inv(L11)^T. 64x64 tiles, BK=16, 256 thr.
// ==========================================================================
__global__ __launch_bounds__(256, 2)
void gemm_nt(const float* __restrict__ A, int lda,
             const float* __restrict__ B, int ldb,
             float* __restrict__ C, int ldc, int K)
{
    __shared__ float As[16][64];
    __shared__ float Bs[16][64];
    int bi = blockIdx.y, bj = blockIdx.x;
    int tid = threadIdx.x;
    int tx = tid & 15, ty = tid >> 4;

    const float* Ab = A + (size_t)(bi * 64) * lda;
    const float* Bb = B + (size_t)(bj * 64) * ldb;

    int arow = tid >> 2, akk = (tid & 3) << 2;

    float acc[4][4];
#pragma unroll
    for (int i = 0; i < 4; i++)
#pragma unroll
        for (int j = 0; j < 4; j++) acc[i][j] = 0.f;

    for (int k0 = 0; k0 < K; k0 += 16) {
        float4 va = *(const float4*)(Ab + (size_t)arow * lda + k0 + akk);
        float4 vb = *(const float4*)(Bb + (size_t)arow * ldb + k0 + akk);
        As[akk + 0][arow] = va.x; As[akk + 1][arow] = va.y;
        As[akk + 2][arow] = va.z; As[akk + 3][arow] = va.w;
        Bs[akk + 0][arow] = vb.x; Bs[akk + 1][arow] = vb.y;
        Bs[akk + 2][arow] = vb.z; Bs[akk + 3][arow] = vb.w;
        __syncthreads();
#pragma unroll
        for (int kk = 0; kk < 16; kk++) {
            float4 a = *(const float4*)&As[kk][ty * 4];
            float4 b = *(const float4*)&Bs[kk][tx * 4];
            float av[4] = {a.x, a.y, a.z, a.w};
            float bv[4] = {b.x, b.y, b.z, b.w};
#pragma unroll
            for (int i = 0; i < 4; i++)
#pragma unroll
                for (int j = 0; j < 4; j++)
                    acc[i][j] += av[i] * bv[j];
        }
        __syncthreads();
    }

#pragma unroll
    for (int i = 0; i < 4; i++)
#pragma unroll
        for (int j = 0; j < 4; j++)
            C[(size_t)(bi * 64 + ty * 4 + i) * ldc + bj * 64 + tx * 4 + j] =
                acc[i][j];
}

// copy TRSM result panel back into S (needed as L for later stages)
__global__ void copy_panel(int kb)
{
    int r = blockIdx.x;
    int j = threadIdx.x;  // 128
    g_S[(size_t)((kb + 1) * NB + r) * N + kb * NB + j] = g_P[(size_t)r * NB + j];
}

// ==========================================================================
// generic small GEMM: C[M x Ncol] = alpha * A[M x K] * B[K x Ncol]  (beta=0)
// 64x64 tiles, BK=16, 256 threads, 4x4 micro-tiles. grid=(Ncol/64, M/64).
// ==========================================================================
__global__ __launch_bounds__(256, 2)
void gemm_nn(const float* __restrict__ A, int lda,
             const float* __restrict__ B, int ldb,
             float* __restrict__ C, int ldc,
             int K, float alpha)
{
    __shared__ float As[16][64];
    __shared__ float Bs[16][64];
    int bi = blockIdx.y, bj = blockIdx.x;
    int tid = threadIdx.x;
    int tx = tid & 15, ty = tid >> 4;

    const float* Ab = A + (size_t)(bi * 64) * lda;
    const float* Bb = B + bj * 64;

    int arow = tid >> 2, akk = (tid & 3) << 2;
    int brow = tid >> 4, bcol = (tid & 15) << 2;

    float acc[4][4];
#pragma unroll
    for (int i = 0; i < 4; i++)
#pragma unroll
        for (int j = 0; j < 4; j++) acc[i][j] = 0.f;

    for (int k0 = 0; k0 < K; k0 += 16) {
        float4 va = *(const float4*)(Ab + (size_t)arow * lda + k0 + akk);
        float4 vb = *(const float4*)(Bb + (size_t)(k0 + brow) * ldb + bcol);
        As[akk + 0][arow] = va.x; As[akk + 1][arow] = va.y;
        As[akk + 2][arow] = va.z; As[akk + 3][arow] = va.w;
        *(float4*)&Bs[brow][bcol] = vb;
        __syncthreads();
#pragma unroll
        for (int kk = 0; kk < 16; kk++) {
            float4 a = *(const float4*)&As[kk][ty * 4];
            float4 b = *(const float4*)&Bs[kk][tx * 4];
            float av[4] = {a.x, a.y, a.z, a.w};
            float bv[4] = {b.x, b.y, b.z, b.w};
#pragma unroll
            for (int i = 0; i < 4; i++)
#pragma unroll
                for (int j = 0; j < 4; j++)
                    acc[i][j] += av[i] * bv[j];
        }
        __syncthreads();
    }

#pragma unroll
    for (int i = 0; i < 4; i++)
#pragma unroll
        for (int j = 0; j < 4; j++)
            C[(size_t)(bi * 64 + ty * 4 + i) * ldc + bj * 64 + tx * 4 + j] =
                alpha * acc[i][j];
}

// ==========================================================================
// misc small kernels
// ==========================================================================
__global__ void zero_kernel(float* p, int n)
{
    for (int i = blockIdx.x * blockDim.x + threadIdx.x; i < n;
         i += gridDim.x * blockDim.x)
        p[i] = 0.f;
}

__global__ void copy_diag_kernel()
{
    int kb = blockIdx.y;
    int idx = blockIdx.x * 256 + threadIdx.x;  // 64*256 = NB*NB
    int i = idx >> 7, j = idx & 127;
    g_W[(size_t)(kb * NB + i) * N + kb * NB + j] = g_invD[(size_t)kb * NB * NB + idx];
}

__global__ void fnorm_kernel()
{
    __shared__ float red[256];
    float s = 0.f;
    size_t total = (size_t)N * N;
    for (size_t i = blockIdx.x * blockDim.x + threadIdx.x; i < total;
         i += (size_t)gridDim.x * blockDim.x) {
        float v = g_W[i];
        s += v * v;
    }
    red[threadIdx.x] = s; __syncthreads();
    for (int o = 128; o > 0; o >>= 1) {
        if (threadIdx.x < o) red[threadIdx.x] += red[threadIdx.x + o];
        __syncthreads();
    }
    if (threadIdx.x == 0) atomicAdd(&g_scal[0], red[0]);
}

__global__ void proj_kernel(const float* __restrict__ c)
{
    __shared__ float red[256];
    int r = blockIdx.x;
    const float* row = g_W + (size_t)r * N;
    float s = 0.f;
    for (int j = threadIdx.x; j < N; j += 256) s += row[j] * c[j];
    red[threadIdx.x] = s; __syncthreads();
    for (int o = 128; o > 0; o >>= 1) {
        if (threadIdx.x < o) red[threadIdx.x] += red[threadIdx.x + o];
        __syncthreads();
    }
    if (threadIdx.x == 0) {
        float y = red[0];
        atomicAdd(&g_scal[1], y * y);
    }
}

__global__ void final_kernel(float* out)
{
    __shared__ float red[256];
    float s = 0.f;
    for (int i = threadIdx.x; i < N; i += 256)
        s += logf(g_S[(size_t)i * N + i]);
    red[threadIdx.x] = s; __syncthreads();
    for (int o = 128; o > 0; o >>= 1) {
        if (threadIdx.x < o) red[threadIdx.x] += red[threadIdx.x + o];
        __syncthreads();
    }
    if (threadIdx.x == 0) {
        float nrd = expf(red[0] * (2.0f / (float)N));
        float tr = g_scal[0];
        float pj = g_scal[1];
        out[0] = (float)N / 5.0f +
                 nrd * ((0.5f - 1.0f / PI_F) * tr + pj / PI_F);
    }
}

// ==========================================================================
// host orchestration
// ==========================================================================
extern "C" void kernel_launch(void* const* d_in, const int* in_sizes, int n_in,
                              void* d_out, int out_size)
{
    (void)in_sizes; (void)n_in; (void)out_size;
    const float* x     = (const float*)d_in[0];
    const float* c     = (const float*)d_in[1];
    const float* alpha = (const float*)d_in[2];
    float* out = (float*)d_out;

    float *Sp, *Wp, *iDp, *Tp, *Pp, *scalp;
    cudaGetSymbolAddress((void**)&Sp,    g_S);
    cudaGetSymbolAddress((void**)&Wp,    g_W);
    cudaGetSymbolAddress((void**)&iDp,   g_invD);
    cudaGetSymbolAddress((void**)&Tp,    g_T);
    cudaGetSymbolAddress((void**)&Pp,    g_P);
    cudaGetSymbolAddress((void**)&scalp, g_scal);

    int potrf_smem = 2 * NB * LDA * (int)sizeof(float);
    cudaFuncSetAttribute(potrf_invert,
                         cudaFuncAttributeMaxDynamicSharedMemorySize,
                         potrf_smem);

    // 1. gram: sigma = clip(X X^T / D), lower tiles only
    nt_tile_kernel<<<NBLK * (NBLK + 1) / 2, 256>>>(x, D, Sp, N, D,
                                                   1.0f / (float)D, 0);

    // 2. arc-cosine kernel step (DEPTH=2 -> one step)
    diag_kernel<<<N / 256, 256>>>();
    step_kernel<<<dim3(N / 32, N / 8), dim3(32, 8)>>>(alpha);

    // 3. blocked Cholesky (in place, lower)
    for (int k = 0; k < NBLK; k++) {
        potrf_invert<<<1, 256, potrf_smem>>>(k);
        if (k < NBLK - 1) {
            int rows = (NBLK - 1 - k) * NB;
            // TRSM as GEMM: P = A21 * inv(L11)^T  (out of place, race-free)
            gemm_nt<<<dim3(2, rows / 64), 256>>>(
                Sp + (size_t)(k + 1) * NB * N + (size_t)k * NB, N,
                iDp + (size_t)k * NB * NB, NB,
                Pp, NB, NB);
            copy_panel<<<rows, NB>>>(k);
            int T2 = NBLK - 1 - k;
            nt_tile_kernel<<<T2 * (T2 + 1) / 2, 256>>>(
                Pp, NB,
                Sp + (size_t)(k + 1) * NB * N + (size_t)(k + 1) * NB, N,
                NB, 1.0f, 1);
        }
    }

    // 4. blocked triangular inversion: W = L^{-1} (lower)
    zero_kernel<<<4096, 256>>>(Wp, N * N);
    copy_diag_kernel<<<dim3(64, NBLK), 256>>>();
    for (int i = 1; i < NBLK; i++) {
        // T = L_{i,0:i} * W_{0:i,0:i}
        gemm_nn<<<dim3(2 * i, 2), 256>>>(Sp + (size_t)i * NB * N, N,
                                         Wp, N, Tp, N, i * NB, 1.0f);
        // W_{i,0:i} = -inv(L_ii) * T
        gemm_nn<<<dim3(2 * i, 2), 256>>>(iDp + (size_t)i * NB * NB, NB,
                                         Tp, N, Wp + (size_t)i * NB * N, N,
                                         NB, -1.0f);
    }

    // 5. reductions + final scalar
    zero_kernel<<<1, 32>>>(scalp, 4);
    fnorm_kernel<<<1024, 256>>>();          // trace(inv) = ||L^{-1}||_F^2
    proj_kernel<<<N, 256>>>(c);             // c^T inv c = ||L^{-1} c||^2
    final_kernel<<<1, 256>>>(out);
}

// round 3
// speedup vs baseline: 1.5177x; 1.3331x over previous
#include <cuda_runtime.h>
#include <math.h>

#define N 2048
#define D 16384
#define NB 128
#define LDA 129            // padded smem stride (bank-conflict-free columns)
#define NBLK 16            // N / NB
#define PI_F 3.14159265358979323846f

// ---------------- device scratch (no allocations allowed) ----------------
__device__ float g_S[(size_t)N * N];      // gram / sigma / L (lower, in place)
__device__ float g_W[(size_t)N * N];      // L^{-1} (lower)
__device__ float g_invD[NBLK * NB * NB];  // per-panel inv(L11) (full 128x128)
__device__ float g_T[NB * N];             // GEMM scratch
__device__ float g_P[(size_t)N * NB];     // TRSM panel scratch
__device__ float g_diag[N];               // diag snapshot for kernel step
__device__ float g_scal[4];               // [0]=trace acc, [1]=proj acc

// ==========================================================================
// NT tile kernel: C(bi,bj) (lower tile pairs) = f(A_rows(bi) * A_rows(bj)^T)
// mode 0: C = clip(scale*acc, -1, 1)      (gram)
// mode 1: C -= acc                        (syrk trailing update)
// ==========================================================================
__global__ __launch_bounds__(256, 1)
void nt_tile_kernel(const float* __restrict__ Abase, int lda,
                    float* __restrict__ Cbase, int ldc,
                    int K, float scale, int mode)
{
    __shared__ float As[8][128];
    __shared__ float Bs[8][128];

    int t = blockIdx.x;
    int bi = (int)((sqrtf(8.f * (float)t + 1.f) - 1.f) * 0.5f);
    while ((bi + 1) * (bi + 2) / 2 <= t) bi++;
    while (bi * (bi + 1) / 2 > t) bi--;
    int bj = t - bi * (bi + 1) / 2;

    int tid = threadIdx.x;
    int tx = tid & 15, ty = tid >> 4;

    int lrow = tid >> 1;
    int lkk  = (tid & 1) * 4;
    const float* Ap = Abase + (size_t)(bi * 128 + lrow) * lda + lkk;
    const float* Bp = Abase + (size_t)(bj * 128 + lrow) * lda + lkk;

    float4 pa = *(const float4*)(Ap);
    float4 pb = *(const float4*)(Bp);

    float acc[8][8];
#pragma unroll
    for (int i = 0; i < 8; i++)
#pragma unroll
        for (int j = 0; j < 8; j++) acc[i][j] = 0.f;

    for (int k0 = 0; k0 < K; k0 += 8) {
        if (k0) __syncthreads();
        As[lkk + 0][lrow] = pa.x; As[lkk + 1][lrow] = pa.y;
        As[lkk + 2][lrow] = pa.z; As[lkk + 3][lrow] = pa.w;
        Bs[lkk + 0][lrow] = pb.x; Bs[lkk + 1][lrow] = pb.y;
        Bs[lkk + 2][lrow] = pb.z; Bs[lkk + 3][lrow] = pb.w;
        __syncthreads();
        if (k0 + 8 < K) {
            pa = *(const float4*)(Ap + k0 + 8);
            pb = *(const float4*)(Bp + k0 + 8);
        }
#pragma unroll
        for (int kk = 0; kk < 8; kk++) {
            float4 a0 = *(const float4*)&As[kk][ty * 4];
            float4 a1 = *(const float4*)&As[kk][64 + ty * 4];
            float4 b0 = *(const float4*)&Bs[kk][tx * 4];
            float4 b1 = *(const float4*)&Bs[kk][64 + tx * 4];
            float a[8] = {a0.x, a0.y, a0.z, a0.w, a1.x, a1.y, a1.z, a1.w};
            float b[8] = {b0.x, b0.y, b0.z, b0.w, b1.x, b1.y, b1.z, b1.w};
#pragma unroll
            for (int i = 0; i < 8; i++)
#pragma unroll
                for (int j = 0; j < 8; j++)
                    acc[i][j] += a[i] * b[j];
        }
    }

#pragma unroll
    for (int i = 0; i < 8; i++) {
        int r = bi * 128 + ((i < 4) ? ty * 4 + i : 64 + ty * 4 + (i - 4));
#pragma unroll
        for (int j = 0; j < 8; j++) {
            int cc = bj * 128 + ((j < 4) ? tx * 4 + j : 64 + tx * 4 + (j - 4));
            float* cp = Cbase + (size_t)r * ldc + cc;
            if (mode == 0) {
                float v = acc[i][j] * scale;
                *cp = fminf(fmaxf(v, -1.f), 1.f);
            } else {
                *cp -= acc[i][j];
            }
        }
    }
}

// ==========================================================================
__global__ void diag_kernel()
{
    int i = blockIdx.x * blockDim.x + threadIdx.x;
    if (i < N) g_diag[i] = g_S[(size_t)i * N + i];
}

__global__ void step_kernel(const float* __restrict__ alpha_p)
{
    int j = blockIdx.x * 32 + threadIdx.x;
    int i = blockIdx.y * 8 + threadIdx.y;
    if (i >= N || j > i) return;
    float a  = *alpha_p;
    float a2 = a * a;
    float cross = sqrtf(g_diag[i] * g_diag[j]);
    float s = g_S[(size_t)i * N + j];
    float m = fminf(fmaxf(s / cross, -1.f), 1.f);
    float q = 1.f - m * m;
    float sq, ac;
    if (q > 0.f) { sq = sqrtf(q); ac = acosf(m); }
    else         { sq = 0.f;      ac = (m > 0.f) ? 0.f : PI_F; }
    float f  = (sq + m * (PI_F - ac)) / PI_F;
    float ts = cross * f;
    float ov = (s + a2 * ts) / (1.f + a2);
    g_S[(size_t)i * N + j] = fminf(fmaxf(ov, -1.f), 1.f);
}

// ==========================================================================
// panel factorization + inversion of the 128x128 diag block, sub-blocked
// by 32. Warp-synchronous 32x32 potf2 + invert; parallel TRSM / SYRK /
// blocked inversion across all 256 threads. ~20 block syncs total.
// ==========================================================================
__global__ __launch_bounds__(256, 1)
void potrf_invert(int kb)
{
    extern __shared__ float sh[];
    float* A = sh;                 // NB x NB, stride LDA (L, lower)
    float* W = sh + NB * LDA;      // NB x NB, stride LDA (inv(L), lower)
    __shared__ float rs[NB];
    __shared__ float Ts[3 * 32 * 33];  // scratch for blocked inversion
    int tid = threadIdx.x;             // 256
    int base = kb * NB;

    for (int idx = tid; idx < NB * NB; idx += 256) {
        int i = idx >> 7, j = idx & 127;
        A[i * LDA + j] = (j <= i) ? g_S[(size_t)(base + i) * N + base + j] : 0.f;
        W[i * LDA + j] = 0.f;
    }
    __syncthreads();

    for (int p = 0; p < 4; p++) {
        int off = p * 32;

        // ---- potf2 (32x32) + invert, warp 0 only, warp-synchronous ----
        if (tid < 32) {
            int lane = tid;
#pragma unroll 1
            for (int j = 0; j < 32; j++) {
                float d  = A[(off + j) * LDA + off + j];
                float sj = sqrtf(d);
                float rsj = 1.0f / sj;
                if (lane == j) { A[(off + j) * LDA + off + j] = sj; rs[off + j] = rsj; }
                if (lane > j)  A[(off + lane) * LDA + off + j] *= rsj;
                __syncwarp();
                if (lane > j) {
                    float lij = A[(off + lane) * LDA + off + j];
                    for (int t = j + 1; t <= lane; t++)
                        A[(off + lane) * LDA + off + t] -=
                            lij * A[(off + t) * LDA + off + j];
                }
                __syncwarp();
            }
            // invert 32x32: lane = column c, independent chains
            int c = lane;
            W[(off + c) * LDA + off + c] = rs[off + c];
            for (int i = c + 1; i < 32; i++) {
                float s = 0.f;
                for (int t = c; t < i; t++)
                    s -= A[(off + i) * LDA + off + t] *
                         W[(off + t) * LDA + off + c];
                W[(off + i) * LDA + off + c] = s * rs[off + i];
            }
        }
        __syncthreads();

        int nr = NB - off - 32;
        if (nr > 0) {
            // ---- TRSM: rows off+32..127, in-place fwd substitution ----
            if (tid < nr) {
                int r = off + 32 + tid;
                float* arow = A + (size_t)r * LDA + off;
                for (int cc = 0; cc < 32; cc++) {
                    float s = arow[cc];
                    const float* lrow = A + (size_t)(off + cc) * LDA + off;
                    for (int t = 0; t < cc; t++) s -= arow[t] * lrow[t];
                    arow[cc] = s * rs[off + cc];
                }
            }
            __syncthreads();

            // ---- SYRK trailing update within the block ----
            for (int idx = tid; idx < nr * nr; idx += 256) {
                int i = idx / nr + off + 32;
                int t = idx % nr + off + 32;
                if (t <= i) {
                    const float* ai = A + (size_t)i * LDA + off;
                    const float* at = A + (size_t)t * LDA + off;
                    float acc = 0.f;
#pragma unroll
                    for (int k = 0; k < 32; k++) acc += ai[k] * at[k];
                    A[i * LDA + t] -= acc;
                }
            }
            __syncthreads();
        }
    }

    // ---- blocked inversion of off-diag 32x32 blocks of W ----
    for (int ib = 1; ib < 4; ib++) {
        // T[j] = sum_{t=j..ib-1} L[ib][t] * W[t][j]
        for (int idx = tid; idx < ib * 1024; idx += 256) {
            int j = idx >> 10, e = idx & 1023;
            int r = e >> 5, c = e & 31;
            float acc = 0.f;
            for (int tb = j; tb < ib; tb++) {
                const float* lr = A + (size_t)(32 * ib + r) * LDA + 32 * tb;
#pragma unroll 8
                for (int k = 0; k < 32; k++)
                    acc += lr[k] * W[(32 * tb + k) * LDA + 32 * j + c];
            }
            Ts[j * 1056 + r * 33 + c] = acc;
        }
        __syncthreads();
        // W[ib][j] = -inv(L_ii) * T[j]   (inv(L_ii) lower triangular)
        for (int idx = tid; idx < ib * 1024; idx += 256) {
            int j = idx >> 10, e = idx & 1023;
            int r = e >> 5, c = e & 31;
            const float* wi = W + (size_t)(32 * ib + r) * LDA + 32 * ib;
            float acc = 0.f;
            for (int k = 0; k <= r; k++)
                acc += wi[k] * Ts[j * 1056 + k * 33 + c];
            W[(32 * ib + r) * LDA + 32 * j + c] = -acc;
        }
        __syncthreads();
    }

    for (int idx = tid; idx < NB * NB; idx += 256) {
        int i = idx >> 7, j = idx & 127;
        if (j <= i) g_S[(size_t)(base + i) * N + base + j] = A[i * LDA + j];
        g_invD[(size_t)kb * NB * NB + idx] = W[i * LDA + j];
    }
}

// ==========================================================================
// NT GEMM for TRSM: C[M x 32..] = A[M x K] * B[.. x K]^T
// ==========================================================================
__global__ __launch_bounds__(256, 2)
void gemm_nt(const float* __restrict__ A, int lda,
             const float* __restrict__ B, int ldb,
             float* __restrict__ C, int ldc, int K)
{
    __shared__ float As[16][64];
    __shared__ float Bs[16][64];
    int bi = blockIdx.y, bj = blockIdx.x;
    int tid = threadIdx.x;
    int tx = tid & 15, ty = tid >> 4;

    const float* Ab = A + (size_t)(bi * 64) * lda;
    const float* Bb = B + (size_t)(bj * 64) * ldb;

    int arow = tid >> 2, akk = (tid & 3) << 2;

    float acc[4][4];
#pragma unroll
    for (int i = 0; i < 4; i++)
#pragma unroll
        for (int j = 0; j < 4; j++) acc[i][j] = 0.f;

    for (int k0 = 0; k0 < K; k0 += 16) {
        float4 va = *(const float4*)(Ab + (size_t)arow * lda + k0 + akk);
        float4 vb = *(const float4*)(Bb + (size_t)arow * ldb + k0 + akk);
        As[akk + 0][arow] = va.x; As[akk + 1][arow] = va.y;
        As[akk + 2][arow] = va.z; As[akk + 3][arow] = va.w;
        Bs[akk + 0][arow] = vb.x; Bs[akk + 1][arow] = vb.y;
        Bs[akk + 2][arow] = vb.z; Bs[akk + 3][arow] = vb.w;
        __syncthreads();
#pragma unroll
        for (int kk = 0; kk < 16; kk++) {
            float4 a = *(const float4*)&As[kk][ty * 4];
            float4 b = *(const float4*)&Bs[kk][tx * 4];
            float av[4] = {a.x, a.y, a.z, a.w};
            float bv[4] = {b.x, b.y, b.z, b.w};
#pragma unroll
            for (int i = 0; i < 4; i++)
#pragma unroll
                for (int j = 0; j < 4; j++)
                    acc[i][j] += av[i] * bv[j];
        }
        __syncthreads();
    }

#pragma unroll
    for (int i = 0; i < 4; i++)
#pragma unroll
        for (int j = 0; j < 4; j++)
            C[(size_t)(bi * 64 + ty * 4 + i) * ldc + bj * 64 + tx * 4 + j] =
                acc[i][j];
}

__global__ void copy_panel(int kb)
{
    int r = blockIdx.x;
    int j = threadIdx.x;  // 128
    g_S[(size_t)((kb + 1) * NB + r) * N + kb * NB + j] = g_P[(size_t)r * NB + j];
}

// ==========================================================================
// generic NN GEMM: C = alpha * A * B
// ==========================================================================
__global__ __launch_bounds__(256, 2)
void gemm_nn(const float* __restrict__ A, int lda,
             const float* __restrict__ B, int ldb,
             float* __restrict__ C, int ldc,
             int K, float alpha)
{
    __shared__ float As[16][64];
    __shared__ float Bs[16][64];
    int bi = blockIdx.y, bj = blockIdx.x;
    int tid = threadIdx.x;
    int tx = tid & 15, ty = tid >> 4;

    const float* Ab = A + (size_t)(bi * 64) * lda;
    const float* Bb = B + bj * 64;

    int arow = tid >> 2, akk = (tid & 3) << 2;
    int brow = tid >> 4, bcol = (tid & 15) << 2;

    float acc[4][4];
#pragma unroll
    for (int i = 0; i < 4; i++)
#pragma unroll
        for (int j = 0; j < 4; j++) acc[i][j] = 0.f;

    for (int k0 = 0; k0 < K; k0 += 16) {
        float4 va = *(const float4*)(Ab + (size_t)arow * lda + k0 + akk);
        float4 vb = *(const float4*)(Bb + (size_t)(k0 + brow) * ldb + bcol);
        As[akk + 0][arow] = va.x; As[akk + 1][arow] = va.y;
        As[akk + 2][arow] = va.z; As[akk + 3][arow] = va.w;
        *(float4*)&Bs[brow][bcol] = vb;
        __syncthreads();
#pragma unroll
        for (int kk = 0; kk < 16; kk++) {
            float4 a = *(const float4*)&As[kk][ty * 4];
            float4 b = *(const float4*)&Bs[kk][tx * 4];
            float av[4] = {a.x, a.y, a.z, a.w};
            float bv[4] = {b.x, b.y, b.z, b.w};
#pragma unroll
            for (int i = 0; i < 4; i++)
#pragma unroll
                for (int j = 0; j < 4; j++)
                    acc[i][j] += av[i] * bv[j];
        }
        __syncthreads();
    }

#pragma unroll
    for (int i = 0; i < 4; i++)
#pragma unroll
        for (int j = 0; j < 4; j++)
            C[(size_t)(bi * 64 + ty * 4 + i) * ldc + bj * 64 + tx * 4 + j] =
                alpha * acc[i][j];
}

// ==========================================================================
__global__ void zero_kernel(float* p, int n)
{
    for (int i = blockIdx.x * blockDim.x + threadIdx.x; i < n;
         i += gridDim.x * blockDim.x)
        p[i] = 0.f;
}

__global__ void copy_diag_kernel()
{
    int kb = blockIdx.y;
    int idx = blockIdx.x * 256 + threadIdx.x;  // 64*256 = NB*NB
    int i = idx >> 7, j = idx & 127;
    g_W[(size_t)(kb * NB + i) * N + kb * NB + j] =
        g_invD[(size_t)kb * NB * NB + idx];
}

__global__ void fnorm_kernel()
{
    __shared__ float red[256];
    float s = 0.f;
    size_t total = (size_t)N * N;
    for (size_t i = blockIdx.x * blockDim.x + threadIdx.x; i < total;
         i += (size_t)gridDim.x * blockDim.x) {
        float v = g_W[i];
        s += v * v;
    }
    red[threadIdx.x] = s; __syncthreads();
    for (int o = 128; o > 0; o >>= 1) {
        if (threadIdx.x < o) red[threadIdx.x] += red[threadIdx.x + o];
        __syncthreads();
    }
    if (threadIdx.x == 0) atomicAdd(&g_scal[0], red[0]);
}

__global__ void proj_kernel(const float* __restrict__ c)
{
    __shared__ float red[256];
    int r = blockIdx.x;
    const float* row = g_W + (size_t)r * N;
    float s = 0.f;
    for (int j = threadIdx.x; j < N; j += 256) s += row[j] * c[j];
    red[threadIdx.x] = s; __syncthreads();
    for (int o = 128; o > 0; o >>= 1) {
        if (threadIdx.x < o) red[threadIdx.x] += red[threadIdx.x + o];
        __syncthreads();
    }
    if (threadIdx.x == 0) {
        float y = red[0];
        atomicAdd(&g_scal[1], y * y);
    }
}

__global__ void final_kernel(float* out)
{
    __shared__ float red[256];
    float s = 0.f;
    for (int i = threadIdx.x; i < N; i += 256)
        s += logf(g_S[(size_t)i * N + i]);
    red[threadIdx.x] = s; __syncthreads();
    for (int o = 128; o > 0; o >>= 1) {
        if (threadIdx.x < o) red[threadIdx.x] += red[threadIdx.x + o];
        __syncthreads();
    }
    if (threadIdx.x == 0) {
        float nrd = expf(red[0] * (2.0f / (float)N));
        float tr = g_scal[0];
        float pj = g_scal[1];
        out[0] = (float)N / 5.0f +
                 nrd * ((0.5f - 1.0f / PI_F) * tr + pj / PI_F);
    }
}

// ==========================================================================
// host orchestration
// ==========================================================================
extern "C" void kernel_launch(void* const* d_in, const int* in_sizes, int n_in,
                              void* d_out, int out_size)
{
    (void)in_sizes; (void)n_in; (void)out_size;
    const float* x     = (const float*)d_in[0];
    const float* c     = (const float*)d_in[1];
    const float* alpha = (const float*)d_in[2];
    float* out = (float*)d_out;

    float *Sp, *Wp, *iDp, *Tp, *Pp, *scalp;
    cudaGetSymbolAddress((void**)&Sp,    g_S);
    cudaGetSymbolAddress((void**)&Wp,    g_W);
    cudaGetSymbolAddress((void**)&iDp,   g_invD);
    cudaGetSymbolAddress((void**)&Tp,    g_T);
    cudaGetSymbolAddress((void**)&Pp,    g_P);
    cudaGetSymbolAddress((void**)&scalp, g_scal);

    int potrf_smem = 2 * NB * LDA * (int)sizeof(float);
    cudaFuncSetAttribute(potrf_invert,
                         cudaFuncAttributeMaxDynamicSharedMemorySize,
                         potrf_smem);

    // 1. gram: sigma = clip(X X^T / D), lower tiles only
    nt_tile_kernel<<<NBLK * (NBLK + 1) / 2, 256>>>(x, D, Sp, N, D,
                                                   1.0f / (float)D, 0);

    // 2. arc-cosine kernel step (DEPTH=2 -> one step)
    diag_kernel<<<N / 256, 256>>>();
    step_kernel<<<dim3(N / 32, N / 8), dim3(32, 8)>>>(alpha);

    // 3. blocked Cholesky (in place, lower)
    for (int k = 0; k < NBLK; k++) {
        potrf_invert<<<1, 256, potrf_smem>>>(k);
        if (k < NBLK - 1) {
            int rows = (NBLK - 1 - k) * NB;
            gemm_nt<<<dim3(2, rows / 64), 256>>>(
                Sp + (size_t)(k + 1) * NB * N + (size_t)k * NB, N,
                iDp + (size_t)k * NB * NB, NB,
                Pp, NB, NB);
            copy_panel<<<rows, NB>>>(k);
            int T2 = NBLK - 1 - k;
            nt_tile_kernel<<<T2 * (T2 + 1) / 2, 256>>>(
                Pp, NB,
                Sp + (size_t)(k + 1) * NB * N + (size_t)(k + 1) * NB, N,
                NB, 1.0f, 1);
        }
    }

    // 4. blocked triangular inversion: W = L^{-1} (lower)
    zero_kernel<<<4096, 256>>>(Wp, N * N);
    copy_diag_kernel<<<dim3(64, NBLK), 256>>>();
    for (int i = 1; i < NBLK; i++) {
        gemm_nn<<<dim3(2 * i, 2), 256>>>(Sp + (size_t)i * NB * N, N,
                                         Wp, N, Tp, N, i * NB, 1.0f);
        gemm_nn<<<dim3(2 * i, 2), 256>>>(iDp + (size_t)i * NB * NB, NB,
                                         Tp, N, Wp + (size_t)i * NB * N, N,
                                         NB, -1.0f);
    }

    // 5. reductions + final scalar
    zero_kernel<<<1, 32>>>(scalp, 4);
    fnorm_kernel<<<1024, 256>>>();          // trace(inv) = ||L^{-1}||_F^2
    proj_kernel<<<N, 256>>>(c);             // c^T inv c = ||L^{-1} c||^2
    final_kernel<<<1, 256>>>(out);
}

// round 4
// speedup vs baseline: 2.3922x; 1.5762x over previous
#include <cuda_runtime.h>
#include <math.h>

#define N 2048
#define D 16384
#define NB 128
#define LDA 129            // padded smem stride (bank-conflict-free columns)
#define NBLK 16            // N / NB
#define PI_F 3.14159265358979323846f

// ---------------- device scratch (no allocations allowed) ----------------
__device__ float g_S[(size_t)N * N];      // gram / sigma / L (lower, in place)
__device__ float g_W[(size_t)N * N];      // L^{-1} (lower)
__device__ float g_invD[NBLK * NB * NB];  // per-panel inv(L11) (full 128x128)
__device__ float g_T2[(size_t)1024 * 1024]; // D&C inversion scratch
__device__ float g_P[(size_t)N * NB];     // TRSM panel scratch
__device__ float g_diag[N];               // diag snapshot for kernel step
__device__ float g_scal[4];               // [0]=trace acc, [1]=proj acc

// ==========================================================================
// NT tile kernel: C(bi,bj) (lower tile pairs) = f(A_rows(bi) * A_rows(bj)^T)
// mode 0: C = clip(scale*acc, -1, 1)      (gram)
// mode 1: C -= acc                        (syrk trailing update)
// ==========================================================================
__global__ __launch_bounds__(256, 1)
void nt_tile_kernel(const float* __restrict__ Abase, int lda,
                    float* __restrict__ Cbase, int ldc,
                    int K, float scale, int mode)
{
    __shared__ float As[8][128];
    __shared__ float Bs[8][128];

    int t = blockIdx.x;
    int bi = (int)((sqrtf(8.f * (float)t + 1.f) - 1.f) * 0.5f);
    while ((bi + 1) * (bi + 2) / 2 <= t) bi++;
    while (bi * (bi + 1) / 2 > t) bi--;
    int bj = t - bi * (bi + 1) / 2;

    int tid = threadIdx.x;
    int tx = tid & 15, ty = tid >> 4;

    int lrow = tid >> 1;
    int lkk  = (tid & 1) * 4;
    const float* Ap = Abase + (size_t)(bi * 128 + lrow) * lda + lkk;
    const float* Bp = Abase + (size_t)(bj * 128 + lrow) * lda + lkk;

    float4 pa = *(const float4*)(Ap);
    float4 pb = *(const float4*)(Bp);

    float acc[8][8];
#pragma unroll
    for (int i = 0; i < 8; i++)
#pragma unroll
        for (int j = 0; j < 8; j++) acc[i][j] = 0.f;

    for (int k0 = 0; k0 < K; k0 += 8) {
        if (k0) __syncthreads();
        As[lkk + 0][lrow] = pa.x; As[lkk + 1][lrow] = pa.y;
        As[lkk + 2][lrow] = pa.z; As[lkk + 3][lrow] = pa.w;
        Bs[lkk + 0][lrow] = pb.x; Bs[lkk + 1][lrow] = pb.y;
        Bs[lkk + 2][lrow] = pb.z; Bs[lkk + 3][lrow] = pb.w;
        __syncthreads();
        if (k0 + 8 < K) {
            pa = *(const float4*)(Ap + k0 + 8);
            pb = *(const float4*)(Bp + k0 + 8);
        }
#pragma unroll
        for (int kk = 0; kk < 8; kk++) {
            float4 a0 = *(const float4*)&As[kk][ty * 4];
            float4 a1 = *(const float4*)&As[kk][64 + ty * 4];
            float4 b0 = *(const float4*)&Bs[kk][tx * 4];
            float4 b1 = *(const float4*)&Bs[kk][64 + tx * 4];
            float a[8] = {a0.x, a0.y, a0.z, a0.w, a1.x, a1.y, a1.z, a1.w};
            float b[8] = {b0.x, b0.y, b0.z, b0.w, b1.x, b1.y, b1.z, b1.w};
#pragma unroll
            for (int i = 0; i < 8; i++)
#pragma unroll
                for (int j = 0; j < 8; j++)
                    acc[i][j] += a[i] * b[j];
        }
    }

#pragma unroll
    for (int i = 0; i < 8; i++) {
        int r = bi * 128 + ((i < 4) ? ty * 4 + i : 64 + ty * 4 + (i - 4));
#pragma unroll
        for (int j = 0; j < 8; j++) {
            int cc = bj * 128 + ((j < 4) ? tx * 4 + j : 64 + tx * 4 + (j - 4));
            float* cp = Cbase + (size_t)r * ldc + cc;
            if (mode == 0) {
                float v = acc[i][j] * scale;
                *cp = fminf(fmaxf(v, -1.f), 1.f);
            } else {
                *cp -= acc[i][j];
            }
        }
    }
}

// ==========================================================================
__global__ void diag_kernel()
{
    int i = blockIdx.x * blockDim.x + threadIdx.x;
    if (i < N) g_diag[i] = g_S[(size_t)i * N + i];
}

__global__ void step_kernel(const float* __restrict__ alpha_p)
{
    int j = blockIdx.x * 32 + threadIdx.x;
    int i = blockIdx.y * 8 + threadIdx.y;
    if (i >= N || j > i) return;
    float a  = *alpha_p;
    float a2 = a * a;
    float cross = sqrtf(g_diag[i] * g_diag[j]);
    float s = g_S[(size_t)i * N + j];
    float m = fminf(fmaxf(s / cross, -1.f), 1.f);
    float q = 1.f - m * m;
    float sq, ac;
    if (q > 0.f) { sq = sqrtf(q); ac = acosf(m); }
    else         { sq = 0.f;      ac = (m > 0.f) ? 0.f : PI_F; }
    float f  = (sq + m * (PI_F - ac)) / PI_F;
    float ts = cross * f;
    float ov = (s + a2 * ts) / (1.f + a2);
    g_S[(size_t)i * N + j] = fminf(fmaxf(ov, -1.f), 1.f);
}

// ==========================================================================
// panel factorization + inversion of 128x128 diag block, sub-blocked by 32.
// potf2 + inv32 are fully register/shuffle-resident in warp 0 (no smem in
// the dependency chain). TRSM is a parallel multiply by inv(L11_32)^T.
// ==========================================================================
__global__ __launch_bounds__(256, 1)
void potrf_invert(int kb)
{
    extern __shared__ float sh[];
    float* A = sh;                 // NB x NB, stride LDA (L, lower)
    float* W = sh + NB * LDA;      // NB x NB, stride LDA (inv(L), lower)
    __shared__ float Ts[3 * 32 * 33];  // TRSM staging / blocked-inv scratch
    int tid = threadIdx.x;             // 256
    int base = kb * NB;

    for (int idx = tid; idx < NB * NB; idx += 256) {
        int i = idx >> 7, j = idx & 127;
        A[i * LDA + j] = (j <= i) ? g_S[(size_t)(base + i) * N + base + j] : 0.f;
        W[i * LDA + j] = 0.f;
    }
    __syncthreads();

    for (int p = 0; p < 4; p++) {
        int off = p * 32;

        // ---- register-resident potf2 + inv32, warp 0 ----
        if (tid < 32) {
            const unsigned FULL = 0xffffffffu;
            int r = tid;
            float ar[32];
#pragma unroll
            for (int t = 0; t < 32; t++)
                ar[t] = (t <= r) ? A[(off + r) * LDA + off + t] : 0.f;
            float rs_reg = 0.f;

            // Cholesky of 32x32 in registers; lane r = row r
#pragma unroll
            for (int j = 0; j < 32; j++) {
                float d   = __shfl_sync(FULL, ar[j], j);
                float rsj = rsqrtf(d);
                float lj  = ar[j] * rsj;   // L[r][j] (valid for r >= j)
                ar[j] = lj;
                if (r == j) rs_reg = rsj;
#pragma unroll
                for (int t = j + 1; t < 32; t++) {
                    float ltj = __shfl_sync(FULL, lj, t);
                    ar[t] -= lj * ltj;
                }
            }

            // inverse: lane c = column c of inv(L), forward substitution
            int c = r;
            float w[32];
#pragma unroll
            for (int t = 0; t < 32; t++) w[t] = 0.f;
#pragma unroll
            for (int i = 0; i < 32; i++) {
                float s = (i == c) ? 1.f : 0.f;
#pragma unroll
                for (int t = 0; t < i; t++) {
                    float lit = __shfl_sync(FULL, ar[t], i);  // L[i][t]
                    s -= lit * w[t];
                }
                float rsi = __shfl_sync(FULL, rs_reg, i);
                w[i] = (i >= c) ? s * rsi : 0.f;
            }

            // write back L row r and inv column c
#pragma unroll
            for (int t = 0; t < 32; t++)
                if (t <= r) A[(off + r) * LDA + off + t] = ar[t];
#pragma unroll
            for (int i = 0; i < 32; i++)
                if (i >= c) W[(off + i) * LDA + off + c] = w[i];
        }
        __syncthreads();

        int nr = NB - off - 32;
        if (nr > 0) {
            // ---- TRSM: A21 <- A21 * inv(L11_32)^T  (parallel dots) ----
            for (int idx = tid; idx < nr * 32; idx += 256) {
                int r = idx >> 5, cc = idx & 31;
                const float* arow = A + (size_t)(off + 32 + r) * LDA + off;
                const float* wrow = W + (size_t)(off + cc) * LDA + off;
                float s = 0.f;
#pragma unroll 8
                for (int t = 0; t <= cc; t++) s += arow[t] * wrow[t];
                Ts[idx] = s;
            }
            __syncthreads();
            for (int idx = tid; idx < nr * 32; idx += 256) {
                int r = idx >> 5, cc = idx & 31;
                A[(off + 32 + r) * LDA + off + cc] = Ts[idx];
            }
            __syncthreads();

            // ---- SYRK trailing update within the block ----
            for (int idx = tid; idx < nr * nr; idx += 256) {
                int i = idx / nr + off + 32;
                int t = idx % nr + off + 32;
                if (t <= i) {
                    const float* ai = A + (size_t)i * LDA + off;
                    const float* at = A + (size_t)t * LDA + off;
                    float acc = 0.f;
#pragma unroll
                    for (int k = 0; k < 32; k++) acc += ai[k] * at[k];
                    A[i * LDA + t] -= acc;
                }
            }
            __syncthreads();
        }
    }

    // ---- blocked inversion of off-diag 32x32 blocks of W ----
    for (int ib = 1; ib < 4; ib++) {
        for (int idx = tid; idx < ib * 1024; idx += 256) {
            int j = idx >> 10, e = idx & 1023;
            int r = e >> 5, c = e & 31;
            float acc = 0.f;
            for (int tb = j; tb < ib; tb++) {
                const float* lr = A + (size_t)(32 * ib + r) * LDA + 32 * tb;
#pragma unroll 8
                for (int k = 0; k < 32; k++)
                    acc += lr[k] * W[(32 * tb + k) * LDA + 32 * j + c];
            }
            Ts[j * 1056 + r * 33 + c] = acc;
        }
        __syncthreads();
        for (int idx = tid; idx < ib * 1024; idx += 256) {
            int j = idx >> 10, e = idx & 1023;
            int r = e >> 5, c = e & 31;
            const float* wi = W + (size_t)(32 * ib + r) * LDA + 32 * ib;
            float acc = 0.f;
            for (int k = 0; k <= r; k++)
                acc += wi[k] * Ts[j * 1056 + k * 33 + c];
            W[(32 * ib + r) * LDA + 32 * j + c] = -acc;
        }
        __syncthreads();
    }

    for (int idx = tid; idx < NB * NB; idx += 256) {
        int i = idx >> 7, j = idx & 127;
        if (j <= i) g_S[(size_t)(base + i) * N + base + j] = A[i * LDA + j];
        g_invD[(size_t)kb * NB * NB + idx] = W[i * LDA + j];
    }
}

// ==========================================================================
// NT GEMM for TRSM panels: C = A * B^T
// ==========================================================================
__global__ __launch_bounds__(256, 2)
void gemm_nt(const float* __restrict__ A, int lda,
             const float* __restrict__ B, int ldb,
             float* __restrict__ C, int ldc, int K)
{
    __shared__ float As[16][64];
    __shared__ float Bs[16][64];
    int bi = blockIdx.y, bj = blockIdx.x;
    int tid = threadIdx.x;
    int tx = tid & 15, ty = tid >> 4;

    const float* Ab = A + (size_t)(bi * 64) * lda;
    const float* Bb = B + (size_t)(bj * 64) * ldb;

    int arow = tid >> 2, akk = (tid & 3) << 2;

    float acc[4][4];
#pragma unroll
    for (int i = 0; i < 4; i++)
#pragma unroll
        for (int j = 0; j < 4; j++) acc[i][j] = 0.f;

    for (int k0 = 0; k0 < K; k0 += 16) {
        float4 va = *(const float4*)(Ab + (size_t)arow * lda + k0 + akk);
        float4 vb = *(const float4*)(Bb + (size_t)arow * ldb + k0 + akk);
        As[akk + 0][arow] = va.x; As[akk + 1][arow] = va.y;
        As[akk + 2][arow] = va.z; As[akk + 3][arow] = va.w;
        Bs[akk + 0][arow] = vb.x; Bs[akk + 1][arow] = vb.y;
        Bs[akk + 2][arow] = vb.z; Bs[akk + 3][arow] = vb.w;
        __syncthreads();
#pragma unroll
        for (int kk = 0; kk < 16; kk++) {
            float4 a = *(const float4*)&As[kk][ty * 4];
            float4 b = *(const float4*)&Bs[kk][tx * 4];
            float av[4] = {a.x, a.y, a.z, a.w};
            float bv[4] = {b.x, b.y, b.z, b.w};
#pragma unroll
            for (int i = 0; i < 4; i++)
#pragma unroll
                for (int j = 0; j < 4; j++)
                    acc[i][j] += av[i] * bv[j];
        }
        __syncthreads();
    }

#pragma unroll
    for (int i = 0; i < 4; i++)
#pragma unroll
        for (int j = 0; j < 4; j++)
            C[(size_t)(bi * 64 + ty * 4 + i) * ldc + bj * 64 + tx * 4 + j] =
                acc[i][j];
}

__global__ void copy_panel(int kb)
{
    int r = blockIdx.x;
    int j = threadIdx.x;  // 128
    g_S[(size_t)((kb + 1) * NB + r) * N + kb * NB + j] = g_P[(size_t)r * NB + j];
}

// ==========================================================================
// batched NN GEMM: C = alpha * A * B, batch via blockIdx.z with strides
// ==========================================================================
__global__ __launch_bounds__(256, 2)
void gemm_nn_b(const float* __restrict__ A, size_t strA, int lda,
               const float* __restrict__ B, size_t strB, int ldb,
               float* __restrict__ C, size_t strC, int ldc,
               int K, float alpha)
{
    A += (size_t)blockIdx.z * strA;
    B += (size_t)blockIdx.z * strB;
    C += (size_t)blockIdx.z * strC;

    __shared__ float As[16][64];
    __shared__ float Bs[16][64];
    int bi = blockIdx.y, bj = blockIdx.x;
    int tid = threadIdx.x;
    int tx = tid & 15, ty = tid >> 4;

    const float* Ab = A + (size_t)(bi * 64) * lda;
    const float* Bb = B + bj * 64;

    int arow = tid >> 2, akk = (tid & 3) << 2;
    int brow = tid >> 4, bcol = (tid & 15) << 2;

    float acc[4][4];
#pragma unroll
    for (int i = 0; i < 4; i++)
#pragma unroll
        for (int j = 0; j < 4; j++) acc[i][j] = 0.f;

    for (int k0 = 0; k0 < K; k0 += 16) {
        float4 va = *(const float4*)(Ab + (size_t)arow * lda + k0 + akk);
        float4 vb = *(const float4*)(Bb + (size_t)(k0 + brow) * ldb + bcol);
        As[akk + 0][arow] = va.x; As[akk + 1][arow] = va.y;
        As[akk + 2][arow] = va.z; As[akk + 3][arow] = va.w;
        *(float4*)&Bs[brow][bcol] = vb;
        __syncthreads();
#pragma unroll
        for (int kk = 0; kk < 16; kk++) {
            float4 a = *(const float4*)&As[kk][ty * 4];
            float4 b = *(const float4*)&Bs[kk][tx * 4];
            float av[4] = {a.x, a.y, a.z, a.w};
            float bv[4] = {b.x, b.y, b.z, b.w};
#pragma unroll
            for (int i = 0; i < 4; i++)
#pragma unroll
                for (int j = 0; j < 4; j++)
                    acc[i][j] += av[i] * bv[j];
        }
        __syncthreads();
    }

#pragma unroll
    for (int i = 0; i < 4; i++)
#pragma unroll
        for (int j = 0; j < 4; j++)
            C[(size_t)(bi * 64 + ty * 4 + i) * ldc + bj * 64 + tx * 4 + j] =
                alpha * acc[i][j];
}

// ==========================================================================
__global__ void zero_kernel(float* p, int n)
{
    for (int i = blockIdx.x * blockDim.x + threadIdx.x; i < n;
         i += gridDim.x * blockDim.x)
        p[i] = 0.f;
}

__global__ void copy_diag_kernel()
{
    int kb = blockIdx.y;
    int idx = blockIdx.x * 256 + threadIdx.x;  // 64*256 = NB*NB
    int i = idx >> 7, j = idx & 127;
    g_W[(size_t)(kb * NB + i) * N + kb * NB + j] =
        g_invD[(size_t)kb * NB * NB + idx];
}

__global__ void fnorm_kernel()
{
    __shared__ float red[256];
    float s = 0.f;
    size_t total = (size_t)N * N;
    for (size_t i = blockIdx.x * blockDim.x + threadIdx.x; i < total;
         i += (size_t)gridDim.x * blockDim.x) {
        float v = g_W[i];
        s += v * v;
    }
    red[threadIdx.x] = s; __syncthreads();
    for (int o = 128; o > 0; o >>= 1) {
        if (threadIdx.x < o) red[threadIdx.x] += red[threadIdx.x + o];
        __syncthreads();
    }
    if (threadIdx.x == 0) atomicAdd(&g_scal[0], red[0]);
}

__global__ void proj_kernel(const float* __restrict__ c)
{
    __shared__ float red[256];
    int r = blockIdx.x;
    const float* row = g_W + (size_t)r * N;
    float s = 0.f;
    for (int j = threadIdx.x; j < N; j += 256) s += row[j] * c[j];
    red[threadIdx.x] = s; __syncthreads();
    for (int o = 128; o > 0; o >>= 1) {
        if (threadIdx.x < o) red[threadIdx.x] += red[threadIdx.x + o];
        __syncthreads();
    }
    if (threadIdx.x == 0) {
        float y = red[0];
        atomicAdd(&g_scal[1], y * y);
    }
}

__global__ void final_kernel(float* out)
{
    __shared__ float red[256];
    float s = 0.f;
    for (int i = threadIdx.x; i < N; i += 256)
        s += logf(g_S[(size_t)i * N + i]);
    red[threadIdx.x] = s; __syncthreads();
    for (int o = 128; o > 0; o >>= 1) {
        if (threadIdx.x < o) red[threadIdx.x] += red[threadIdx.x + o];
        __syncthreads();
    }
    if (threadIdx.x == 0) {
        float nrd = expf(red[0] * (2.0f / (float)N));
        float tr = g_scal[0];
        float pj = g_scal[1];
        out[0] = (float)N / 5.0f +
                 nrd * ((0.5f - 1.0f / PI_F) * tr + pj / PI_F);
    }
}

// ==========================================================================
// host orchestration
// ==========================================================================
extern "C" void kernel_launch(void* const* d_in, const int* in_sizes, int n_in,
                              void* d_out, int out_size)
{
    (void)in_sizes; (void)n_in; (void)out_size;
    const float* x     = (const float*)d_in[0];
    const float* c     = (const float*)d_in[1];
    const float* alpha = (const float*)d_in[2];
    float* out = (float*)d_out;

    float *Sp, *Wp, *iDp, *T2p, *Pp, *scalp;
    cudaGetSymbolAddress((void**)&Sp,    g_S);
    cudaGetSymbolAddress((void**)&Wp,    g_W);
    cudaGetSymbolAddress((void**)&iDp,   g_invD);
    cudaGetSymbolAddress((void**)&T2p,   g_T2);
    cudaGetSymbolAddress((void**)&Pp,    g_P);
    cudaGetSymbolAddress((void**)&scalp, g_scal);

    int potrf_smem = 2 * NB * LDA * (int)sizeof(float);
    cudaFuncSetAttribute(potrf_invert,
                         cudaFuncAttributeMaxDynamicSharedMemorySize,
                         potrf_smem);

    // 1. gram: sigma = clip(X X^T / D), lower tiles only
    nt_tile_kernel<<<NBLK * (NBLK + 1) / 2, 256>>>(x, D, Sp, N, D,
                                                   1.0f / (float)D, 0);

    // 2. arc-cosine kernel step (DEPTH=2 -> one step)
    diag_kernel<<<N / 256, 256>>>();
    step_kernel<<<dim3(N / 32, N / 8), dim3(32, 8)>>>(alpha);

    // 3. blocked Cholesky (in place, lower)
    for (int k = 0; k < NBLK; k++) {
        potrf_invert<<<1, 256, potrf_smem>>>(k);
        if (k < NBLK - 1) {
            int rows = (NBLK - 1 - k) * NB;
            gemm_nt<<<dim3(2, rows / 64), 256>>>(
                Sp + (size_t)(k + 1) * NB * N + (size_t)k * NB, N,
                iDp + (size_t)k * NB * NB, NB,
                Pp, NB, NB);
            copy_panel<<<rows, NB>>>(k);
            int T2 = NBLK - 1 - k;
            nt_tile_kernel<<<T2 * (T2 + 1) / 2, 256>>>(
                Pp, NB,
                Sp + (size_t)(k + 1) * NB * N + (size_t)(k + 1) * NB, N,
                NB, 1.0f, 1);
        }
    }

    // 4. divide & conquer triangular inversion: W = L^{-1} (lower)
    zero_kernel<<<4096, 256>>>(Wp, N * N);
    copy_diag_kernel<<<dim3(64, NBLK), 256>>>();
    for (int lev = 0; lev < 4; lev++) {
        int s = 128 << lev;
        int pairs = N / (2 * s);
        size_t strW = (size_t)2 * s * (N + 1);
        // T_q = W11 * L10
        gemm_nn_b<<<dim3(s / 64, s / 64, pairs), 256>>>(
            Wp + (size_t)s * N + s, strW, N,
            Sp + (size_t)s * N,     strW, N,
            T2p, (size_t)s * s, s,
            s, 1.0f);
        // W10 = -T_q * W00
        gemm_nn_b<<<dim3(s / 64, s / 64, pairs), 256>>>(
            T2p, (size_t)s * s, s,
            Wp, strW, N,
            Wp + (size_t)s * N, strW, N,
            s, -1.0f);
    }

    // 5. reductions + final scalar
    zero_kernel<<<1, 32>>>(scalp, 4);
    fnorm_kernel<<<1024, 256>>>();          // trace(inv) = ||L^{-1}||_F^2
    proj_kernel<<<N, 256>>>(c);             // c^T inv c = ||L^{-1} c||^2
    final_kernel<<<1, 256>>>(out);
}

// round 6
// speedup vs baseline: 2.9414x; 1.2296x over previous
#include <cuda_runtime.h>
#include <cuda_bf16.h>
#include <math.h>
#include <stdint.h>

#define N 2048
#define D 16384
#define NB 128
#define LDA 129            // padded smem stride (bank-conflict-free columns)
#define NBLK 16            // N / NB
#define PI_F 3.14159265358979323846f

// ---------------- device scratch (no allocations allowed) ----------------
__device__ float g_S[(size_t)N * N];        // gram / sigma / L (lower, in place)
__device__ float g_W[(size_t)N * N];        // L^{-1} (lower)
__device__ float g_invD[NBLK * NB * NB];    // per-panel inv(L11)
__device__ float g_T2[(size_t)1024 * 1024]; // D&C inversion scratch
__device__ float g_P[(size_t)N * NB];       // TRSM panel scratch
__device__ float g_diag[N];                 // diag snapshot
__device__ float g_scal[4];                 // [0]=trace acc, [1]=proj acc
__device__ __nv_bfloat16 g_hi[(size_t)N * D];
__device__ __nv_bfloat16 g_lo[(size_t)N * D];

// ==========================================================================
__device__ __forceinline__ uint32_t smem_u32(const void* p) {
    uint32_t a;
    asm("{ .reg .u64 t; cvta.to.shared.u64 t, %1; cvt.u32.u64 %0, t; }"
        : "=r"(a) : "l"(p));
    return a;
}

// ==========================================================================
// split conversion: x -> hi (bf16) + lo (bf16 of residual)
// ==========================================================================
__global__ void split_kernel(const float* __restrict__ x)
{
    size_t total = (size_t)N * D;
    for (size_t i = blockIdx.x * (size_t)blockDim.x + threadIdx.x; i < total;
         i += (size_t)gridDim.x * blockDim.x) {
        float v = x[i];
        __nv_bfloat16 h = __float2bfloat16(v);
        g_hi[i] = h;
        g_lo[i] = __float2bfloat16(v - __bfloat162float(h));
    }
}

// ==========================================================================
// gram via mma.sync bf16 split GEMM (baseline PTX tensor path):
// sigma = clip((hi*hi^T + hi*lo^T + lo*hi^T)/D, -1, 1), lower 128x128 tiles
// ==========================================================================
#define BKG 32
#define GSTRIDE 40                         // bf16 elems per smem row (pad)
#define GTILE_B (128 * GSTRIDE * 2)        // 10240 bytes per operand tile
#define GRAM_SMEM (2 * 4 * GTILE_B)        // 81920 bytes

__device__ __forceinline__ void ldsm_x4(uint32_t* r, uint32_t addr) {
    asm volatile("ldmatrix.sync.aligned.m8n8.x4.shared.b16 {%0,%1,%2,%3}, [%4];"
                 : "=r"(r[0]), "=r"(r[1]), "=r"(r[2]), "=r"(r[3]) : "r"(addr));
}
__device__ __forceinline__ void ldsm_x2(uint32_t* r, uint32_t addr) {
    asm volatile("ldmatrix.sync.aligned.m8n8.x2.shared.b16 {%0,%1}, [%2];"
                 : "=r"(r[0]), "=r"(r[1]) : "r"(addr));
}
__device__ __forceinline__ void mma_bf16(float* d, const uint32_t* a,
                                         const uint32_t* b) {
    asm volatile(
        "mma.sync.aligned.m16n8k16.row.col.f32.bf16.bf16.f32 "
        "{%0,%1,%2,%3}, {%4,%5,%6,%7}, {%8,%9}, {%0,%1,%2,%3};"
        : "+f"(d[0]), "+f"(d[1]), "+f"(d[2]), "+f"(d[3])
        : "r"(a[0]), "r"(a[1]), "r"(a[2]), "r"(a[3]), "r"(b[0]), "r"(b[1]));
}
#define CP_ASYNC(dst, src) \
    asm volatile("cp.async.cg.shared.global [%0], [%1], 16;" \
                 :: "r"(dst), "l"(src))
#define CP_COMMIT() asm volatile("cp.async.commit_group;" ::: "memory")

__global__ __launch_bounds__(256, 1)
void gram_mma_kernel(float* __restrict__ Cbase)
{
    extern __shared__ char dsm[];
    uint32_t sbase = smem_u32(dsm);

    int tid  = threadIdx.x;
    int wid  = tid >> 5;
    int lane = tid & 31;

    // tile-pair mapping (bi >= bj)
    int t = blockIdx.x;
    int bi = (int)((sqrtf(8.f * (float)t + 1.f) - 1.f) * 0.5f);
    while ((bi + 1) * (bi + 2) / 2 <= t) bi++;
    while (bi * (bi + 1) / 2 > t) bi--;
    int bj = t - bi * (bi + 1) / 2;

    const __nv_bfloat16* srcs[4] = {
        g_hi + (size_t)bi * 128 * D,   // Ahi
        g_lo + (size_t)bi * 128 * D,   // Alo
        g_hi + (size_t)bj * 128 * D,   // Bhi
        g_lo + (size_t)bj * 128 * D    // Blo
    };

    // per-thread load slots: 2048 16B-chunks per stage / 256 thr = 8
    int m0w = (wid & 1) * 64;
    int n0w = (wid >> 1) * 32;

    float acc[4][4][4];
#pragma unroll
    for (int im = 0; im < 4; im++)
#pragma unroll
        for (int jn = 0; jn < 4; jn++)
#pragma unroll
            for (int e = 0; e < 4; e++) acc[im][jn][e] = 0.f;

    const int S = D / BKG;   // 512 stages

    // prefetch stage 0 into buffer 0
    {
        int k0 = 0;
#pragma unroll
        for (int it = 0; it < 8; it++) {
            int idx = tid + it * 256;
            int tile = idx >> 9;
            int rem = idx & 511;
            int r = rem >> 2, ch = rem & 3;
            uint32_t dst = sbase + (uint32_t)tile * GTILE_B + r * 80 + ch * 16;
            CP_ASYNC(dst, srcs[tile] + (size_t)r * D + k0 + ch * 8);
        }
        CP_COMMIT();
    }

#pragma unroll 1
    for (int s = 0; s < S; s++) {
        if (s + 1 < S) {
            int k0 = (s + 1) * BKG;
            uint32_t boff = (uint32_t)((s + 1) & 1) * (4 * GTILE_B);
#pragma unroll
            for (int it = 0; it < 8; it++) {
                int idx = tid + it * 256;
                int tile = idx >> 9;
                int rem = idx & 511;
                int r = rem >> 2, ch = rem & 3;
                uint32_t dst = sbase + boff + (uint32_t)tile * GTILE_B +
                               r * 80 + ch * 16;
                CP_ASYNC(dst, srcs[tile] + (size_t)r * D + k0 + ch * 8);
            }
            CP_COMMIT();
            asm volatile("cp.async.wait_group 1;" ::: "memory");
        } else {
            asm volatile("cp.async.wait_group 0;" ::: "memory");
        }
        __syncthreads();

        uint32_t buf = sbase + (uint32_t)(s & 1) * (4 * GTILE_B);
        uint32_t Ahi_b = buf;
        uint32_t Alo_b = buf + GTILE_B;
        uint32_t Bhi_b = buf + 2 * GTILE_B;
        uint32_t Blo_b = buf + 3 * GTILE_B;

#pragma unroll
        for (int ks = 0; ks < 2; ks++) {
            int kof = ks * 16;
            int arow = lane & 15;
            int acol = kof + 8 * (lane >> 4);
            uint32_t ah[4][4], al[4][4];
#pragma unroll
            for (int im = 0; im < 4; im++) {
                uint32_t ro = (uint32_t)(m0w + im * 16 + arow) * 80 + acol * 2;
                ldsm_x4(ah[im], Ahi_b + ro);
                ldsm_x4(al[im], Alo_b + ro);
            }
            int brow = lane & 7;
            int bcol = kof + 8 * ((lane >> 3) & 1);
            uint32_t bh[4][2], bl[4][2];
#pragma unroll
            for (int jn = 0; jn < 4; jn++) {
                uint32_t ro = (uint32_t)(n0w + jn * 8 + brow) * 80 + bcol * 2;
                ldsm_x2(bh[jn], Bhi_b + ro);
                ldsm_x2(bl[jn], Blo_b + ro);
            }
#pragma unroll
            for (int im = 0; im < 4; im++)
#pragma unroll
                for (int jn = 0; jn < 4; jn++) {
                    mma_bf16(acc[im][jn], ah[im], bh[jn]);
                    mma_bf16(acc[im][jn], ah[im], bl[jn]);
                    mma_bf16(acc[im][jn], al[im], bh[jn]);
                }
        }
        __syncthreads();
    }

    // epilogue: scale + clip + store
    const float inv_d = 1.0f / (float)D;
#pragma unroll
    for (int im = 0; im < 4; im++) {
        int row = bi * 128 + m0w + im * 16 + (lane >> 2);
#pragma unroll
        for (int jn = 0; jn < 4; jn++) {
            int col = bj * 128 + n0w + jn * 8 + (lane & 3) * 2;
            float v0 = fminf(fmaxf(acc[im][jn][0] * inv_d, -1.f), 1.f);
            float v1 = fminf(fmaxf(acc[im][jn][1] * inv_d, -1.f), 1.f);
            float v2 = fminf(fmaxf(acc[im][jn][2] * inv_d, -1.f), 1.f);
            float v3 = fminf(fmaxf(acc[im][jn][3] * inv_d, -1.f), 1.f);
            Cbase[(size_t)row * N + col]           = v0;
            Cbase[(size_t)row * N + col + 1]       = v1;
            Cbase[(size_t)(row + 8) * N + col]     = v2;
            Cbase[(size_t)(row + 8) * N + col + 1] = v3;
        }
    }
}

// ==========================================================================
// NT tile kernel (fp32 SIMT) — SYRK trailing update (mode 1: C -= acc)
// ==========================================================================
__global__ __launch_bounds__(256, 1)
void nt_tile_kernel(const float* __restrict__ Abase, int lda,
                    float* __restrict__ Cbase, int ldc,
                    int K, float scale, int mode)
{
    __shared__ float As[8][128];
    __shared__ float Bs[8][128];

    int t = blockIdx.x;
    int bi = (int)((sqrtf(8.f * (float)t + 1.f) - 1.f) * 0.5f);
    while ((bi + 1) * (bi + 2) / 2 <= t) bi++;
    while (bi * (bi + 1) / 2 > t) bi--;
    int bj = t - bi * (bi + 1) / 2;

    int tid = threadIdx.x;
    int tx = tid & 15, ty = tid >> 4;

    int lrow = tid >> 1;
    int lkk  = (tid & 1) * 4;
    const float* Ap = Abase + (size_t)(bi * 128 + lrow) * lda + lkk;
    const float* Bp = Abase + (size_t)(bj * 128 + lrow) * lda + lkk;

    float4 pa = *(const float4*)(Ap);
    float4 pb = *(const float4*)(Bp);

    float acc[8][8];
#pragma unroll
    for (int i = 0; i < 8; i++)
#pragma unroll
        for (int j = 0; j < 8; j++) acc[i][j] = 0.f;

    for (int k0 = 0; k0 < K; k0 += 8) {
        if (k0) __syncthreads();
        As[lkk + 0][lrow] = pa.x; As[lkk + 1][lrow] = pa.y;
        As[lkk + 2][lrow] = pa.z; As[lkk + 3][lrow] = pa.w;
        Bs[lkk + 0][lrow] = pb.x; Bs[lkk + 1][lrow] = pb.y;
        Bs[lkk + 2][lrow] = pb.z; Bs[lkk + 3][lrow] = pb.w;
        __syncthreads();
        if (k0 + 8 < K) {
            pa = *(const float4*)(Ap + k0 + 8);
            pb = *(const float4*)(Bp + k0 + 8);
        }
#pragma unroll
        for (int kk = 0; kk < 8; kk++) {
            float4 a0 = *(const float4*)&As[kk][ty * 4];
            float4 a1 = *(const float4*)&As[kk][64 + ty * 4];
            float4 b0 = *(const float4*)&Bs[kk][tx * 4];
            float4 b1 = *(const float4*)&Bs[kk][64 + tx * 4];
            float a[8] = {a0.x, a0.y, a0.z, a0.w, a1.x, a1.y, a1.z, a1.w};
            float b[8] = {b0.x, b0.y, b0.z, b0.w, b1.x, b1.y, b1.z, b1.w};
#pragma unroll
            for (int i = 0; i < 8; i++)
#pragma unroll
                for (int j = 0; j < 8; j++)
                    acc[i][j] += a[i] * b[j];
        }
    }

#pragma unroll
    for (int i = 0; i < 8; i++) {
        int r = bi * 128 + ((i < 4) ? ty * 4 + i : 64 + ty * 4 + (i - 4));
#pragma unroll
        for (int j = 0; j < 8; j++) {
            int cc = bj * 128 + ((j < 4) ? tx * 4 + j : 64 + tx * 4 + (j - 4));
            float* cp = Cbase + (size_t)r * ldc + cc;
            if (mode == 0) {
                float v = acc[i][j] * scale;
                *cp = fminf(fmaxf(v, -1.f), 1.f);
            } else {
                *cp -= acc[i][j];
            }
        }
    }
}

// ==========================================================================
__global__ void diag_kernel()
{
    int i = blockIdx.x * blockDim.x + threadIdx.x;
    if (i < N) g_diag[i] = g_S[(size_t)i * N + i];
}

__global__ void step_kernel(const float* __restrict__ alpha_p)
{
    int j = blockIdx.x * 32 + threadIdx.x;
    int i = blockIdx.y * 8 + threadIdx.y;
    if (i >= N || j > i) return;
    float a  = *alpha_p;
    float a2 = a * a;
    float cross = sqrtf(g_diag[i] * g_diag[j]);
    float s = g_S[(size_t)i * N + j];
    float m = fminf(fmaxf(s / cross, -1.f), 1.f);
    float q = 1.f - m * m;
    float sq, ac;
    if (q > 0.f) { sq = sqrtf(q); ac = acosf(m); }
    else         { sq = 0.f;      ac = (m > 0.f) ? 0.f : PI_F; }
    float f  = (sq + m * (PI_F - ac)) / PI_F;
    float ts = cross * f;
    float ov = (s + a2 * ts) / (1.f + a2);
    g_S[(size_t)i * N + j] = fminf(fmaxf(ov, -1.f), 1.f);
}

// ==========================================================================
// panel factorization + inversion of 128x128 diag block (round-4 version)
// ==========================================================================
__global__ __launch_bounds__(256, 1)
void potrf_invert(int kb)
{
    extern __shared__ float sh[];
    float* A = sh;
    float* W = sh + NB * LDA;
    __shared__ float Ts[3 * 32 * 33];
    int tid = threadIdx.x;
    int base = kb * NB;

    for (int idx = tid; idx < NB * NB; idx += 256) {
        int i = idx >> 7, j = idx & 127;
        A[i * LDA + j] = (j <= i) ? g_S[(size_t)(base + i) * N + base + j] : 0.f;
        W[i * LDA + j] = 0.f;
    }
    __syncthreads();

    for (int p = 0; p < 4; p++) {
        int off = p * 32;

        if (tid < 32) {
            const unsigned FULL = 0xffffffffu;
            int r = tid;
            float ar[32];
#pragma unroll
            for (int t = 0; t < 32; t++)
                ar[t] = (t <= r) ? A[(off + r) * LDA + off + t] : 0.f;
            float rs_reg = 0.f;
#pragma unroll
            for (int j = 0; j < 32; j++) {
                float d   = __shfl_sync(FULL, ar[j], j);
                float rsj = rsqrtf(d);
                float lj  = ar[j] * rsj;
                ar[j] = lj;
                if (r == j) rs_reg = rsj;
#pragma unroll
                for (int t = j + 1; t < 32; t++) {
                    float ltj = __shfl_sync(FULL, lj, t);
                    ar[t] -= lj * ltj;
                }
            }
            int c = r;
            float w[32];
#pragma unroll
            for (int t = 0; t < 32; t++) w[t] = 0.f;
#pragma unroll
            for (int i = 0; i < 32; i++) {
                float s = (i == c) ? 1.f : 0.f;
#pragma unroll
                for (int t = 0; t < i; t++) {
                    float lit = __shfl_sync(FULL, ar[t], i);
                    s -= lit * w[t];
                }
                float rsi = __shfl_sync(FULL, rs_reg, i);
                w[i] = (i >= c) ? s * rsi : 0.f;
            }
#pragma unroll
            for (int t = 0; t < 32; t++)
                if (t <= r) A[(off + r) * LDA + off + t] = ar[t];
#pragma unroll
            for (int i = 0; i < 32; i++)
                if (i >= c) W[(off + i) * LDA + off + c] = w[i];
        }
        __syncthreads();

        int nr = NB - off - 32;
        if (nr > 0) {
            for (int idx = tid; idx < nr * 32; idx += 256) {
                int r = idx >> 5, cc = idx & 31;
                const float* arow = A + (size_t)(off + 32 + r) * LDA + off;
                const float* wrow = W + (size_t)(off + cc) * LDA + off;
                float s = 0.f;
#pragma unroll 8
                for (int t = 0; t <= cc; t++) s += arow[t] * wrow[t];
                Ts[idx] = s;
            }
            __syncthreads();
            for (int idx = tid; idx < nr * 32; idx += 256) {
                int r = idx >> 5, cc = idx & 31;
                A[(off + 32 + r) * LDA + off + cc] = Ts[idx];
            }
            __syncthreads();

            for (int idx = tid; idx < nr * nr; idx += 256) {
                int i = idx / nr + off + 32;
                int t = idx % nr + off + 32;
                if (t <= i) {
                    const float* ai = A + (size_t)i * LDA + off;
                    const float* at = A + (size_t)t * LDA + off;
                    float acc = 0.f;
#pragma unroll
                    for (int k = 0; k < 32; k++) acc += ai[k] * at[k];
                    A[i * LDA + t] -= acc;
                }
            }
            __syncthreads();
        }
    }

    for (int ib = 1; ib < 4; ib++) {
        for (int idx = tid; idx < ib * 1024; idx += 256) {
            int j = idx >> 10, e = idx & 1023;
            int r = e >> 5, c = e & 31;
            float acc = 0.f;
            for (int tb = j; tb < ib; tb++) {
                const float* lr = A + (size_t)(32 * ib + r) * LDA + 32 * tb;
#pragma unroll 8
                for (int k = 0; k < 32; k++)
                    acc += lr[k] * W[(32 * tb + k) * LDA + 32 * j + c];
            }
            Ts[j * 1056 + r * 33 + c] = acc;
        }
        __syncthreads();
        for (int idx = tid; idx < ib * 1024; idx += 256) {
            int j = idx >> 10, e = idx & 1023;
            int r = e >> 5, c = e & 31;
            const float* wi = W + (size_t)(32 * ib + r) * LDA + 32 * ib;
            float acc = 0.f;
            for (int k = 0; k <= r; k++)
                acc += wi[k] * Ts[j * 1056 + k * 33 + c];
            W[(32 * ib + r) * LDA + 32 * j + c] = -acc;
        }
        __syncthreads();
    }

    for (int idx = tid; idx < NB * NB; idx += 256) {
        int i = idx >> 7, j = idx & 127;
        if (j <= i) g_S[(size_t)(base + i) * N + base + j] = A[i * LDA + j];
        g_invD[(size_t)kb * NB * NB + idx] = W[i * LDA + j];
    }
}

// ==========================================================================
// NT GEMM for TRSM panels: C = A * B^T (64x64 tiles)
// ==========================================================================
__global__ __launch_bounds__(256, 2)
void gemm_nt(const float* __restrict__ A, int lda,
             const float* __restrict__ B, int ldb,
             float* __restrict__ C, int ldc, int K)
{
    __shared__ float As[16][64];
    __shared__ float Bs[16][64];
    int bi = blockIdx.y, bj = blockIdx.x;
    int tid = threadIdx.x;
    int tx = tid & 15, ty = tid >> 4;

    const float* Ab = A + (size_t)(bi * 64) * lda;
    const float* Bb = B + (size_t)(bj * 64) * ldb;

    int arow = tid >> 2, akk = (tid & 3) << 2;

    float acc[4][4];
#pragma unroll
    for (int i = 0; i < 4; i++)
#pragma unroll
        for (int j = 0; j < 4; j++) acc[i][j] = 0.f;

    for (int k0 = 0; k0 < K; k0 += 16) {
        float4 va = *(const float4*)(Ab + (size_t)arow * lda + k0 + akk);
        float4 vb = *(const float4*)(Bb + (size_t)arow * ldb + k0 + akk);
        As[akk + 0][arow] = va.x; As[akk + 1][arow] = va.y;
        As[akk + 2][arow] = va.z; As[akk + 3][arow] = va.w;
        Bs[akk + 0][arow] = vb.x; Bs[akk + 1][arow] = vb.y;
        Bs[akk + 2][arow] = vb.z; Bs[akk + 3][arow] = vb.w;
        __syncthreads();
#pragma unroll
        for (int kk = 0; kk < 16; kk++) {
            float4 a = *(const float4*)&As[kk][ty * 4];
            float4 b = *(const float4*)&Bs[kk][tx * 4];
            float av[4] = {a.x, a.y, a.z, a.w};
            float bv[4] = {b.x, b.y, b.z, b.w};
#pragma unroll
            for (int i = 0; i < 4; i++)
#pragma unroll
                for (int j = 0; j < 4; j++)
                    acc[i][j] += av[i] * bv[j];
        }
        __syncthreads();
    }

#pragma unroll
    for (int i = 0; i < 4; i++)
#pragma unroll
        for (int j = 0; j < 4; j++)
            C[(size_t)(bi * 64 + ty * 4 + i) * ldc + bj * 64 + tx * 4 + j] =
                acc[i][j];
}

__global__ void copy_panel(int kb)
{
    int r = blockIdx.x;
    int j = threadIdx.x;  // 128
    g_S[(size_t)((kb + 1) * NB + r) * N + kb * NB + j] = g_P[(size_t)r * NB + j];
}

// ==========================================================================
// batched NN GEMM, 128x128 tiles / 8x8 micro-tiles (for D&C inversion)
// ==========================================================================
__global__ __launch_bounds__(256, 1)
void gemm_nn_b128(const float* __restrict__ A, size_t strA, int lda,
                  const float* __restrict__ B, size_t strB, int ldb,
                  float* __restrict__ C, size_t strC, int ldc,
                  int K, float alpha)
{
    A += (size_t)blockIdx.z * strA;
    B += (size_t)blockIdx.z * strB;
    C += (size_t)blockIdx.z * strC;

    __shared__ float As[8][128];
    __shared__ float Bs[8][128];

    int bi = blockIdx.y, bj = blockIdx.x;
    int tid = threadIdx.x;
    int tx = tid & 15, ty = tid >> 4;

    int lrow = tid >> 1;
    int lkk  = (tid & 1) * 4;
    int brow = tid >> 5;
    int bcol = (tid & 31) * 4;

    const float* Ap = A + (size_t)(bi * 128 + lrow) * lda + lkk;
    const float* Bp = B + bj * 128 + bcol;

    float acc[8][8];
#pragma unroll
    for (int i = 0; i < 8; i++)
#pragma unroll
        for (int j = 0; j < 8; j++) acc[i][j] = 0.f;

    for (int k0 = 0; k0 < K; k0 += 8) {
        float4 va = *(const float4*)(Ap + k0);
        float4 vb = *(const float4*)(Bp + (size_t)(k0 + brow) * ldb);
        if (k0) __syncthreads();
        As[lkk + 0][lrow] = va.x; As[lkk + 1][lrow] = va.y;
        As[lkk + 2][lrow] = va.z; As[lkk + 3][lrow] = va.w;
        *(float4*)&Bs[brow][bcol] = vb;
        __syncthreads();
#pragma unroll
        for (int kk = 0; kk < 8; kk++) {
            float4 a0 = *(const float4*)&As[kk][ty * 4];
            float4 a1 = *(const float4*)&As[kk][64 + ty * 4];
            float4 b0 = *(const float4*)&Bs[kk][tx * 4];
            float4 b1 = *(const float4*)&Bs[kk][64 + tx * 4];
            float a[8] = {a0.x, a0.y, a0.z, a0.w, a1.x, a1.y, a1.z, a1.w};
            float b[8] = {b0.x, b0.y, b0.z, b0.w, b1.x, b1.y, b1.z, b1.w};
#pragma unroll
            for (int i = 0; i < 8; i++)
#pragma unroll
                for (int j = 0; j < 8; j++)
                    acc[i][j] += a[i] * b[j];
        }
    }

#pragma unroll
    for (int i = 0; i < 8; i++) {
        int r = bi * 128 + ((i < 4) ? ty * 4 + i : 64 + ty * 4 + (i - 4));
#pragma unroll
        for (int j = 0; j < 8; j++) {
            int cc = bj * 128 + ((j < 4) ? tx * 4 + j : 64 + tx * 4 + (j - 4));
            C[(size_t)r * ldc + cc] = alpha * acc[i][j];
        }
    }
}

// ==========================================================================
__global__ void zero_kernel(float* p, int n)
{
    for (int i = blockIdx.x * blockDim.x + threadIdx.x; i < n;
         i += gridDim.x * blockDim.x)
        p[i] = 0.f;
}

__global__ void copy_diag_kernel()
{
    int kb = blockIdx.y;
    int idx = blockIdx.x * 256 + threadIdx.x;
    int i = idx >> 7, j = idx & 127;
    g_W[(size_t)(kb * NB + i) * N + kb * NB + j] =
        g_invD[(size_t)kb * NB * NB + idx];
}

__global__ void fnorm_kernel()
{
    __shared__ float red[256];
    float s = 0.f;
    size_t total = (size_t)N * N;
    for (size_t i = blockIdx.x * blockDim.x + threadIdx.x; i < total;
         i += (size_t)gridDim.x * blockDim.x) {
        float v = g_W[i];
        s += v * v;
    }
    red[threadIdx.x] = s; __syncthreads();
    for (int o = 128; o > 0; o >>= 1) {
        if (threadIdx.x < o) red[threadIdx.x] += red[threadIdx.x + o];
        __syncthreads();
    }
    if (threadIdx.x == 0) atomicAdd(&g_scal[0], red[0]);
}

__global__ void proj_kernel(const float* __restrict__ c)
{
    __shared__ float red[256];
    int r = blockIdx.x;
    const float* row = g_W + (size_t)r * N;
    float s = 0.f;
    for (int j = threadIdx.x; j < N; j += 256) s += row[j] * c[j];
    red[threadIdx.x] = s; __syncthreads();
    for (int o = 128; o > 0; o >>= 1) {
        if (threadIdx.x < o) red[threadIdx.x] += red[threadIdx.x + o];
        __syncthreads();
    }
    if (threadIdx.x == 0) {
        float y = red[0];
        atomicAdd(&g_scal[1], y * y);
    }
}

__global__ void final_kernel(float* out)
{
    __shared__ float red[256];
    float s = 0.f;
    for (int i = threadIdx.x; i < N; i += 256)
        s += logf(g_S[(size_t)i * N + i]);
    red[threadIdx.x] = s; __syncthreads();
    for (int o = 128; o > 0; o >>= 1) {
        if (threadIdx.x < o) red[threadIdx.x] += red[threadIdx.x + o];
        __syncthreads();
    }
    if (threadIdx.x == 0) {
        float nrd = expf(red[0] * (2.0f / (float)N));
        out[0] = (float)N / 5.0f +
                 nrd * ((0.5f - 1.0f / PI_F) * g_scal[0] + g_scal[1] / PI_F);
    }
}

// ==========================================================================
// host orchestration
// ==========================================================================
extern "C" void kernel_launch(void* const* d_in, const int* in_sizes, int n_in,
                              void* d_out, int out_size)
{
    (void)in_sizes; (void)n_in; (void)out_size;
    const float* x     = (const float*)d_in[0];
    const float* c     = (const float*)d_in[1];
    const float* alpha = (const float*)d_in[2];
    float* out = (float*)d_out;

    float *Sp, *Wp, *iDp, *T2p, *Pp, *scalp;
    cudaGetSymbolAddress((void**)&Sp,    g_S);
    cudaGetSymbolAddress((void**)&Wp,    g_W);
    cudaGetSymbolAddress((void**)&iDp,   g_invD);
    cudaGetSymbolAddress((void**)&T2p,   g_T2);
    cudaGetSymbolAddress((void**)&Pp,    g_P);
    cudaGetSymbolAddress((void**)&scalp, g_scal);

    int potrf_smem = 2 * NB * LDA * (int)sizeof(float);
    cudaFuncSetAttribute(potrf_invert,
                         cudaFuncAttributeMaxDynamicSharedMemorySize,
                         potrf_smem);
    cudaFuncSetAttribute(gram_mma_kernel,
                         cudaFuncAttributeMaxDynamicSharedMemorySize,
                         GRAM_SMEM);

    // 1. gram via mma.sync bf16 split GEMM
    split_kernel<<<4096, 256>>>(x);
    gram_mma_kernel<<<NBLK * (NBLK + 1) / 2, 256, GRAM_SMEM>>>(Sp);

    // 2. arc-cosine kernel step
    diag_kernel<<<N / 256, 256>>>();
    step_kernel<<<dim3(N / 32, N / 8), dim3(32, 8)>>>(alpha);

    // 3. blocked Cholesky (in place, lower)
    for (int k = 0; k < NBLK; k++) {
        potrf_invert<<<1, 256, potrf_smem>>>(k);
        if (k < NBLK - 1) {
            int rows = (NBLK - 1 - k) * NB;
            gemm_nt<<<dim3(2, rows / 64), 256>>>(
                Sp + (size_t)(k + 1) * NB * N + (size_t)k * NB, N,
                iDp + (size_t)k * NB * NB, NB,
                Pp, NB, NB);
            copy_panel<<<rows, NB>>>(k);
            int T2 = NBLK - 1 - k;
            nt_tile_kernel<<<T2 * (T2 + 1) / 2, 256>>>(
                Pp, NB,
                Sp + (size_t)(k + 1) * NB * N + (size_t)(k + 1) * NB, N,
                NB, 1.0f, 1);
        }
    }

    // 4. divide & conquer triangular inversion: W = L^{-1}
    zero_kernel<<<4096, 256>>>(Wp, N * N);
    copy_diag_kernel<<<dim3(64, NBLK), 256>>>();
    for (int lev = 0; lev < 4; lev++) {
        int s = 128 << lev;
        int pairs = N / (2 * s);
        size_t strW = (size_t)2 * s * (N + 1);
        gemm_nn_b128<<<dim3(s / 128, s / 128, pairs), 256>>>(
            Wp + (size_t)s * N + s, strW, N,
            Sp + (size_t)s * N,     strW, N,
            T2p, (size_t)s * s, s,
            s, 1.0f);
        gemm_nn_b128<<<dim3(s / 128, s / 128, pairs), 256>>>(
            T2p, (size_t)s * s, s,
            Wp, strW, N,
            Wp + (size_t)s * N, strW, N,
            s, -1.0f);
    }

    // 5. reductions + final scalar
    zero_kernel<<<1, 32>>>(scalp, 4);
    fnorm_kernel<<<1024, 256>>>();
    proj_kernel<<<N, 256>>>(c);
    final_kernel<<<1, 256>>>(out);
}

// round 7
// speedup vs baseline: 3.5681x; 1.2131x over previous
#include <cuda_runtime.h>
#include <cuda_bf16.h>
#include <math.h>
#include <stdint.h>

#define N 2048
#define D 16384
#define NB 128
#define LDA 129            // padded smem stride (bank-conflict-free columns)
#define NBLK 16            // N / NB
#define PI_F 3.14159265358979323846f

// ---------------- device scratch (no allocations allowed) ----------------
__device__ float g_S[(size_t)N * N];        // gram / sigma / L (lower, in place)
__device__ float g_W[(size_t)N * N];        // L^{-1} (lower)
__device__ float g_invD[NBLK * NB * NB];    // per-panel inv(L11)
__device__ float g_T2[(size_t)1024 * 1024]; // D&C inversion scratch
__device__ float g_P[(size_t)N * NB];       // TRSM panel scratch
__device__ float g_diag[N];                 // diag snapshot
__device__ float g_scal[4];                 // [0]=trace acc, [1]=proj acc
__device__ __nv_bfloat16 g_hi[(size_t)N * D];
__device__ __nv_bfloat16 g_lo[(size_t)N * D];

// ==========================================================================
__device__ __forceinline__ uint32_t smem_u32(const void* p) {
    uint32_t a;
    asm("{ .reg .u64 t; cvta.to.shared.u64 t, %1; cvt.u32.u64 %0, t; }"
        : "=r"(a) : "l"(p));
    return a;
}

// ==========================================================================
// split conversion: x -> hi (bf16) + lo (bf16 of residual)
// ==========================================================================
__global__ void split_kernel(const float* __restrict__ x)
{
    size_t total = (size_t)N * D;
    for (size_t i = blockIdx.x * (size_t)blockDim.x + threadIdx.x; i < total;
         i += (size_t)gridDim.x * blockDim.x) {
        float v = x[i];
        __nv_bfloat16 h = __float2bfloat16(v);
        g_hi[i] = h;
        g_lo[i] = __float2bfloat16(v - __bfloat162float(h));
    }
}

// ==========================================================================
// gram via mma.sync bf16 split GEMM:
// sigma = clip((hi*hi^T + hi*lo^T + lo*hi^T)/D, -1, 1), lower 128x128 tiles
// ==========================================================================
#define BKG 32
#define GSTRIDE 40
#define GTILE_B (128 * GSTRIDE * 2)
#define GRAM_SMEM (2 * 4 * GTILE_B)

__device__ __forceinline__ void ldsm_x4(uint32_t* r, uint32_t addr) {
    asm volatile("ldmatrix.sync.aligned.m8n8.x4.shared.b16 {%0,%1,%2,%3}, [%4];"
                 : "=r"(r[0]), "=r"(r[1]), "=r"(r[2]), "=r"(r[3]) : "r"(addr));
}
__device__ __forceinline__ void ldsm_x2(uint32_t* r, uint32_t addr) {
    asm volatile("ldmatrix.sync.aligned.m8n8.x2.shared.b16 {%0,%1}, [%2];"
                 : "=r"(r[0]), "=r"(r[1]) : "r"(addr));
}
__device__ __forceinline__ void mma_bf16(float* d, const uint32_t* a,
                                         const uint32_t* b) {
    asm volatile(
        "mma.sync.aligned.m16n8k16.row.col.f32.bf16.bf16.f32 "
        "{%0,%1,%2,%3}, {%4,%5,%6,%7}, {%8,%9}, {%0,%1,%2,%3};"
        : "+f"(d[0]), "+f"(d[1]), "+f"(d[2]), "+f"(d[3])
        : "r"(a[0]), "r"(a[1]), "r"(a[2]), "r"(a[3]), "r"(b[0]), "r"(b[1]));
}
#define CP_ASYNC(dst, src) \
    asm volatile("cp.async.cg.shared.global [%0], [%1], 16;" \
                 :: "r"(dst), "l"(src))
#define CP_COMMIT() asm volatile("cp.async.commit_group;" ::: "memory")

__global__ __launch_bounds__(256, 1)
void gram_mma_kernel(float* __restrict__ Cbase)
{
    extern __shared__ char dsm[];
    uint32_t sbase = smem_u32(dsm);

    int tid  = threadIdx.x;
    int wid  = tid >> 5;
    int lane = tid & 31;

    int t = blockIdx.x;
    int bi = (int)((sqrtf(8.f * (float)t + 1.f) - 1.f) * 0.5f);
    while ((bi + 1) * (bi + 2) / 2 <= t) bi++;
    while (bi * (bi + 1) / 2 > t) bi--;
    int bj = t - bi * (bi + 1) / 2;

    const __nv_bfloat16* srcs[4] = {
        g_hi + (size_t)bi * 128 * D,
        g_lo + (size_t)bi * 128 * D,
        g_hi + (size_t)bj * 128 * D,
        g_lo + (size_t)bj * 128 * D
    };

    int m0w = (wid & 1) * 64;
    int n0w = (wid >> 1) * 32;

    float acc[4][4][4];
#pragma unroll
    for (int im = 0; im < 4; im++)
#pragma unroll
        for (int jn = 0; jn < 4; jn++)
#pragma unroll
            for (int e = 0; e < 4; e++) acc[im][jn][e] = 0.f;

    const int S = D / BKG;

    {
        int k0 = 0;
#pragma unroll
        for (int it = 0; it < 8; it++) {
            int idx = tid + it * 256;
            int tile = idx >> 9;
            int rem = idx & 511;
            int r = rem >> 2, ch = rem & 3;
            uint32_t dst = sbase + (uint32_t)tile * GTILE_B + r * 80 + ch * 16;
            CP_ASYNC(dst, srcs[tile] + (size_t)r * D + k0 + ch * 8);
        }
        CP_COMMIT();
    }

#pragma unroll 1
    for (int s = 0; s < S; s++) {
        if (s + 1 < S) {
            int k0 = (s + 1) * BKG;
            uint32_t boff = (uint32_t)((s + 1) & 1) * (4 * GTILE_B);
#pragma unroll
            for (int it = 0; it < 8; it++) {
                int idx = tid + it * 256;
                int tile = idx >> 9;
                int rem = idx & 511;
                int r = rem >> 2, ch = rem & 3;
                uint32_t dst = sbase + boff + (uint32_t)tile * GTILE_B +
                               r * 80 + ch * 16;
                CP_ASYNC(dst, srcs[tile] + (size_t)r * D + k0 + ch * 8);
            }
            CP_COMMIT();
            asm volatile("cp.async.wait_group 1;" ::: "memory");
        } else {
            asm volatile("cp.async.wait_group 0;" ::: "memory");
        }
        __syncthreads();

        uint32_t buf = sbase + (uint32_t)(s & 1) * (4 * GTILE_B);
        uint32_t Ahi_b = buf;
        uint32_t Alo_b = buf + GTILE_B;
        uint32_t Bhi_b = buf + 2 * GTILE_B;
        uint32_t Blo_b = buf + 3 * GTILE_B;

#pragma unroll
        for (int ks = 0; ks < 2; ks++) {
            int kof = ks * 16;
            int arow = lane & 15;
            int acol = kof + 8 * (lane >> 4);
            uint32_t ah[4][4], al[4][4];
#pragma unroll
            for (int im = 0; im < 4; im++) {
                uint32_t ro = (uint32_t)(m0w + im * 16 + arow) * 80 + acol * 2;
                ldsm_x4(ah[im], Ahi_b + ro);
                ldsm_x4(al[im], Alo_b + ro);
            }
            int brow = lane & 7;
            int bcol = kof + 8 * ((lane >> 3) & 1);
            uint32_t bh[4][2], bl[4][2];
#pragma unroll
            for (int jn = 0; jn < 4; jn++) {
                uint32_t ro = (uint32_t)(n0w + jn * 8 + brow) * 80 + bcol * 2;
                ldsm_x2(bh[jn], Bhi_b + ro);
                ldsm_x2(bl[jn], Blo_b + ro);
            }
#pragma unroll
            for (int im = 0; im < 4; im++)
#pragma unroll
                for (int jn = 0; jn < 4; jn++) {
                    mma_bf16(acc[im][jn], ah[im], bh[jn]);
                    mma_bf16(acc[im][jn], ah[im], bl[jn]);
                    mma_bf16(acc[im][jn], al[im], bh[jn]);
                }
        }
        __syncthreads();
    }

    const float inv_d = 1.0f / (float)D;
#pragma unroll
    for (int im = 0; im < 4; im++) {
        int row = bi * 128 + m0w + im * 16 + (lane >> 2);
#pragma unroll
        for (int jn = 0; jn < 4; jn++) {
            int col = bj * 128 + n0w + jn * 8 + (lane & 3) * 2;
            float v0 = fminf(fmaxf(acc[im][jn][0] * inv_d, -1.f), 1.f);
            float v1 = fminf(fmaxf(acc[im][jn][1] * inv_d, -1.f), 1.f);
            float v2 = fminf(fmaxf(acc[im][jn][2] * inv_d, -1.f), 1.f);
            float v3 = fminf(fmaxf(acc[im][jn][3] * inv_d, -1.f), 1.f);
            Cbase[(size_t)row * N + col]           = v0;
            Cbase[(size_t)row * N + col + 1]       = v1;
            Cbase[(size_t)(row + 8) * N + col]     = v2;
            Cbase[(size_t)(row + 8) * N + col + 1] = v3;
        }
    }
}

// ==========================================================================
// NT tile kernel (fp32 SIMT) — SYRK trailing update (mode 1: C -= acc)
// ==========================================================================
__global__ __launch_bounds__(256, 1)
void nt_tile_kernel(const float* __restrict__ Abase, int lda,
                    float* __restrict__ Cbase, int ldc,
                    int K, float scale, int mode)
{
    __shared__ float As[8][128];
    __shared__ float Bs[8][128];

    int t = blockIdx.x;
    int bi = (int)((sqrtf(8.f * (float)t + 1.f) - 1.f) * 0.5f);
    while ((bi + 1) * (bi + 2) / 2 <= t) bi++;
    while (bi * (bi + 1) / 2 > t) bi--;
    int bj = t - bi * (bi + 1) / 2;

    int tid = threadIdx.x;
    int tx = tid & 15, ty = tid >> 4;

    int lrow = tid >> 1;
    int lkk  = (tid & 1) * 4;
    const float* Ap = Abase + (size_t)(bi * 128 + lrow) * lda + lkk;
    const float* Bp = Abase + (size_t)(bj * 128 + lrow) * lda + lkk;

    float4 pa = *(const float4*)(Ap);
    float4 pb = *(const float4*)(Bp);

    float acc[8][8];
#pragma unroll
    for (int i = 0; i < 8; i++)
#pragma unroll
        for (int j = 0; j < 8; j++) acc[i][j] = 0.f;

    for (int k0 = 0; k0 < K; k0 += 8) {
        if (k0) __syncthreads();
        As[lkk + 0][lrow] = pa.x; As[lkk + 1][lrow] = pa.y;
        As[lkk + 2][lrow] = pa.z; As[lkk + 3][lrow] = pa.w;
        Bs[lkk + 0][lrow] = pb.x; Bs[lkk + 1][lrow] = pb.y;
        Bs[lkk + 2][lrow] = pb.z; Bs[lkk + 3][lrow] = pb.w;
        __syncthreads();
        if (k0 + 8 < K) {
            pa = *(const float4*)(Ap + k0 + 8);
            pb = *(const float4*)(Bp + k0 + 8);
        }
#pragma unroll
        for (int kk = 0; kk < 8; kk++) {
            float4 a0 = *(const float4*)&As[kk][ty * 4];
            float4 a1 = *(const float4*)&As[kk][64 + ty * 4];
            float4 b0 = *(const float4*)&Bs[kk][tx * 4];
            float4 b1 = *(const float4*)&Bs[kk][64 + tx * 4];
            float a[8] = {a0.x, a0.y, a0.z, a0.w, a1.x, a1.y, a1.z, a1.w};
            float b[8] = {b0.x, b0.y, b0.z, b0.w, b1.x, b1.y, b1.z, b1.w};
#pragma unroll
            for (int i = 0; i < 8; i++)
#pragma unroll
                for (int j = 0; j < 8; j++)
                    acc[i][j] += a[i] * b[j];
        }
    }

#pragma unroll
    for (int i = 0; i < 8; i++) {
        int r = bi * 128 + ((i < 4) ? ty * 4 + i : 64 + ty * 4 + (i - 4));
#pragma unroll
        for (int j = 0; j < 8; j++) {
            int cc = bj * 128 + ((j < 4) ? tx * 4 + j : 64 + tx * 4 + (j - 4));
            float* cp = Cbase + (size_t)r * ldc + cc;
            if (mode == 0) {
                float v = acc[i][j] * scale;
                *cp = fminf(fmaxf(v, -1.f), 1.f);
            } else {
                *cp -= acc[i][j];
            }
        }
    }
}

// ==========================================================================
__global__ void diag_kernel()
{
    int i = blockIdx.x * blockDim.x + threadIdx.x;
    if (i < N) g_diag[i] = g_S[(size_t)i * N + i];
}

__global__ void step_kernel(const float* __restrict__ alpha_p)
{
    int j = blockIdx.x * 32 + threadIdx.x;
    int i = blockIdx.y * 8 + threadIdx.y;
    if (i >= N || j > i) return;
    float a  = *alpha_p;
    float a2 = a * a;
    float cross = sqrtf(g_diag[i] * g_diag[j]);
    float s = g_S[(size_t)i * N + j];
    float m = fminf(fmaxf(s / cross, -1.f), 1.f);
    float q = 1.f - m * m;
    float sq, ac;
    if (q > 0.f) { sq = sqrtf(q); ac = acosf(m); }
    else         { sq = 0.f;      ac = (m > 0.f) ? 0.f : PI_F; }
    float f  = (sq + m * (PI_F - ac)) / PI_F;
    float ts = cross * f;
    float ov = (s + a2 * ts) / (1.f + a2);
    g_S[(size_t)i * N + j] = fminf(fmaxf(ov, -1.f), 1.f);
}

// ==========================================================================
// panel factorization + inversion of 128x128 diag block.
// potf2/inv32 register-resident (warp 0). TRSM / SYRK / blocked inversion
// use 4x4 register micro-tiles (8 LDS per 16 FMA instead of 2 per 1).
// W upper triangles are zero -> all k-loops run full 32 without predicates.
// ==========================================================================
__global__ __launch_bounds__(256, 1)
void potrf_invert(int kb)
{
    extern __shared__ float sh[];
    float* A = sh;                 // NB x NB stride LDA (L, lower)
    float* W = sh + NB * LDA;      // NB x NB stride LDA (inv(L), lower)
    __shared__ float Ts[3 * 1056]; // staging (TRSM: 96*32; inv: 3*32*33)
    int tid = threadIdx.x;         // 256
    int base = kb * NB;

    for (int idx = tid; idx < NB * NB; idx += 256) {
        int i = idx >> 7, j = idx & 127;
        A[i * LDA + j] = (j <= i) ? g_S[(size_t)(base + i) * N + base + j] : 0.f;
        W[i * LDA + j] = 0.f;
    }
    __syncthreads();

    for (int p = 0; p < 4; p++) {
        int off = p * 32;

        // ---- register-resident potf2 + inv32, warp 0 ----
        if (tid < 32) {
            const unsigned FULL = 0xffffffffu;
            int r = tid;
            float ar[32];
#pragma unroll
            for (int t = 0; t < 32; t++)
                ar[t] = (t <= r) ? A[(off + r) * LDA + off + t] : 0.f;
            float rs_reg = 0.f;
#pragma unroll
            for (int j = 0; j < 32; j++) {
                float d   = __shfl_sync(FULL, ar[j], j);
                float rsj = rsqrtf(d);
                float lj  = ar[j] * rsj;
                ar[j] = lj;
                if (r == j) rs_reg = rsj;
#pragma unroll
                for (int t = j + 1; t < 32; t++) {
                    float ltj = __shfl_sync(FULL, lj, t);
                    ar[t] -= lj * ltj;
                }
            }
            int c = r;
            float w[32];
#pragma unroll
            for (int t = 0; t < 32; t++) w[t] = 0.f;
#pragma unroll
            for (int i = 0; i < 32; i++) {
                float s = (i == c) ? 1.f : 0.f;
#pragma unroll
                for (int t = 0; t < i; t++) {
                    float lit = __shfl_sync(FULL, ar[t], i);
                    s -= lit * w[t];
                }
                float rsi = __shfl_sync(FULL, rs_reg, i);
                w[i] = (i >= c) ? s * rsi : 0.f;
            }
#pragma unroll
            for (int t = 0; t < 32; t++)
                if (t <= r) A[(off + r) * LDA + off + t] = ar[t];
#pragma unroll
            for (int i = 0; i < 32; i++)
                if (i >= c) W[(off + i) * LDA + off + c] = w[i];
        }
        __syncthreads();

        int nr = NB - off - 32;
        if (nr > 0) {
            // ---- TRSM: A21 <- A21 * inv(L11_32)^T, 4x4 micro-tiles ----
            // out(r,cc) = sum_k arow[k] * W[(off+cc)*LDA+off+k]  (W zero-padded)
            int ntr = (nr >> 2) * 8;
            for (int tId = tid; tId < ntr; tId += 256) {
                int tr = (tId >> 3) * 4;
                int tc = (tId & 7) * 4;
                float acc[4][4];
#pragma unroll
                for (int r = 0; r < 4; r++)
#pragma unroll
                    for (int cidx = 0; cidx < 4; cidx++) acc[r][cidx] = 0.f;
#pragma unroll 8
                for (int k = 0; k < 32; k++) {
                    float av[4], wv[4];
#pragma unroll
                    for (int r = 0; r < 4; r++)
                        av[r] = A[(off + 32 + tr + r) * LDA + off + k];
#pragma unroll
                    for (int cidx = 0; cidx < 4; cidx++)
                        wv[cidx] = W[(off + tc + cidx) * LDA + off + k];
#pragma unroll
                    for (int r = 0; r < 4; r++)
#pragma unroll
                        for (int cidx = 0; cidx < 4; cidx++)
                            acc[r][cidx] += av[r] * wv[cidx];
                }
#pragma unroll
                for (int r = 0; r < 4; r++)
#pragma unroll
                    for (int cidx = 0; cidx < 4; cidx++)
                        Ts[(tr + r) * 32 + tc + cidx] = acc[r][cidx];
            }
            __syncthreads();
            for (int idx = tid; idx < nr * 32; idx += 256) {
                int r = idx >> 5, cc = idx & 31;
                A[(off + 32 + r) * LDA + off + cc] = Ts[idx];
            }
            __syncthreads();

            // ---- SYRK trailing update, 4x4 micro-tiles (lower only) ----
            int nt = nr >> 2;
            int ntot = nt * (nt + 1) / 2;
            for (int tId = tid; tId < ntot; tId += 256) {
                int ti = (int)((sqrtf(8.f * (float)tId + 1.f) - 1.f) * 0.5f);
                while ((ti + 1) * (ti + 2) / 2 <= tId) ti++;
                while (ti * (ti + 1) / 2 > tId) ti--;
                int tj = tId - ti * (ti + 1) / 2;
                int i0 = off + 32 + ti * 4;
                int t0 = off + 32 + tj * 4;
                float acc[4][4];
#pragma unroll
                for (int r = 0; r < 4; r++)
#pragma unroll
                    for (int cidx = 0; cidx < 4; cidx++) acc[r][cidx] = 0.f;
#pragma unroll 8
                for (int k = 0; k < 32; k++) {
                    float av[4], bv[4];
#pragma unroll
                    for (int r = 0; r < 4; r++)
                        av[r] = A[(i0 + r) * LDA + off + k];
#pragma unroll
                    for (int cidx = 0; cidx < 4; cidx++)
                        bv[cidx] = A[(t0 + cidx) * LDA + off + k];
#pragma unroll
                    for (int r = 0; r < 4; r++)
#pragma unroll
                        for (int cidx = 0; cidx < 4; cidx++)
                            acc[r][cidx] += av[r] * bv[cidx];
                }
#pragma unroll
                for (int r = 0; r < 4; r++)
#pragma unroll
                    for (int cidx = 0; cidx < 4; cidx++) {
                        int ii = i0 + r, tt = t0 + cidx;
                        if (tt <= ii) A[ii * LDA + tt] -= acc[r][cidx];
                    }
            }
            __syncthreads();
        }
    }

    // ---- blocked inversion of off-diag 32x32 blocks of W, 4x4 tiles ----
    for (int ib = 1; ib < 4; ib++) {
        // step 1: T[j] = sum_{tb=j..ib-1} L[ib][tb] * W[tb][j]
        for (int tId = tid; tId < ib * 64; tId += 256) {
            int j = tId >> 6;
            int e = tId & 63;
            int r0 = (e >> 3) * 4, c0 = (e & 7) * 4;
            float acc[4][4];
#pragma unroll
            for (int r = 0; r < 4; r++)
#pragma unroll
                for (int cidx = 0; cidx < 4; cidx++) acc[r][cidx] = 0.f;
            for (int tb = j; tb < ib; tb++) {
#pragma unroll 8
                for (int k = 0; k < 32; k++) {
                    float lv[4], wv[4];
#pragma unroll
                    for (int r = 0; r < 4; r++)
                        lv[r] = A[(32 * ib + r0 + r) * LDA + 32 * tb + k];
#pragma unroll
                    for (int cidx = 0; cidx < 4; cidx++)
                        wv[cidx] = W[(32 * tb + k) * LDA + 32 * j + c0 + cidx];
#pragma unroll
                    for (int r = 0; r < 4; r++)
#pragma unroll
                        for (int cidx = 0; cidx < 4; cidx++)
                            acc[r][cidx] += lv[r] * wv[cidx];
                }
            }
#pragma unroll
            for (int r = 0; r < 4; r++)
#pragma unroll
                for (int cidx = 0; cidx < 4; cidx++)
                    Ts[j * 1056 + (r0 + r) * 33 + c0 + cidx] = acc[r][cidx];
        }
        __syncthreads();
        // step 2: W[ib][j] = -inv(L_ii) * T[j]  (inv upper is zero-padded)
        for (int tId = tid; tId < ib * 64; tId += 256) {
            int j = tId >> 6;
            int e = tId & 63;
            int r0 = (e >> 3) * 4, c0 = (e & 7) * 4;
            float acc[4][4];
#pragma unroll
            for (int r = 0; r < 4; r++)
#pragma unroll
                for (int cidx = 0; cidx < 4; cidx++) acc[r][cidx] = 0.f;
#pragma unroll 8
            for (int k = 0; k < 32; k++) {
                float wv[4], tv[4];
#pragma unroll
                for (int r = 0; r < 4; r++)
                    wv[r] = W[(32 * ib + r0 + r) * LDA + 32 * ib + k];
#pragma unroll
                for (int cidx = 0; cidx < 4; cidx++)
                    tv[cidx] = Ts[j * 1056 + k * 33 + c0 + cidx];
#pragma unroll
                for (int r = 0; r < 4; r++)
#pragma unroll
                    for (int cidx = 0; cidx < 4; cidx++)
                        acc[r][cidx] += wv[r] * tv[cidx];
            }
#pragma unroll
            for (int r = 0; r < 4; r++)
#pragma unroll
                for (int cidx = 0; cidx < 4; cidx++)
                    W[(32 * ib + r0 + r) * LDA + 32 * j + c0 + cidx] =
                        -acc[r][cidx];
        }
        __syncthreads();
    }

    for (int idx = tid; idx < NB * NB; idx += 256) {
        int i = idx >> 7, j = idx & 127;
        if (j <= i) g_S[(size_t)(base + i) * N + base + j] = A[i * LDA + j];
        g_invD[(size_t)kb * NB * NB + idx] = W[i * LDA + j];
    }
}

// ==========================================================================
// NT GEMM for TRSM panels: C = A * B^T (64x64 tiles)
// ==========================================================================
__global__ __launch_bounds__(256, 2)
void gemm_nt(const float* __restrict__ A, int lda,
             const float* __restrict__ B, int ldb,
             float* __restrict__ C, int ldc, int K)
{
    __shared__ float As[16][64];
    __shared__ float Bs[16][64];
    int bi = blockIdx.y, bj = blockIdx.x;
    int tid = threadIdx.x;
    int tx = tid & 15, ty = tid >> 4;

    const float* Ab = A + (size_t)(bi * 64) * lda;
    const float* Bb = B + (size_t)(bj * 64) * ldb;

    int arow = tid >> 2, akk = (tid & 3) << 2;

    float acc[4][4];
#pragma unroll
    for (int i = 0; i < 4; i++)
#pragma unroll
        for (int j = 0; j < 4; j++) acc[i][j] = 0.f;

    for (int k0 = 0; k0 < K; k0 += 16) {
        float4 va = *(const float4*)(Ab + (size_t)arow * lda + k0 + akk);
        float4 vb = *(const float4*)(Bb + (size_t)arow * ldb + k0 + akk);
        As[akk + 0][arow] = va.x; As[akk + 1][arow] = va.y;
        As[akk + 2][arow] = va.z; As[akk + 3][arow] = va.w;
        Bs[akk + 0][arow] = vb.x; Bs[akk + 1][arow] = vb.y;
        Bs[akk + 2][arow] = vb.z; Bs[akk + 3][arow] = vb.w;
        __syncthreads();
#pragma unroll
        for (int kk = 0; kk < 16; kk++) {
            float4 a = *(const float4*)&As[kk][ty * 4];
            float4 b = *(const float4*)&Bs[kk][tx * 4];
            float av[4] = {a.x, a.y, a.z, a.w};
            float bv[4] = {b.x, b.y, b.z, b.w};
#pragma unroll
            for (int i = 0; i < 4; i++)
#pragma unroll
                for (int j = 0; j < 4; j++)
                    acc[i][j] += av[i] * bv[j];
        }
        __syncthreads();
    }

#pragma unroll
    for (int i = 0; i < 4; i++)
#pragma unroll
        for (int j = 0; j < 4; j++)
            C[(size_t)(bi * 64 + ty * 4 + i) * ldc + bj * 64 + tx * 4 + j] =
                acc[i][j];
}

__global__ void copy_panel(int kb)
{
    int r = blockIdx.x;
    int j = threadIdx.x;  // 128
    g_S[(size_t)((kb + 1) * NB + r) * N + kb * NB + j] = g_P[(size_t)r * NB + j];
}

// ==========================================================================
// batched NN GEMM, 128x128 tiles / 8x8 micro-tiles (for D&C inversion)
// ==========================================================================
__global__ __launch_bounds__(256, 1)
void gemm_nn_b128(const float* __restrict__ A, size_t strA, int lda,
                  const float* __restrict__ B, size_t strB, int ldb,
                  float* __restrict__ C, size_t strC, int ldc,
                  int K, float alpha)
{
    A += (size_t)blockIdx.z * strA;
    B += (size_t)blockIdx.z * strB;
    C += (size_t)blockIdx.z * strC;

    __shared__ float As[8][128];
    __shared__ float Bs[8][128];

    int bi = blockIdx.y, bj = blockIdx.x;
    int tid = threadIdx.x;
    int tx = tid & 15, ty = tid >> 4;

    int lrow = tid >> 1;
    int lkk  = (tid & 1) * 4;
    int brow = tid >> 5;
    int bcol = (tid & 31) * 4;

    const float* Ap = A + (size_t)(bi * 128 + lrow) * lda + lkk;
    const float* Bp = B + bj * 128 + bcol;

    float acc[8][8];
#pragma unroll
    for (int i = 0; i < 8; i++)
#pragma unroll
        for (int j = 0; j < 8; j++) acc[i][j] = 0.f;

    for (int k0 = 0; k0 < K; k0 += 8) {
        float4 va = *(const float4*)(Ap + k0);
        float4 vb = *(const float4*)(Bp + (size_t)(k0 + brow) * ldb);
        if (k0) __syncthreads();
        As[lkk + 0][lrow] = va.x; As[lkk + 1][lrow] = va.y;
        As[lkk + 2][lrow] = va.z; As[lkk + 3][lrow] = va.w;
        *(float4*)&Bs[brow][bcol] = vb;
        __syncthreads();
#pragma unroll
        for (int kk = 0; kk < 8; kk++) {
            float4 a0 = *(const float4*)&As[kk][ty * 4];
            float4 a1 = *(const float4*)&As[kk][64 + ty * 4];
            float4 b0 = *(const float4*)&Bs[kk][tx * 4];
            float4 b1 = *(const float4*)&Bs[kk][64 + tx * 4];
            float a[8] = {a0.x, a0.y, a0.z, a0.w, a1.x, a1.y, a1.z, a1.w};
            float b[8] = {b0.x, b0.y, b0.z, b0.w, b1.x, b1.y, b1.z, b1.w};
#pragma unroll
            for (int i = 0; i < 8; i++)
#pragma unroll
                for (int j = 0; j < 8; j++)
                    acc[i][j] += a[i] * b[j];
        }
    }

#pragma unroll
    for (int i = 0; i < 8; i++) {
        int r = bi * 128 + ((i < 4) ? ty * 4 + i : 64 + ty * 4 + (i - 4));
#pragma unroll
        for (int j = 0; j < 8; j++) {
            int cc = bj * 128 + ((j < 4) ? tx * 4 + j : 64 + tx * 4 + (j - 4));
            C[(size_t)r * ldc + cc] = alpha * acc[i][j];
        }
    }
}

// ==========================================================================
__global__ void zero_kernel(float* p, int n)
{
    for (int i = blockIdx.x * blockDim.x + threadIdx.x; i < n;
         i += gridDim.x * blockDim.x)
        p[i] = 0.f;
}

__global__ void copy_diag_kernel()
{
    int kb = blockIdx.y;
    int idx = blockIdx.x * 256 + threadIdx.x;
    int i = idx >> 7, j = idx & 127;
    g_W[(size_t)(kb * NB + i) * N + kb * NB + j] =
        g_invD[(size_t)kb * NB * NB + idx];
}

__global__ void fnorm_kernel()
{
    __shared__ float red[256];
    float s = 0.f;
    size_t total = (size_t)N * N;
    for (size_t i = blockIdx.x * blockDim.x + threadIdx.x; i < total;
         i += (size_t)gridDim.x * blockDim.x) {
        float v = g_W[i];
        s += v * v;
    }
    red[threadIdx.x] = s; __syncthreads();
    for (int o = 128; o > 0; o >>= 1) {
        if (threadIdx.x < o) red[threadIdx.x] += red[threadIdx.x + o];
        __syncthreads();
    }
    if (threadIdx.x == 0) atomicAdd(&g_scal[0], red[0]);
}

__global__ void proj_kernel(const float* __restrict__ c)
{
    __shared__ float red[256];
    int r = blockIdx.x;
    const float* row = g_W + (size_t)r * N;
    float s = 0.f;
    for (int j = threadIdx.x; j < N; j += 256) s += row[j] * c[j];
    red[threadIdx.x] = s; __syncthreads();
    for (int o = 128; o > 0; o >>= 1) {
        if (threadIdx.x < o) red[threadIdx.x] += red[threadIdx.x + o];
        __syncthreads();
    }
    if (threadIdx.x == 0) {
        float y = red[0];
        atomicAdd(&g_scal[1], y * y);
    }
}

__global__ void final_kernel(float* out)
{
    __shared__ float red[256];
    float s = 0.f;
    for (int i = threadIdx.x; i < N; i += 256)
        s += logf(g_S[(size_t)i * N + i]);
    red[threadIdx.x] = s; __syncthreads();
    for (int o = 128; o > 0; o >>= 1) {
        if (threadIdx.x < o) red[threadIdx.x] += red[threadIdx.x + o];
        __syncthreads();
    }
    if (threadIdx.x == 0) {
        float nrd = expf(red[0] * (2.0f / (float)N));
        out[0] = (float)N / 5.0f +
                 nrd * ((0.5f - 1.0f / PI_F) * g_scal[0] + g_scal[1] / PI_F);
    }
}

// ==========================================================================
// host orchestration
// ==========================================================================
extern "C" void kernel_launch(void* const* d_in, const int* in_sizes, int n_in,
                              void* d_out, int out_size)
{
    (void)in_sizes; (void)n_in; (void)out_size;
    const float* x     = (const float*)d_in[0];
    const float* c     = (const float*)d_in[1];
    const float* alpha = (const float*)d_in[2];
    float* out = (float*)d_out;

    float *Sp, *Wp, *iDp, *T2p, *Pp, *scalp;
    cudaGetSymbolAddress((void**)&Sp,    g_S);
    cudaGetSymbolAddress((void**)&Wp,    g_W);
    cudaGetSymbolAddress((void**)&iDp,   g_invD);
    cudaGetSymbolAddress((void**)&T2p,   g_T2);
    cudaGetSymbolAddress((void**)&Pp,    g_P);
    cudaGetSymbolAddress((void**)&scalp, g_scal);

    int potrf_smem = 2 * NB * LDA * (int)sizeof(float);
    cudaFuncSetAttribute(potrf_invert,
                         cudaFuncAttributeMaxDynamicSharedMemorySize,
                         potrf_smem);
    cudaFuncSetAttribute(gram_mma_kernel,
                         cudaFuncAttributeMaxDynamicSharedMemorySize,
                         GRAM_SMEM);

    // 1. gram via mma.sync bf16 split GEMM
    split_kernel<<<4096, 256>>>(x);
    gram_mma_kernel<<<NBLK * (NBLK + 1) / 2, 256, GRAM_SMEM>>>(Sp);

    // 2. arc-cosine kernel step
    diag_kernel<<<N / 256, 256>>>();
    step_kernel<<<dim3(N / 32, N / 8), dim3(32, 8)>>>(alpha);

    // 3. blocked Cholesky (in place, lower)
    for (int k = 0; k < NBLK; k++) {
        potrf_invert<<<1, 256, potrf_smem>>>(k);
        if (k < NBLK - 1) {
            int rows = (NBLK - 1 - k) * NB;
            gemm_nt<<<dim3(2, rows / 64), 256>>>(
                Sp + (size_t)(k + 1) * NB * N + (size_t)k * NB, N,
                iDp + (size_t)k * NB * NB, NB,
                Pp, NB, NB);
            copy_panel<<<rows, NB>>>(k);
            int T2 = NBLK - 1 - k;
            nt_tile_kernel<<<T2 * (T2 + 1) / 2, 256>>>(
                Pp, NB,
                Sp + (size_t)(k + 1) * NB * N + (size_t)(k + 1) * NB, N,
                NB, 1.0f, 1);
        }
    }

    // 4. divide & conquer triangular inversion: W = L^{-1}
    zero_kernel<<<4096, 256>>>(Wp, N * N);
    copy_diag_kernel<<<dim3(64, NBLK), 256>>>();
    for (int lev = 0; lev < 4; lev++) {
        int s = 128 << lev;
        int pairs = N / (2 * s);
        size_t strW = (size_t)2 * s * (N + 1);
        gemm_nn_b128<<<dim3(s / 128, s / 128, pairs), 256>>>(
            Wp + (size_t)s * N + s, strW, N,
            Sp + (size_t)s * N,     strW, N,
            T2p, (size_t)s * s, s,
            s, 1.0f);
        gemm_nn_b128<<<dim3(s / 128, s / 128, pairs), 256>>>(
            T2p, (size_t)s * s, s,
            Wp, strW, N,
            Wp + (size_t)s * N, strW, N,
            s, -1.0f);
    }

    // 5. reductions + final scalar
    zero_kernel<<<1, 32>>>(scalp, 4);
    fnorm_kernel<<<1024, 256>>>();
    proj_kernel<<<N, 256>>>(c);
    final_kernel<<<1, 256>>>(out);
}

// round 8
// speedup vs baseline: 3.7381x; 1.0476x over previous
#include <cuda_runtime.h>
#include <cuda_bf16.h>
#include <math.h>
#include <stdint.h>

#define N 2048
#define D 16384
#define NB 128
#define LDA 129            // padded smem stride (bank-conflict-free columns)
#define NBLK 16            // N / NB
#define PI_F 3.14159265358979323846f

// ---------------- device scratch (no allocations allowed) ----------------
__device__ float g_S[(size_t)N * N];        // gram / sigma / L (lower, in place)
__device__ float g_W[(size_t)N * N];        // L^{-1} (lower)
__device__ float g_invD[NBLK * NB * NB];    // per-panel inv(L11)
__device__ float g_T2[(size_t)1024 * 1024]; // D&C inversion scratch
__device__ float g_diag[N];                 // diag snapshot
__device__ float g_scal[4];                 // [0]=trace acc, [1]=proj acc
__device__ __nv_bfloat16 g_hi[(size_t)N * D];
__device__ __nv_bfloat16 g_lo[(size_t)N * D];
__device__ __nv_bfloat16 g_Phi[(size_t)N * NB];  // TRSM panel, bf16 hi
__device__ __nv_bfloat16 g_Plo[(size_t)N * NB];  // TRSM panel, bf16 lo

// ==========================================================================
__device__ __forceinline__ uint32_t smem_u32(const void* p) {
    uint32_t a;
    asm("{ .reg .u64 t; cvta.to.shared.u64 t, %1; cvt.u32.u64 %0, t; }"
        : "=r"(a) : "l"(p));
    return a;
}

// ==========================================================================
// split conversion: x -> hi (bf16) + lo (bf16 of residual)
// ==========================================================================
__global__ void split_kernel(const float* __restrict__ x)
{
    size_t total = (size_t)N * D;
    for (size_t i = blockIdx.x * (size_t)blockDim.x + threadIdx.x; i < total;
         i += (size_t)gridDim.x * blockDim.x) {
        float v = x[i];
        __nv_bfloat16 h = __float2bfloat16(v);
        g_hi[i] = h;
        g_lo[i] = __float2bfloat16(v - __bfloat162float(h));
    }
}

// ==========================================================================
// unified bf16-split NT mma kernel over lower tile pairs:
//   acc = Ahi*Bhi^T + Ahi*Blo^T + Alo*Bhi^T   (fp32 accum)
// mode 0:  C = clip(acc*scale, -1, 1)       (gram)
// mode 1:  C -= acc                          (SYRK trailing update)
// ==========================================================================
#define BKG 32
#define GTILE_B (128 * 40 * 2)
#define GRAM_SMEM (2 * 4 * GTILE_B)

__device__ __forceinline__ void ldsm_x4(uint32_t* r, uint32_t addr) {
    asm volatile("ldmatrix.sync.aligned.m8n8.x4.shared.b16 {%0,%1,%2,%3}, [%4];"
                 : "=r"(r[0]), "=r"(r[1]), "=r"(r[2]), "=r"(r[3]) : "r"(addr));
}
__device__ __forceinline__ void ldsm_x2(uint32_t* r, uint32_t addr) {
    asm volatile("ldmatrix.sync.aligned.m8n8.x2.shared.b16 {%0,%1}, [%2];"
                 : "=r"(r[0]), "=r"(r[1]) : "r"(addr));
}
__device__ __forceinline__ void mma_bf16(float* d, const uint32_t* a,
                                         const uint32_t* b) {
    asm volatile(
        "mma.sync.aligned.m16n8k16.row.col.f32.bf16.bf16.f32 "
        "{%0,%1,%2,%3}, {%4,%5,%6,%7}, {%8,%9}, {%0,%1,%2,%3};"
        : "+f"(d[0]), "+f"(d[1]), "+f"(d[2]), "+f"(d[3])
        : "r"(a[0]), "r"(a[1]), "r"(a[2]), "r"(a[3]), "r"(b[0]), "r"(b[1]));
}
#define CP_ASYNC(dst, src) \
    asm volatile("cp.async.cg.shared.global [%0], [%1], 16;" \
                 :: "r"(dst), "l"(src))
#define CP_COMMIT() asm volatile("cp.async.commit_group;" ::: "memory")

__global__ __launch_bounds__(256, 1)
void mma_nt_kernel(const __nv_bfloat16* __restrict__ Ahi,
                   const __nv_bfloat16* __restrict__ Alo,
                   const __nv_bfloat16* __restrict__ Bhi,
                   const __nv_bfloat16* __restrict__ Blo,
                   size_t lda, float* __restrict__ Cbase, int ldc,
                   int K, float scale, int mode)
{
    extern __shared__ char dsm[];
    uint32_t sbase = smem_u32(dsm);

    int tid  = threadIdx.x;
    int wid  = tid >> 5;
    int lane = tid & 31;

    int t = blockIdx.x;
    int bi = (int)((sqrtf(8.f * (float)t + 1.f) - 1.f) * 0.5f);
    while ((bi + 1) * (bi + 2) / 2 <= t) bi++;
    while (bi * (bi + 1) / 2 > t) bi--;
    int bj = t - bi * (bi + 1) / 2;

    const __nv_bfloat16* srcs[4] = {
        Ahi + (size_t)bi * 128 * lda,
        Alo + (size_t)bi * 128 * lda,
        Bhi + (size_t)bj * 128 * lda,
        Blo + (size_t)bj * 128 * lda
    };

    int m0w = (wid & 1) * 64;
    int n0w = (wid >> 1) * 32;

    float acc[4][4][4];
#pragma unroll
    for (int im = 0; im < 4; im++)
#pragma unroll
        for (int jn = 0; jn < 4; jn++)
#pragma unroll
            for (int e = 0; e < 4; e++) acc[im][jn][e] = 0.f;

    const int S = K / BKG;

    {
#pragma unroll
        for (int it = 0; it < 8; it++) {
            int idx = tid + it * 256;
            int tile = idx >> 9;
            int rem = idx & 511;
            int r = rem >> 2, ch = rem & 3;
            uint32_t dst = sbase + (uint32_t)tile * GTILE_B + r * 80 + ch * 16;
            CP_ASYNC(dst, srcs[tile] + (size_t)r * lda + ch * 8);
        }
        CP_COMMIT();
    }

#pragma unroll 1
    for (int s = 0; s < S; s++) {
        if (s + 1 < S) {
            int k0 = (s + 1) * BKG;
            uint32_t boff = (uint32_t)((s + 1) & 1) * (4 * GTILE_B);
#pragma unroll
            for (int it = 0; it < 8; it++) {
                int idx = tid + it * 256;
                int tile = idx >> 9;
                int rem = idx & 511;
                int r = rem >> 2, ch = rem & 3;
                uint32_t dst = sbase + boff + (uint32_t)tile * GTILE_B +
                               r * 80 + ch * 16;
                CP_ASYNC(dst, srcs[tile] + (size_t)r * lda + k0 + ch * 8);
            }
            CP_COMMIT();
            asm volatile("cp.async.wait_group 1;" ::: "memory");
        } else {
            asm volatile("cp.async.wait_group 0;" ::: "memory");
        }
        __syncthreads();

        uint32_t buf = sbase + (uint32_t)(s & 1) * (4 * GTILE_B);
        uint32_t Ahi_b = buf;
        uint32_t Alo_b = buf + GTILE_B;
        uint32_t Bhi_b = buf + 2 * GTILE_B;
        uint32_t Blo_b = buf + 3 * GTILE_B;

#pragma unroll
        for (int ks = 0; ks < 2; ks++) {
            int kof = ks * 16;
            int arow = lane & 15;
            int acol = kof + 8 * (lane >> 4);
            uint32_t ah[4][4], al[4][4];
#pragma unroll
            for (int im = 0; im < 4; im++) {
                uint32_t ro = (uint32_t)(m0w + im * 16 + arow) * 80 + acol * 2;
                ldsm_x4(ah[im], Ahi_b + ro);
                ldsm_x4(al[im], Alo_b + ro);
            }
            int brow = lane & 7;
            int bcol = kof + 8 * ((lane >> 3) & 1);
            uint32_t bh[4][2], bl[4][2];
#pragma unroll
            for (int jn = 0; jn < 4; jn++) {
                uint32_t ro = (uint32_t)(n0w + jn * 8 + brow) * 80 + bcol * 2;
                ldsm_x2(bh[jn], Bhi_b + ro);
                ldsm_x2(bl[jn], Blo_b + ro);
            }
#pragma unroll
            for (int im = 0; im < 4; im++)
#pragma unroll
                for (int jn = 0; jn < 4; jn++) {
                    mma_bf16(acc[im][jn], ah[im], bh[jn]);
                    mma_bf16(acc[im][jn], ah[im], bl[jn]);
                    mma_bf16(acc[im][jn], al[im], bh[jn]);
                }
        }
        __syncthreads();
    }

#pragma unroll
    for (int im = 0; im < 4; im++) {
        int row = bi * 128 + m0w + im * 16 + (lane >> 2);
#pragma unroll
        for (int jn = 0; jn < 4; jn++) {
            int col = bj * 128 + n0w + jn * 8 + (lane & 3) * 2;
            float* p0 = Cbase + (size_t)row * ldc + col;
            float* p1 = Cbase + (size_t)(row + 8) * ldc + col;
            if (mode == 0) {
                p0[0] = fminf(fmaxf(acc[im][jn][0] * scale, -1.f), 1.f);
                p0[1] = fminf(fmaxf(acc[im][jn][1] * scale, -1.f), 1.f);
                p1[0] = fminf(fmaxf(acc[im][jn][2] * scale, -1.f), 1.f);
                p1[1] = fminf(fmaxf(acc[im][jn][3] * scale, -1.f), 1.f);
            } else {
                p0[0] -= acc[im][jn][0];
                p0[1] -= acc[im][jn][1];
                p1[0] -= acc[im][jn][2];
                p1[1] -= acc[im][jn][3];
            }
        }
    }
}

// ==========================================================================
__global__ void diag_kernel()
{
    int i = blockIdx.x * blockDim.x + threadIdx.x;
    if (i < N) g_diag[i] = g_S[(size_t)i * N + i];
}

__global__ void step_kernel(const float* __restrict__ alpha_p)
{
    int j = blockIdx.x * 32 + threadIdx.x;
    int i = blockIdx.y * 8 + threadIdx.y;
    if (i >= N || j > i) return;
    float a  = *alpha_p;
    float a2 = a * a;
    float cross = sqrtf(g_diag[i] * g_diag[j]);
    float s = g_S[(size_t)i * N + j];
    float m = fminf(fmaxf(s / cross, -1.f), 1.f);
    float q = 1.f - m * m;
    float sq, ac;
    if (q > 0.f) { sq = sqrtf(q); ac = acosf(m); }
    else         { sq = 0.f;      ac = (m > 0.f) ? 0.f : PI_F; }
    float f  = (sq + m * (PI_F - ac)) / PI_F;
    float ts = cross * f;
    float ov = (s + a2 * ts) / (1.f + a2);
    g_S[(size_t)i * N + j] = fminf(fmaxf(ov, -1.f), 1.f);
}

// ==========================================================================
// panel factorization + inversion of 128x128 diag block.
// Register-resident potf2/inv32; 4x4 micro-tiled TRSM/SYRK/blocked-inv.
// No W zero-init (potf2 lanes write full columns; writeback masks
// block-upper). No A upper zeroing (never read). float4 global loads.
// ==========================================================================
__global__ __launch_bounds__(256, 1)
void potrf_invert(int kb)
{
    extern __shared__ float sh[];
    float* A = sh;                 // NB x NB stride LDA (L, lower)
    float* W = sh + NB * LDA;      // NB x NB stride LDA (inv(L), lower)
    __shared__ float Ts[3 * 1056];
    int tid = threadIdx.x;
    int base = kb * NB;

    // vectorized load (full rows; upper garbage never read)
    for (int idx = tid; idx < NB * 32; idx += 256) {
        int i = idx >> 5, j4 = (idx & 31) << 2;
        float4 v = *(const float4*)&g_S[(size_t)(base + i) * N + base + j4];
        A[i * LDA + j4 + 0] = v.x;
        A[i * LDA + j4 + 1] = v.y;
        A[i * LDA + j4 + 2] = v.z;
        A[i * LDA + j4 + 3] = v.w;
    }
    __syncthreads();

    for (int p = 0; p < 4; p++) {
        int off = p * 32;

        // ---- register-resident potf2 + inv32, warp 0 ----
        if (tid < 32) {
            const unsigned FULL = 0xffffffffu;
            int r = tid;
            float ar[32];
#pragma unroll
            for (int t = 0; t < 32; t++)
                ar[t] = (t <= r) ? A[(off + r) * LDA + off + t] : 0.f;
            float rs_reg = 0.f;
#pragma unroll
            for (int j = 0; j < 32; j++) {
                float d   = __shfl_sync(FULL, ar[j], j);
                float rsj = rsqrtf(d);
                float lj  = ar[j] * rsj;
                ar[j] = lj;
                if (r == j) rs_reg = rsj;
#pragma unroll
                for (int t = j + 1; t < 32; t++) {
                    float ltj = __shfl_sync(FULL, lj, t);
                    ar[t] -= lj * ltj;
                }
            }
            int c = r;
            float w[32];
#pragma unroll
            for (int t = 0; t < 32; t++) w[t] = 0.f;
#pragma unroll
            for (int i = 0; i < 32; i++) {
                float s = (i == c) ? 1.f : 0.f;
#pragma unroll
                for (int t = 0; t < i; t++) {
                    float lit = __shfl_sync(FULL, ar[t], i);
                    s -= lit * w[t];
                }
                float rsi = __shfl_sync(FULL, rs_reg, i);
                w[i] = (i >= c) ? s * rsi : 0.f;
            }
#pragma unroll
            for (int t = 0; t < 32; t++)
                if (t <= r) A[(off + r) * LDA + off + t] = ar[t];
            // write FULL column (zeros above diag) -> W diag blocks padded
#pragma unroll
            for (int i = 0; i < 32; i++)
                W[(off + i) * LDA + off + c] = w[i];
        }
        __syncthreads();

        int nr = NB - off - 32;
        if (nr > 0) {
            // ---- TRSM: A21 <- A21 * inv(L11_32)^T, 4x4 micro-tiles ----
            int ntr = (nr >> 2) * 8;
            for (int tId = tid; tId < ntr; tId += 256) {
                int tr = (tId >> 3) * 4;
                int tc = (tId & 7) * 4;
                float acc[4][4];
#pragma unroll
                for (int r = 0; r < 4; r++)
#pragma unroll
                    for (int cidx = 0; cidx < 4; cidx++) acc[r][cidx] = 0.f;
#pragma unroll 8
                for (int k = 0; k < 32; k++) {
                    float av[4], wv[4];
#pragma unroll
                    for (int r = 0; r < 4; r++)
                        av[r] = A[(off + 32 + tr + r) * LDA + off + k];
#pragma unroll
                    for (int cidx = 0; cidx < 4; cidx++)
                        wv[cidx] = W[(off + tc + cidx) * LDA + off + k];
#pragma unroll
                    for (int r = 0; r < 4; r++)
#pragma unroll
                        for (int cidx = 0; cidx < 4; cidx++)
                            acc[r][cidx] += av[r] * wv[cidx];
                }
#pragma unroll
                for (int r = 0; r < 4; r++)
#pragma unroll
                    for (int cidx = 0; cidx < 4; cidx++)
                        Ts[(tr + r) * 32 + tc + cidx] = acc[r][cidx];
            }
            __syncthreads();
            for (int idx = tid; idx < nr * 32; idx += 256) {
                int r = idx >> 5, cc = idx & 31;
                A[(off + 32 + r) * LDA + off + cc] = Ts[idx];
            }
            __syncthreads();

            // ---- SYRK trailing update, 4x4 micro-tiles (lower only) ----
            int nt = nr >> 2;
            int ntot = nt * (nt + 1) / 2;
            for (int tId = tid; tId < ntot; tId += 256) {
                int ti = (int)((sqrtf(8.f * (float)tId + 1.f) - 1.f) * 0.5f);
                while ((ti + 1) * (ti + 2) / 2 <= tId) ti++;
                while (ti * (ti + 1) / 2 > tId) ti--;
                int tj = tId - ti * (ti + 1) / 2;
                int i0 = off + 32 + ti * 4;
                int t0 = off + 32 + tj * 4;
                float acc[4][4];
#pragma unroll
                for (int r = 0; r < 4; r++)
#pragma unroll
                    for (int cidx = 0; cidx < 4; cidx++) acc[r][cidx] = 0.f;
#pragma unroll 8
                for (int k = 0; k < 32; k++) {
                    float av[4], bv[4];
#pragma unroll
                    for (int r = 0; r < 4; r++)
                        av[r] = A[(i0 + r) * LDA + off + k];
#pragma unroll
                    for (int cidx = 0; cidx < 4; cidx++)
                        bv[cidx] = A[(t0 + cidx) * LDA + off + k];
#pragma unroll
                    for (int r = 0; r < 4; r++)
#pragma unroll
                        for (int cidx = 0; cidx < 4; cidx++)
                            acc[r][cidx] += av[r] * bv[cidx];
                }
#pragma unroll
                for (int r = 0; r < 4; r++)
#pragma unroll
                    for (int cidx = 0; cidx < 4; cidx++) {
                        int ii = i0 + r, tt = t0 + cidx;
                        if (tt <= ii) A[ii * LDA + tt] -= acc[r][cidx];
                    }
            }
            __syncthreads();
        }
    }

    // ---- blocked inversion of off-diag 32x32 blocks of W, 4x4 tiles ----
    for (int ib = 1; ib < 4; ib++) {
        for (int tId = tid; tId < ib * 64; tId += 256) {
            int j = tId >> 6;
            int e = tId & 63;
            int r0 = (e >> 3) * 4, c0 = (e & 7) * 4;
            float acc[4][4];
#pragma unroll
            for (int r = 0; r < 4; r++)
#pragma unroll
                for (int cidx = 0; cidx < 4; cidx++) acc[r][cidx] = 0.f;
            for (int tb = j; tb < ib; tb++) {
#pragma unroll 8
                for (int k = 0; k < 32; k++) {
                    float lv[4], wv[4];
#pragma unroll
                    for (int r = 0; r < 4; r++)
                        lv[r] = A[(32 * ib + r0 + r) * LDA + 32 * tb + k];
#pragma unroll
                    for (int cidx = 0; cidx < 4; cidx++)
                        wv[cidx] = W[(32 * tb + k) * LDA + 32 * j + c0 + cidx];
#pragma unroll
                    for (int r = 0; r < 4; r++)
#pragma unroll
                        for (int cidx = 0; cidx < 4; cidx++)
                            acc[r][cidx] += lv[r] * wv[cidx];
                }
            }
#pragma unroll
            for (int r = 0; r < 4; r++)
#pragma unroll
                for (int cidx = 0; cidx < 4; cidx++)
                    Ts[j * 1056 + (r0 + r) * 33 + c0 + cidx] = acc[r][cidx];
        }
        __syncthreads();
        for (int tId = tid; tId < ib * 64; tId += 256) {
            int j = tId >> 6;
            int e = tId & 63;
            int r0 = (e >> 3) * 4, c0 = (e & 7) * 4;
            float acc[4][4];
#pragma unroll
            for (int r = 0; r < 4; r++)
#pragma unroll
                for (int cidx = 0; cidx < 4; cidx++) acc[r][cidx] = 0.f;
#pragma unroll 8
            for (int k = 0; k < 32; k++) {
                float wv[4], tv[4];
#pragma unroll
                for (int r = 0; r < 4; r++)
                    wv[r] = W[(32 * ib + r0 + r) * LDA + 32 * ib + k];
#pragma unroll
                for (int cidx = 0; cidx < 4; cidx++)
                    tv[cidx] = Ts[j * 1056 + k * 33 + c0 + cidx];
#pragma unroll
                for (int r = 0; r < 4; r++)
#pragma unroll
                    for (int cidx = 0; cidx < 4; cidx++)
                        acc[r][cidx] += wv[r] * tv[cidx];
            }
#pragma unroll
            for (int r = 0; r < 4; r++)
#pragma unroll
                for (int cidx = 0; cidx < 4; cidx++)
                    W[(32 * ib + r0 + r) * LDA + 32 * j + c0 + cidx] =
                        -acc[r][cidx];
        }
        __syncthreads();
    }

    for (int idx = tid; idx < NB * NB; idx += 256) {
        int i = idx >> 7, j = idx & 127;
        if (j <= i) g_S[(size_t)(base + i) * N + base + j] = A[i * LDA + j];
        // block-upper of W never written -> mask to zero
        g_invD[(size_t)kb * NB * NB + idx] =
            ((j >> 5) <= (i >> 5)) ? W[i * LDA + j] : 0.f;
    }
}

// ==========================================================================
// TRSM panel GEMM: C = A * B^T (64x64 tiles); epilogue writes fp32 into S
// (as L) AND bf16 hi/lo split into the panel buffers for the mma SYRK.
// ==========================================================================
__global__ __launch_bounds__(256, 2)
void gemm_nt_split(const float* __restrict__ A, int lda,
                   const float* __restrict__ B, int ldb,
                   float* __restrict__ Cs, int ldcs,
                   __nv_bfloat16* __restrict__ Phi,
                   __nv_bfloat16* __restrict__ Plo, int K)
{
    __shared__ float As[16][64];
    __shared__ float Bs[16][64];
    int bi = blockIdx.y, bj = blockIdx.x;
    int tid = threadIdx.x;
    int tx = tid & 15, ty = tid >> 4;

    const float* Ab = A + (size_t)(bi * 64) * lda;
    const float* Bb = B + (size_t)(bj * 64) * ldb;

    int arow = tid >> 2, akk = (tid & 3) << 2;

    float acc[4][4];
#pragma unroll
    for (int i = 0; i < 4; i++)
#pragma unroll
        for (int j = 0; j < 4; j++) acc[i][j] = 0.f;

    for (int k0 = 0; k0 < K; k0 += 16) {
        float4 va = *(const float4*)(Ab + (size_t)arow * lda + k0 + akk);
        float4 vb = *(const float4*)(Bb + (size_t)arow * ldb + k0 + akk);
        As[akk + 0][arow] = va.x; As[akk + 1][arow] = va.y;
        As[akk + 2][arow] = va.z; As[akk + 3][arow] = va.w;
        Bs[akk + 0][arow] = vb.x; Bs[akk + 1][arow] = vb.y;
        Bs[akk + 2][arow] = vb.z; Bs[akk + 3][arow] = vb.w;
        __syncthreads();
#pragma unroll
        for (int kk = 0; kk < 16; kk++) {
            float4 a = *(const float4*)&As[kk][ty * 4];
            float4 b = *(const float4*)&Bs[kk][tx * 4];
            float av[4] = {a.x, a.y, a.z, a.w};
            float bv[4] = {b.x, b.y, b.z, b.w};
#pragma unroll
            for (int i = 0; i < 4; i++)
#pragma unroll
                for (int j = 0; j < 4; j++)
                    acc[i][j] += av[i] * bv[j];
        }
        __syncthreads();
    }

#pragma unroll
    for (int i = 0; i < 4; i++) {
        int row = bi * 64 + ty * 4 + i;
#pragma unroll
        for (int j = 0; j < 4; j++) {
            int col = bj * 64 + tx * 4 + j;
            float v = acc[i][j];
            Cs[(size_t)row * ldcs + col] = v;
            __nv_bfloat16 h = __float2bfloat16(v);
            Phi[(size_t)row * NB + col] = h;
            Plo[(size_t)row * NB + col] =
                __float2bfloat16(v - __bfloat162float(h));
        }
    }
}

// ==========================================================================
// batched NN GEMM, 128x128 tiles / 8x8 micro-tiles (for D&C inversion)
// ==========================================================================
__global__ __launch_bounds__(256, 1)
void gemm_nn_b128(const float* __restrict__ A, size_t strA, int lda,
                  const float* __restrict__ B, size_t strB, int ldb,
                  float* __restrict__ C, size_t strC, int ldc,
                  int K, float alpha)
{
    A += (size_t)blockIdx.z * strA;
    B += (size_t)blockIdx.z * strB;
    C += (size_t)blockIdx.z * strC;

    __shared__ float As[8][128];
    __shared__ float Bs[8][128];

    int bi = blockIdx.y, bj = blockIdx.x;
    int tid = threadIdx.x;
    int tx = tid & 15, ty = tid >> 4;

    int lrow = tid >> 1;
    int lkk  = (tid & 1) * 4;
    int brow = tid >> 5;
    int bcol = (tid & 31) * 4;

    const float* Ap = A + (size_t)(bi * 128 + lrow) * lda + lkk;
    const float* Bp = B + bj * 128 + bcol;

    float acc[8][8];
#pragma unroll
    for (int i = 0; i < 8; i++)
#pragma unroll
        for (int j = 0; j < 8; j++) acc[i][j] = 0.f;

    for (int k0 = 0; k0 < K; k0 += 8) {
        float4 va = *(const float4*)(Ap + k0);
        float4 vb = *(const float4*)(Bp + (size_t)(k0 + brow) * ldb);
        if (k0) __syncthreads();
        As[lkk + 0][lrow] = va.x; As[lkk + 1][lrow] = va.y;
        As[lkk + 2][lrow] = va.z; As[lkk + 3][lrow] = va.w;
        *(float4*)&Bs[brow][bcol] = vb;
        __syncthreads();
#pragma unroll
        for (int kk = 0; kk < 8; kk++) {
            float4 a0 = *(const float4*)&As[kk][ty * 4];
            float4 a1 = *(const float4*)&As[kk][64 + ty * 4];
            float4 b0 = *(const float4*)&Bs[kk][tx * 4];
            float4 b1 = *(const float4*)&Bs[kk][64 + tx * 4];
            float a[8] = {a0.x, a0.y, a0.z, a0.w, a1.x, a1.y, a1.z, a1.w};
            float b[8] = {b0.x, b0.y, b0.z, b0.w, b1.x, b1.y, b1.z, b1.w};
#pragma unroll
            for (int i = 0; i < 8; i++)
#pragma unroll
                for (int j = 0; j < 8; j++)
                    acc[i][j] += a[i] * b[j];
        }
    }

#pragma unroll
    for (int i = 0; i < 8; i++) {
        int r = bi * 128 + ((i < 4) ? ty * 4 + i : 64 + ty * 4 + (i - 4));
#pragma unroll
        for (int j = 0; j < 8; j++) {
            int cc = bj * 128 + ((j < 4) ? tx * 4 + j : 64 + tx * 4 + (j - 4));
            C[(size_t)r * ldc + cc] = alpha * acc[i][j];
        }
    }
}

// ==========================================================================
__global__ void zero_kernel(float* p, int n)
{
    for (int i = blockIdx.x * blockDim.x + threadIdx.x; i < n;
         i += gridDim.x * blockDim.x)
        p[i] = 0.f;
}

__global__ void copy_diag_kernel()
{
    int kb = blockIdx.y;
    int idx = blockIdx.x * 256 + threadIdx.x;
    int i = idx >> 7, j = idx & 127;
    g_W[(size_t)(kb * NB + i) * N + kb * NB + j] =
        g_invD[(size_t)kb * NB * NB + idx];
}

__global__ void fnorm_kernel()
{
    __shared__ float red[256];
    float s = 0.f;
    size_t total = (size_t)N * N;
    for (size_t i = blockIdx.x * blockDim.x + threadIdx.x; i < total;
         i += (size_t)gridDim.x * blockDim.x) {
        float v = g_W[i];
        s += v * v;
    }
    red[threadIdx.x] = s; __syncthreads();
    for (int o = 128; o > 0; o >>= 1) {
        if (threadIdx.x < o) red[threadIdx.x] += red[threadIdx.x + o];
        __syncthreads();
    }
    if (threadIdx.x == 0) atomicAdd(&g_scal[0], red[0]);
}

__global__ void proj_kernel(const float* __restrict__ c)
{
    __shared__ float red[256];
    int r = blockIdx.x;
    const float* row = g_W + (size_t)r * N;
    float s = 0.f;
    for (int j = threadIdx.x; j < N; j += 256) s += row[j] * c[j];
    red[threadIdx.x] = s; __syncthreads();
    for (int o = 128; o > 0; o >>= 1) {
        if (threadIdx.x < o) red[threadIdx.x] += red[threadIdx.x + o];
        __syncthreads();
    }
    if (threadIdx.x == 0) {
        float y = red[0];
        atomicAdd(&g_scal[1], y * y);
    }
}

__global__ void final_kernel(float* out)
{
    __shared__ float red[256];
    float s = 0.f;
    for (int i = threadIdx.x; i < N; i += 256)
        s += logf(g_S[(size_t)i * N + i]);
    red[threadIdx.x] = s; __syncthreads();
    for (int o = 128; o > 0; o >>= 1) {
        if (threadIdx.x < o) red[threadIdx.x] += red[threadIdx.x + o];
        __syncthreads();
    }
    if (threadIdx.x == 0) {
        float nrd = expf(red[0] * (2.0f / (float)N));
        out[0] = (float)N / 5.0f +
                 nrd * ((0.5f - 1.0f / PI_F) * g_scal[0] + g_scal[1] / PI_F);
    }
}

// ==========================================================================
// host orchestration
// ==========================================================================
extern "C" void kernel_launch(void* const* d_in, const int* in_sizes, int n_in,
                              void* d_out, int out_size)
{
    (void)in_sizes; (void)n_in; (void)out_size;
    const float* x     = (const float*)d_in[0];
    const float* c     = (const float*)d_in[1];
    const float* alpha = (const float*)d_in[2];
    float* out = (float*)d_out;

    float *Sp, *Wp, *iDp, *T2p, *scalp;
    __nv_bfloat16 *hip, *lop, *Phip, *Plop;
    cudaGetSymbolAddress((void**)&Sp,    g_S);
    cudaGetSymbolAddress((void**)&Wp,    g_W);
    cudaGetSymbolAddress((void**)&iDp,   g_invD);
    cudaGetSymbolAddress((void**)&T2p,   g_T2);
    cudaGetSymbolAddress((void**)&scalp, g_scal);
    cudaGetSymbolAddress((void**)&hip,   g_hi);
    cudaGetSymbolAddress((void**)&lop,   g_lo);
    cudaGetSymbolAddress((void**)&Phip,  g_Phi);
    cudaGetSymbolAddress((void**)&Plop,  g_Plo);

    int potrf_smem = 2 * NB * LDA * (int)sizeof(float);
    cudaFuncSetAttribute(potrf_invert,
                         cudaFuncAttributeMaxDynamicSharedMemorySize,
                         potrf_smem);
    cudaFuncSetAttribute(mma_nt_kernel,
                         cudaFuncAttributeMaxDynamicSharedMemorySize,
                         GRAM_SMEM);

    // 1. gram via bf16 split mma
    split_kernel<<<4096, 256>>>(x);
    mma_nt_kernel<<<NBLK * (NBLK + 1) / 2, 256, GRAM_SMEM>>>(
        hip, lop, hip, lop, D, Sp, N, D, 1.0f / (float)D, 0);

    // 2. arc-cosine kernel step
    diag_kernel<<<N / 256, 256>>>();
    step_kernel<<<dim3(N / 32, N / 8), dim3(32, 8)>>>(alpha);

    // 3. blocked Cholesky (in place, lower)
    for (int k = 0; k < NBLK; k++) {
        potrf_invert<<<1, 256, potrf_smem>>>(k);
        if (k < NBLK - 1) {
            int rows = (NBLK - 1 - k) * NB;
            // TRSM as GEMM; epilogue writes L (fp32, into S) + bf16 split
            gemm_nt_split<<<dim3(2, rows / 64), 256>>>(
                Sp + (size_t)(k + 1) * NB * N + (size_t)k * NB, N,
                iDp + (size_t)k * NB * NB, NB,
                Sp + (size_t)(k + 1) * NB * N + (size_t)k * NB, N,
                Phip, Plop, NB);
            // trailing SYRK via bf16 split mma (subtract)
            int T2 = NBLK - 1 - k;
            mma_nt_kernel<<<T2 * (T2 + 1) / 2, 256, GRAM_SMEM>>>(
                Phip, Plop, Phip, Plop, NB,
                Sp + (size_t)(k + 1) * NB * N + (size_t)(k + 1) * NB, N,
                NB, 1.0f, 1);
        }
    }

    // 4. divide & conquer triangular inversion: W = L^{-1}
    zero_kernel<<<4096, 256>>>(Wp, N * N);
    copy_diag_kernel<<<dim3(64, NBLK), 256>>>();
    for (int lev = 0; lev < 4; lev++) {
        int s = 128 << lev;
        int pairs = N / (2 * s);
        size_t strW = (size_t)2 * s * (N + 1);
        gemm_nn_b128<<<dim3(s / 128, s / 128, pairs), 256>>>(
            Wp + (size_t)s * N + s, strW, N,
            Sp + (size_t)s * N,     strW, N,
            T2p, (size_t)s * s, s,
            s, 1.0f);
        gemm_nn_b128<<<dim3(s / 128, s / 128, pairs), 256>>>(
            T2p, (size_t)s * s, s,
            Wp, strW, N,
            Wp + (size_t)s * N, strW, N,
            s, -1.0f);
    }

    // 5. reductions + final scalar
    zero_kernel<<<1, 32>>>(scalp, 4);
    fnorm_kernel<<<1024, 256>>>();
    proj_kernel<<<N, 256>>>(c);
    final_kernel<<<1, 256>>>(out);
}

// round 9
// speedup vs baseline: 3.7431x; 1.0014x over previous
#include <cuda_runtime.h>
#include <cuda_bf16.h>
#include <math.h>
#include <stdint.h>

#define N 2048
#define D 16384
#define NB 128
#define LDA 129            // padded smem stride (bank-conflict-free columns)
#define NBLK 16            // N / NB
#define PI_F 3.14159265358979323846f

// ---------------- device scratch (no allocations allowed) ----------------
__device__ float g_S[(size_t)N * N];        // gram / sigma / L (lower, in place)
__device__ float g_W[(size_t)N * N];        // L^{-1} (lower)
__device__ float g_invD[NBLK * NB * NB];    // per-panel inv(L11)
__device__ float g_T2[(size_t)1024 * 1024]; // D&C inversion scratch
__device__ float g_diag[N];                 // diag snapshot
__device__ float g_scal[4];                 // [0]=trace acc, [1]=proj acc
__device__ __nv_bfloat16 g_hi[(size_t)N * D];
__device__ __nv_bfloat16 g_lo[(size_t)N * D];
__device__ __nv_bfloat16 g_Phi[(size_t)N * NB];  // TRSM panel, bf16 hi
__device__ __nv_bfloat16 g_Plo[(size_t)N * NB];  // TRSM panel, bf16 lo

// ==========================================================================
__device__ __forceinline__ uint32_t smem_u32(const void* p) {
    uint32_t a;
    asm("{ .reg .u64 t; cvta.to.shared.u64 t, %1; cvt.u32.u64 %0, t; }"
        : "=r"(a) : "l"(p));
    return a;
}

// ==========================================================================
// split conversion: x -> hi (bf16) + lo (bf16 of residual)
// ==========================================================================
__global__ void split_kernel(const float* __restrict__ x)
{
    size_t total = (size_t)N * D;
    for (size_t i = blockIdx.x * (size_t)blockDim.x + threadIdx.x; i < total;
         i += (size_t)gridDim.x * blockDim.x) {
        float v = x[i];
        __nv_bfloat16 h = __float2bfloat16(v);
        g_hi[i] = h;
        g_lo[i] = __float2bfloat16(v - __bfloat162float(h));
    }
}

// ==========================================================================
// unified bf16-split NT mma kernel over lower tile pairs (tile t0+blockIdx):
//   acc = Ahi*Bhi^T + Ahi*Blo^T + Alo*Bhi^T   (fp32 accum)
// mode 0:  C = clip(acc*scale, -1, 1)       (gram)
// mode 1:  C -= acc                          (SYRK trailing update)
// ==========================================================================
#define BKG 32
#define GTILE_B (128 * 40 * 2)
#define GRAM_SMEM (2 * 4 * GTILE_B)

__device__ __forceinline__ void ldsm_x4(uint32_t* r, uint32_t addr) {
    asm volatile("ldmatrix.sync.aligned.m8n8.x4.shared.b16 {%0,%1,%2,%3}, [%4];"
                 : "=r"(r[0]), "=r"(r[1]), "=r"(r[2]), "=r"(r[3]) : "r"(addr));
}
__device__ __forceinline__ void ldsm_x2(uint32_t* r, uint32_t addr) {
    asm volatile("ldmatrix.sync.aligned.m8n8.x2.shared.b16 {%0,%1}, [%2];"
                 : "=r"(r[0]), "=r"(r[1]) : "r"(addr));
}
__device__ __forceinline__ void mma_bf16(float* d, const uint32_t* a,
                                         const uint32_t* b) {
    asm volatile(
        "mma.sync.aligned.m16n8k16.row.col.f32.bf16.bf16.f32 "
        "{%0,%1,%2,%3}, {%4,%5,%6,%7}, {%8,%9}, {%0,%1,%2,%3};"
        : "+f"(d[0]), "+f"(d[1]), "+f"(d[2]), "+f"(d[3])
        : "r"(a[0]), "r"(a[1]), "r"(a[2]), "r"(a[3]), "r"(b[0]), "r"(b[1]));
}
#define CP_ASYNC(dst, src) \
    asm volatile("cp.async.cg.shared.global [%0], [%1], 16;" \
                 :: "r"(dst), "l"(src))
#define CP_COMMIT() asm volatile("cp.async.commit_group;" ::: "memory")

__global__ __launch_bounds__(256, 1)
void mma_nt_kernel(const __nv_bfloat16* __restrict__ Ahi,
                   const __nv_bfloat16* __restrict__ Alo,
                   const __nv_bfloat16* __restrict__ Bhi,
                   const __nv_bfloat16* __restrict__ Blo,
                   size_t lda, float* __restrict__ Cbase, int ldc,
                   int K, float scale, int mode, int t0)
{
    extern __shared__ char dsm[];
    uint32_t sbase = smem_u32(dsm);

    int tid  = threadIdx.x;
    int wid  = tid >> 5;
    int lane = tid & 31;

    int t = blockIdx.x + t0;
    int bi = (int)((sqrtf(8.f * (float)t + 1.f) - 1.f) * 0.5f);
    while ((bi + 1) * (bi + 2) / 2 <= t) bi++;
    while (bi * (bi + 1) / 2 > t) bi--;
    int bj = t - bi * (bi + 1) / 2;

    const __nv_bfloat16* srcs[4] = {
        Ahi + (size_t)bi * 128 * lda,
        Alo + (size_t)bi * 128 * lda,
        Bhi + (size_t)bj * 128 * lda,
        Blo + (size_t)bj * 128 * lda
    };

    int m0w = (wid & 1) * 64;
    int n0w = (wid >> 1) * 32;

    float acc[4][4][4];
#pragma unroll
    for (int im = 0; im < 4; im++)
#pragma unroll
        for (int jn = 0; jn < 4; jn++)
#pragma unroll
            for (int e = 0; e < 4; e++) acc[im][jn][e] = 0.f;

    const int S = K / BKG;

    {
#pragma unroll
        for (int it = 0; it < 8; it++) {
            int idx = tid + it * 256;
            int tile = idx >> 9;
            int rem = idx & 511;
            int r = rem >> 2, ch = rem & 3;
            uint32_t dst = sbase + (uint32_t)tile * GTILE_B + r * 80 + ch * 16;
            CP_ASYNC(dst, srcs[tile] + (size_t)r * lda + ch * 8);
        }
        CP_COMMIT();
    }

#pragma unroll 1
    for (int s = 0; s < S; s++) {
        if (s + 1 < S) {
            int k0 = (s + 1) * BKG;
            uint32_t boff = (uint32_t)((s + 1) & 1) * (4 * GTILE_B);
#pragma unroll
            for (int it = 0; it < 8; it++) {
                int idx = tid + it * 256;
                int tile = idx >> 9;
                int rem = idx & 511;
                int r = rem >> 2, ch = rem & 3;
                uint32_t dst = sbase + boff + (uint32_t)tile * GTILE_B +
                               r * 80 + ch * 16;
                CP_ASYNC(dst, srcs[tile] + (size_t)r * lda + k0 + ch * 8);
            }
            CP_COMMIT();
            asm volatile("cp.async.wait_group 1;" ::: "memory");
        } else {
            asm volatile("cp.async.wait_group 0;" ::: "memory");
        }
        __syncthreads();

        uint32_t buf = sbase + (uint32_t)(s & 1) * (4 * GTILE_B);
        uint32_t Ahi_b = buf;
        uint32_t Alo_b = buf + GTILE_B;
        uint32_t Bhi_b = buf + 2 * GTILE_B;
        uint32_t Blo_b = buf + 3 * GTILE_B;

#pragma unroll
        for (int ks = 0; ks < 2; ks++) {
            int kof = ks * 16;
            int arow = lane & 15;
            int acol = kof + 8 * (lane >> 4);
            uint32_t ah[4][4], al[4][4];
#pragma unroll
            for (int im = 0; im < 4; im++) {
                uint32_t ro = (uint32_t)(m0w + im * 16 + arow) * 80 + acol * 2;
                ldsm_x4(ah[im], Ahi_b + ro);
                ldsm_x4(al[im], Alo_b + ro);
            }
            int brow = lane & 7;
            int bcol = kof + 8 * ((lane >> 3) & 1);
            uint32_t bh[4][2], bl[4][2];
#pragma unroll
            for (int jn = 0; jn < 4; jn++) {
                uint32_t ro = (uint32_t)(n0w + jn * 8 + brow) * 80 + bcol * 2;
                ldsm_x2(bh[jn], Bhi_b + ro);
                ldsm_x2(bl[jn], Blo_b + ro);
            }
#pragma unroll
            for (int im = 0; im < 4; im++)
#pragma unroll
                for (int jn = 0; jn < 4; jn++) {
                    mma_bf16(acc[im][jn], ah[im], bh[jn]);
                    mma_bf16(acc[im][jn], ah[im], bl[jn]);
                    mma_bf16(acc[im][jn], al[im], bh[jn]);
                }
        }
        __syncthreads();
    }

#pragma unroll
    for (int im = 0; im < 4; im++) {
        int row = bi * 128 + m0w + im * 16 + (lane >> 2);
#pragma unroll
        for (int jn = 0; jn < 4; jn++) {
            int col = bj * 128 + n0w + jn * 8 + (lane & 3) * 2;
            float* p0 = Cbase + (size_t)row * ldc + col;
            float* p1 = Cbase + (size_t)(row + 8) * ldc + col;
            if (mode == 0) {
                p0[0] = fminf(fmaxf(acc[im][jn][0] * scale, -1.f), 1.f);
                p0[1] = fminf(fmaxf(acc[im][jn][1] * scale, -1.f), 1.f);
                p1[0] = fminf(fmaxf(acc[im][jn][2] * scale, -1.f), 1.f);
                p1[1] = fminf(fmaxf(acc[im][jn][3] * scale, -1.f), 1.f);
            } else {
                p0[0] -= acc[im][jn][0];
                p0[1] -= acc[im][jn][1];
                p1[0] -= acc[im][jn][2];
                p1[1] -= acc[im][jn][3];
            }
        }
    }
}

// ==========================================================================
__global__ void diag_kernel()
{
    int i = blockIdx.x * blockDim.x + threadIdx.x;
    if (i < N) g_diag[i] = g_S[(size_t)i * N + i];
}

__global__ void step_kernel(const float* __restrict__ alpha_p)
{
    int j = blockIdx.x * 32 + threadIdx.x;
    int i = blockIdx.y * 8 + threadIdx.y;
    if (i >= N || j > i) return;
    float a  = *alpha_p;
    float a2 = a * a;
    float cross = sqrtf(g_diag[i] * g_diag[j]);
    float s = g_S[(size_t)i * N + j];
    float m = fminf(fmaxf(s / cross, -1.f), 1.f);
    float q = 1.f - m * m;
    float sq, ac;
    if (q > 0.f) { sq = sqrtf(q); ac = acosf(m); }
    else         { sq = 0.f;      ac = (m > 0.f) ? 0.f : PI_F; }
    float f  = (sq + m * (PI_F - ac)) / PI_F;
    float ts = cross * f;
    float ov = (s + a2 * ts) / (1.f + a2);
    g_S[(size_t)i * N + j] = fminf(fmaxf(ov, -1.f), 1.f);
}

// ==========================================================================
// panel factorization + inversion of 128x128 diag block.
// ==========================================================================
__global__ __launch_bounds__(256, 1)
void potrf_invert(int kb)
{
    extern __shared__ float sh[];
    float* A = sh;                 // NB x NB stride LDA (L, lower)
    float* W = sh + NB * LDA;      // NB x NB stride LDA (inv(L), lower)
    __shared__ float Ts[3 * 1056];
    int tid = threadIdx.x;
    int base = kb * NB;

    for (int idx = tid; idx < NB * 32; idx += 256) {
        int i = idx >> 5, j4 = (idx & 31) << 2;
        float4 v = *(const float4*)&g_S[(size_t)(base + i) * N + base + j4];
        A[i * LDA + j4 + 0] = v.x;
        A[i * LDA + j4 + 1] = v.y;
        A[i * LDA + j4 + 2] = v.z;
        A[i * LDA + j4 + 3] = v.w;
    }
    __syncthreads();

    for (int p = 0; p < 4; p++) {
        int off = p * 32;

        // ---- register-resident potf2 + inv32, warp 0 ----
        if (tid < 32) {
            const unsigned FULL = 0xffffffffu;
            int r = tid;
            float ar[32];
#pragma unroll
            for (int t = 0; t < 32; t++)
                ar[t] = (t <= r) ? A[(off + r) * LDA + off + t] : 0.f;
            float rs_reg = 0.f;
#pragma unroll
            for (int j = 0; j < 32; j++) {
                float d   = __shfl_sync(FULL, ar[j], j);
                float rsj = rsqrtf(d);
                float lj  = ar[j] * rsj;
                ar[j] = lj;
                if (r == j) rs_reg = rsj;
#pragma unroll
                for (int t = j + 1; t < 32; t++) {
                    float ltj = __shfl_sync(FULL, lj, t);
                    ar[t] -= lj * ltj;
                }
            }
            int c = r;
            float w[32];
#pragma unroll
            for (int t = 0; t < 32; t++) w[t] = 0.f;
#pragma unroll
            for (int i = 0; i < 32; i++) {
                float s = (i == c) ? 1.f : 0.f;
#pragma unroll
                for (int t = 0; t < i; t++) {
                    float lit = __shfl_sync(FULL, ar[t], i);
                    s -= lit * w[t];
                }
                float rsi = __shfl_sync(FULL, rs_reg, i);
                w[i] = (i >= c) ? s * rsi : 0.f;
            }
#pragma unroll
            for (int t = 0; t < 32; t++)
                if (t <= r) A[(off + r) * LDA + off + t] = ar[t];
#pragma unroll
            for (int i = 0; i < 32; i++)
                W[(off + i) * LDA + off + c] = w[i];
        }
        __syncthreads();

        int nr = NB - off - 32;
        if (nr > 0) {
            // ---- TRSM: A21 <- A21 * inv(L11_32)^T, 4x4 tiles, reg-staged --
            int ntr = (nr >> 2) * 8;   // <= 192 <= 256: one pass
            float acc[4][4];
            int tr = 0, tc = 0;
            if (tid < ntr) {
                tr = (tid >> 3) * 4;
                tc = (tid & 7) * 4;
#pragma unroll
                for (int r = 0; r < 4; r++)
#pragma unroll
                    for (int cidx = 0; cidx < 4; cidx++) acc[r][cidx] = 0.f;
#pragma unroll 8
                for (int k = 0; k < 32; k++) {
                    float av[4], wv[4];
#pragma unroll
                    for (int r = 0; r < 4; r++)
                        av[r] = A[(off + 32 + tr + r) * LDA + off + k];
#pragma unroll
                    for (int cidx = 0; cidx < 4; cidx++)
                        wv[cidx] = W[(off + tc + cidx) * LDA + off + k];
#pragma unroll
                    for (int r = 0; r < 4; r++)
#pragma unroll
                        for (int cidx = 0; cidx < 4; cidx++)
                            acc[r][cidx] += av[r] * wv[cidx];
                }
            }
            __syncthreads();
            if (tid < ntr) {
#pragma unroll
                for (int r = 0; r < 4; r++)
#pragma unroll
                    for (int cidx = 0; cidx < 4; cidx++)
                        A[(off + 32 + tr + r) * LDA + off + tc + cidx] =
                            acc[r][cidx];
            }
            __syncthreads();

            // ---- SYRK trailing update, 4x4 micro-tiles (lower only) ----
            int nt = nr >> 2;
            int ntot = nt * (nt + 1) / 2;
            for (int tId = tid; tId < ntot; tId += 256) {
                int ti = (int)((sqrtf(8.f * (float)tId + 1.f) - 1.f) * 0.5f);
                while ((ti + 1) * (ti + 2) / 2 <= tId) ti++;
                while (ti * (ti + 1) / 2 > tId) ti--;
                int tj = tId - ti * (ti + 1) / 2;
                int i0 = off + 32 + ti * 4;
                int t0 = off + 32 + tj * 4;
                float a2[4][4];
#pragma unroll
                for (int r = 0; r < 4; r++)
#pragma unroll
                    for (int cidx = 0; cidx < 4; cidx++) a2[r][cidx] = 0.f;
#pragma unroll 8
                for (int k = 0; k < 32; k++) {
                    float av[4], bv[4];
#pragma unroll
                    for (int r = 0; r < 4; r++)
                        av[r] = A[(i0 + r) * LDA + off + k];
#pragma unroll
                    for (int cidx = 0; cidx < 4; cidx++)
                        bv[cidx] = A[(t0 + cidx) * LDA + off + k];
#pragma unroll
                    for (int r = 0; r < 4; r++)
#pragma unroll
                        for (int cidx = 0; cidx < 4; cidx++)
                            a2[r][cidx] += av[r] * bv[cidx];
                }
#pragma unroll
                for (int r = 0; r < 4; r++)
#pragma unroll
                    for (int cidx = 0; cidx < 4; cidx++) {
                        int ii = i0 + r, tt = t0 + cidx;
                        if (tt <= ii) A[ii * LDA + tt] -= a2[r][cidx];
                    }
            }
            __syncthreads();
        }
    }

    // ---- blocked inversion of off-diag 32x32 blocks of W, 4x4 tiles ----
    for (int ib = 1; ib < 4; ib++) {
        for (int tId = tid; tId < ib * 64; tId += 256) {
            int j = tId >> 6;
            int e = tId & 63;
            int r0 = (e >> 3) * 4, c0 = (e & 7) * 4;
            float acc[4][4];
#pragma unroll
            for (int r = 0; r < 4; r++)
#pragma unroll
                for (int cidx = 0; cidx < 4; cidx++) acc[r][cidx] = 0.f;
            for (int tb = j; tb < ib; tb++) {
#pragma unroll 8
                for (int k = 0; k < 32; k++) {
                    float lv[4], wv[4];
#pragma unroll
                    for (int r = 0; r < 4; r++)
                        lv[r] = A[(32 * ib + r0 + r) * LDA + 32 * tb + k];
#pragma unroll
                    for (int cidx = 0; cidx < 4; cidx++)
                        wv[cidx] = W[(32 * tb + k) * LDA + 32 * j + c0 + cidx];
#pragma unroll
                    for (int r = 0; r < 4; r++)
#pragma unroll
                        for (int cidx = 0; cidx < 4; cidx++)
                            acc[r][cidx] += lv[r] * wv[cidx];
                }
            }
#pragma unroll
            for (int r = 0; r < 4; r++)
#pragma unroll
                for (int cidx = 0; cidx < 4; cidx++)
                    Ts[j * 1056 + (r0 + r) * 33 + c0 + cidx] = acc[r][cidx];
        }
        __syncthreads();
        for (int tId = tid; tId < ib * 64; tId += 256) {
            int j = tId >> 6;
            int e = tId & 63;
            int r0 = (e >> 3) * 4, c0 = (e & 7) * 4;
            float acc[4][4];
#pragma unroll
            for (int r = 0; r < 4; r++)
#pragma unroll
                for (int cidx = 0; cidx < 4; cidx++) acc[r][cidx] = 0.f;
#pragma unroll 8
            for (int k = 0; k < 32; k++) {
                float wv[4], tv[4];
#pragma unroll
                for (int r = 0; r < 4; r++)
                    wv[r] = W[(32 * ib + r0 + r) * LDA + 32 * ib + k];
#pragma unroll
                for (int cidx = 0; cidx < 4; cidx++)
                    tv[cidx] = Ts[j * 1056 + k * 33 + c0 + cidx];
#pragma unroll
                for (int r = 0; r < 4; r++)
#pragma unroll
                    for (int cidx = 0; cidx < 4; cidx++)
                        acc[r][cidx] += wv[r] * tv[cidx];
            }
#pragma unroll
            for (int r = 0; r < 4; r++)
#pragma unroll
                for (int cidx = 0; cidx < 4; cidx++)
                    W[(32 * ib + r0 + r) * LDA + 32 * j + c0 + cidx] =
                        -acc[r][cidx];
        }
        __syncthreads();
    }

    for (int idx = tid; idx < NB * NB; idx += 256) {
        int i = idx >> 7, j = idx & 127;
        if (j <= i) g_S[(size_t)(base + i) * N + base + j] = A[i * LDA + j];
        g_invD[(size_t)kb * NB * NB + idx] =
            ((j >> 5) <= (i >> 5)) ? W[i * LDA + j] : 0.f;
    }
}

// ==========================================================================
// TRSM panel GEMM: C = A * B^T (64x64 tiles); epilogue writes fp32 into S
// (as L) AND bf16 hi/lo split into the panel buffers for the mma SYRK.
// ==========================================================================
__global__ __launch_bounds__(256, 2)
void gemm_nt_split(const float* __restrict__ A, int lda,
                   const float* __restrict__ B, int ldb,
                   float* __restrict__ Cs, int ldcs,
                   __nv_bfloat16* __restrict__ Phi,
                   __nv_bfloat16* __restrict__ Plo, int K)
{
    __shared__ float As[16][64];
    __shared__ float Bs[16][64];
    int bi = blockIdx.y, bj = blockIdx.x;
    int tid = threadIdx.x;
    int tx = tid & 15, ty = tid >> 4;

    const float* Ab = A + (size_t)(bi * 64) * lda;
    const float* Bb = B + (size_t)(bj * 64) * ldb;

    int arow = tid >> 2, akk = (tid & 3) << 2;

    float acc[4][4];
#pragma unroll
    for (int i = 0; i < 4; i++)
#pragma unroll
        for (int j = 0; j < 4; j++) acc[i][j] = 0.f;

    for (int k0 = 0; k0 < K; k0 += 16) {
        float4 va = *(const float4*)(Ab + (size_t)arow * lda + k0 + akk);
        float4 vb = *(const float4*)(Bb + (size_t)arow * ldb + k0 + akk);
        As[akk + 0][arow] = va.x; As[akk + 1][arow] = va.y;
        As[akk + 2][arow] = va.z; As[akk + 3][arow] = va.w;
        Bs[akk + 0][arow] = vb.x; Bs[akk + 1][arow] = vb.y;
        Bs[akk + 2][arow] = vb.z; Bs[akk + 3][arow] = vb.w;
        __syncthreads();
#pragma unroll
        for (int kk = 0; kk < 16; kk++) {
            float4 a = *(const float4*)&As[kk][ty * 4];
            float4 b = *(const float4*)&Bs[kk][tx * 4];
            float av[4] = {a.x, a.y, a.z, a.w};
            float bv[4] = {b.x, b.y, b.z, b.w};
#pragma unroll
            for (int i = 0; i < 4; i++)
#pragma unroll
                for (int j = 0; j < 4; j++)
                    acc[i][j] += av[i] * bv[j];
        }
        __syncthreads();
    }

#pragma unroll
    for (int i = 0; i < 4; i++) {
        int row = bi * 64 + ty * 4 + i;
#pragma unroll
        for (int j = 0; j < 4; j++) {
            int col = bj * 64 + tx * 4 + j;
            float v = acc[i][j];
            Cs[(size_t)row * ldcs + col] = v;
            __nv_bfloat16 h = __float2bfloat16(v);
            Phi[(size_t)row * NB + col] = h;
            Plo[(size_t)row * NB + col] =
                __float2bfloat16(v - __bfloat162float(h));
        }
    }
}

// ==========================================================================
// batched NN GEMM, 128x128 tiles / 8x8 micro-tiles (for D&C inversion)
// ==========================================================================
__global__ __launch_bounds__(256, 1)
void gemm_nn_b128(const float* __restrict__ A, size_t strA, int lda,
                  const float* __restrict__ B, size_t strB, int ldb,
                  float* __restrict__ C, size_t strC, int ldc,
                  int K, float alpha)
{
    A += (size_t)blockIdx.z * strA;
    B += (size_t)blockIdx.z * strB;
    C += (size_t)blockIdx.z * strC;

    __shared__ float As[8][128];
    __shared__ float Bs[8][128];

    int bi = blockIdx.y, bj = blockIdx.x;
    int tid = threadIdx.x;
    int tx = tid & 15, ty = tid >> 4;

    int lrow = tid >> 1;
    int lkk  = (tid & 1) * 4;
    int brow = tid >> 5;
    int bcol = (tid & 31) * 4;

    const float* Ap = A + (size_t)(bi * 128 + lrow) * lda + lkk;
    const float* Bp = B + bj * 128 + bcol;

    float acc[8][8];
#pragma unroll
    for (int i = 0; i < 8; i++)
#pragma unroll
        for (int j = 0; j < 8; j++) acc[i][j] = 0.f;

    for (int k0 = 0; k0 < K; k0 += 8) {
        float4 va = *(const float4*)(Ap + k0);
        float4 vb = *(const float4*)(Bp + (size_t)(k0 + brow) * ldb);
        if (k0) __syncthreads();
        As[lkk + 0][lrow] = va.x; As[lkk + 1][lrow] = va.y;
        As[lkk + 2][lrow] = va.z; As[lkk + 3][lrow] = va.w;
        *(float4*)&Bs[brow][bcol] = vb;
        __syncthreads();
#pragma unroll
        for (int kk = 0; kk < 8; kk++) {
            float4 a0 = *(const float4*)&As[kk][ty * 4];
            float4 a1 = *(const float4*)&As[kk][64 + ty * 4];
            float4 b0 = *(const float4*)&Bs[kk][tx * 4];
            float4 b1 = *(const float4*)&Bs[kk][64 + tx * 4];
            float a[8] = {a0.x, a0.y, a0.z, a0.w, a1.x, a1.y, a1.z, a1.w};
            float b[8] = {b0.x, b0.y, b0.z, b0.w, b1.x, b1.y, b1.z, b1.w};
#pragma unroll
            for (int i = 0; i < 8; i++)
#pragma unroll
                for (int j = 0; j < 8; j++)
                    acc[i][j] += a[i] * b[j];
        }
    }

#pragma unroll
    for (int i = 0; i < 8; i++) {
        int r = bi * 128 + ((i < 4) ? ty * 4 + i : 64 + ty * 4 + (i - 4));
#pragma unroll
        for (int j = 0; j < 8; j++) {
            int cc = bj * 128 + ((j < 4) ? tx * 4 + j : 64 + tx * 4 + (j - 4));
            C[(size_t)r * ldc + cc] = alpha * acc[i][j];
        }
    }
}

// ==========================================================================
__global__ void zero_kernel(float* p, int n)
{
    for (int i = blockIdx.x * blockDim.x + threadIdx.x; i < n;
         i += gridDim.x * blockDim.x)
        p[i] = 0.f;
}

__global__ void copy_diag_kernel()
{
    int kb = blockIdx.y;
    int idx = blockIdx.x * 256 + threadIdx.x;
    int i = idx >> 7, j = idx & 127;
    g_W[(size_t)(kb * NB + i) * N + kb * NB + j] =
        g_invD[(size_t)kb * NB * NB + idx];
}

__global__ void fnorm_kernel()
{
    __shared__ float red[256];
    float s = 0.f;
    size_t total = (size_t)N * N;
    for (size_t i = blockIdx.x * blockDim.x + threadIdx.x; i < total;
         i += (size_t)gridDim.x * blockDim.x) {
        float v = g_W[i];
        s += v * v;
    }
    red[threadIdx.x] = s; __syncthreads();
    for (int o = 128; o > 0; o >>= 1) {
        if (threadIdx.x < o) red[threadIdx.x] += red[threadIdx.x + o];
        __syncthreads();
    }
    if (threadIdx.x == 0) atomicAdd(&g_scal[0], red[0]);
}

__global__ void proj_kernel(const float* __restrict__ c)
{
    __shared__ float red[256];
    int r = blockIdx.x;
    const float* row = g_W + (size_t)r * N;
    float s = 0.f;
    for (int j = threadIdx.x; j < N; j += 256) s += row[j] * c[j];
    red[threadIdx.x] = s; __syncthreads();
    for (int o = 128; o > 0; o >>= 1) {
        if (threadIdx.x < o) red[threadIdx.x] += red[threadIdx.x + o];
        __syncthreads();
    }
    if (threadIdx.x == 0) {
        float y = red[0];
        atomicAdd(&g_scal[1], y * y);
    }
}

__global__ void final_kernel(float* out)
{
    __shared__ float red[256];
    float s = 0.f;
    for (int i = threadIdx.x; i < N; i += 256)
        s += logf(g_S[(size_t)i * N + i]);
    red[threadIdx.x] = s; __syncthreads();
    for (int o = 128; o > 0; o >>= 1) {
        if (threadIdx.x < o) red[threadIdx.x] += red[threadIdx.x + o];
        __syncthreads();
    }
    if (threadIdx.x == 0) {
        float nrd = expf(red[0] * (2.0f / (float)N));
        out[0] = (float)N / 5.0f +
                 nrd * ((0.5f - 1.0f / PI_F) * g_scal[0] + g_scal[1] / PI_F);
    }
}

// ==========================================================================
// host orchestration (two-stream lookahead Cholesky)
// ==========================================================================
extern "C" void kernel_launch(void* const* d_in, const int* in_sizes, int n_in,
                              void* d_out, int out_size)
{
    (void)in_sizes; (void)n_in; (void)out_size;
    const float* x     = (const float*)d_in[0];
    const float* c     = (const float*)d_in[1];
    const float* alpha = (const float*)d_in[2];
    float* out = (float*)d_out;

    float *Sp, *Wp, *iDp, *T2p, *scalp;
    __nv_bfloat16 *hip, *lop, *Phip, *Plop;
    cudaGetSymbolAddress((void**)&Sp,    g_S);
    cudaGetSymbolAddress((void**)&Wp,    g_W);
    cudaGetSymbolAddress((void**)&iDp,   g_invD);
    cudaGetSymbolAddress((void**)&T2p,   g_T2);
    cudaGetSymbolAddress((void**)&scalp, g_scal);
    cudaGetSymbolAddress((void**)&hip,   g_hi);
    cudaGetSymbolAddress((void**)&lop,   g_lo);
    cudaGetSymbolAddress((void**)&Phip,  g_Phi);
    cudaGetSymbolAddress((void**)&Plop,  g_Plo);

    int potrf_smem = 2 * NB * LDA * (int)sizeof(float);
    cudaFuncSetAttribute(potrf_invert,
                         cudaFuncAttributeMaxDynamicSharedMemorySize,
                         potrf_smem);
    cudaFuncSetAttribute(mma_nt_kernel,
                         cudaFuncAttributeMaxDynamicSharedMemorySize,
                         GRAM_SMEM);

    // side stream + events for lookahead (leaked: cannot destroy streams
    // participating in an ongoing capture; a handful per process run)
    cudaStream_t s1;
    cudaStreamCreateWithFlags(&s1, cudaStreamNonBlocking);
    cudaEvent_t eT[NBLK], eS[NBLK];
    for (int i = 0; i < NBLK; i++) {
        cudaEventCreateWithFlags(&eT[i], cudaEventDisableTiming);
        cudaEventCreateWithFlags(&eS[i], cudaEventDisableTiming);
    }

    // 1. gram via bf16 split mma
    split_kernel<<<4096, 256>>>(x);
    mma_nt_kernel<<<NBLK * (NBLK + 1) / 2, 256, GRAM_SMEM>>>(
        hip, lop, hip, lop, D, Sp, N, D, 1.0f / (float)D, 0, 0);

    // 2. arc-cosine kernel step
    diag_kernel<<<N / 256, 256>>>();
    step_kernel<<<dim3(N / 32, N / 8), dim3(32, 8)>>>(alpha);

    // 3. blocked Cholesky with lookahead: critical path
    //    potrf(k) -> TRSM(k) -> SYRKdiag(k) -> potrf(k+1);
    //    SYRKrest(k) overlaps on s1, joined before TRSM(k+1).
    for (int k = 0; k < NBLK; k++) {
        potrf_invert<<<1, 256, potrf_smem>>>(k);
        if (k < NBLK - 1) {
            if (k >= 1) cudaStreamWaitEvent(0, eS[k - 1], 0);
            int rows = (NBLK - 1 - k) * NB;
            gemm_nt_split<<<dim3(2, rows / 64), 256>>>(
                Sp + (size_t)(k + 1) * NB * N + (size_t)k * NB, N,
                iDp + (size_t)k * NB * NB, NB,
                Sp + (size_t)(k + 1) * NB * N + (size_t)k * NB, N,
                Phip, Plop, NB);
            cudaEventRecord(eT[k], 0);

            int T2 = NBLK - 1 - k;
            float* Ctrail = Sp + (size_t)(k + 1) * NB * N + (size_t)(k + 1) * NB;
            // diag tile (tile 0) on the critical path
            mma_nt_kernel<<<1, 256, GRAM_SMEM>>>(
                Phip, Plop, Phip, Plop, NB, Ctrail, N, NB, 1.0f, 1, 0);
            // remaining tiles on s1
            int restTiles = T2 * (T2 + 1) / 2 - 1;
            if (restTiles > 0) {
                cudaStreamWaitEvent(s1, eT[k], 0);
                mma_nt_kernel<<<restTiles, 256, GRAM_SMEM, s1>>>(
                    Phip, Plop, Phip, Plop, NB, Ctrail, N, NB, 1.0f, 1, 1);
                cudaEventRecord(eS[k], s1);
            } else {
                // no rest work: satisfy next iteration's wait from s0
                cudaEventRecord(eS[k], 0);
            }
        }
    }

    // 4. divide & conquer triangular inversion: W = L^{-1}
    zero_kernel<<<4096, 256>>>(Wp, N * N);
    copy_diag_kernel<<<dim3(64, NBLK), 256>>>();
    for (int lev = 0; lev < 4; lev++) {
        int s = 128 << lev;
        int pairs = N / (2 * s);
        size_t strW = (size_t)2 * s * (N + 1);
        gemm_nn_b128<<<dim3(s / 128, s / 128, pairs), 256>>>(
            Wp + (size_t)s * N + s, strW, N,
            Sp + (size_t)s * N,     strW, N,
            T2p, (size_t)s * s, s,
            s, 1.0f);
        gemm_nn_b128<<<dim3(s / 128, s / 128, pairs), 256>>>(
            T2p, (size_t)s * s, s,
            Wp, strW, N,
            Wp + (size_t)s * N, strW, N,
            s, -1.0f);
    }

    // 5. reductions + final scalar
    zero_kernel<<<1, 32>>>(scalp, 4);
    fnorm_kernel<<<1024, 256>>>();
    proj_kernel<<<N, 256>>>(c);
    final_kernel<<<1, 256>>>(out);
}